// round 2
// baseline (speedup 1.0000x reference)
#include <cuda_runtime.h>
#include <cuda_bf16.h>
#include <cstdint>

// ---------------- problem constants ----------------
#define B_SZ     8
#define L_SEQ    2048
#define P_DIM    32
#define D_MODEL  512
#define D_INNER  1024
#define N_STATE  16
#define DT_RANK  32
#define N_LAYER  4
#define BL_ROWS  (B_SZ * L_SEQ)          // 16384

// ---------------- scratch (static device globals; no malloc allowed) ----
__device__ float g_h   [(size_t)BL_ROWS * D_MODEL];
__device__ float g_xin [(size_t)BL_ROWS * D_MODEL];
__device__ float g_xz  [(size_t)BL_ROWS * 2 * D_INNER];
__device__ float g_xc  [(size_t)BL_ROWS * D_INNER];
__device__ float g_dbl [(size_t)BL_ROWS * 64];
__device__ float g_dt  [(size_t)BL_ROWS * D_INNER];
__device__ float g_ys  [(size_t)BL_ROWS * D_INNER];
__device__ float g_h2  [(size_t)BL_ROWS * D_MODEL];

// ---------------- epilogue ids ----------------
#define EPI_NONE     0
#define EPI_BIAS     1
#define EPI_SOFTPLUS 2
#define EPI_GELU     3
#define EPI_RESID    4

// ---------------- generic tiled SGEMM: C = A(M,K;lda) * W(N,K)^T ----------
template<int BM, int BN, int BK, int TM, int TN, int EPI>
__global__ __launch_bounds__(256) void gemm_k(
    const float* __restrict__ A, int lda,
    const float* __restrict__ W,
    const float* __restrict__ bias,
    const float* __restrict__ resid,
    float* __restrict__ C,
    int M, int N, int K)
{
    __shared__ float As[BK][BM];
    __shared__ float Ws[BK][BN];
    const int tid = threadIdx.x;
    const int bm = blockIdx.y * BM;
    const int bn = blockIdx.x * BN;
    constexpr int TX = BN / TN;
    const int tx = tid % TX;
    const int ty = tid / TX;

    float acc[TM][TN];
#pragma unroll
    for (int i = 0; i < TM; i++)
#pragma unroll
        for (int j = 0; j < TN; j++) acc[i][j] = 0.f;

    for (int k0 = 0; k0 < K; k0 += BK) {
#pragma unroll
        for (int i = tid; i < BM * BK; i += 256) {
            int r = i / BK, c = i % BK;
            As[c][r] = A[(size_t)(bm + r) * lda + k0 + c];
        }
#pragma unroll
        for (int i = tid; i < BN * BK; i += 256) {
            int r = i / BK, c = i % BK;
            Ws[c][r] = W[(size_t)(bn + r) * K + k0 + c];
        }
        __syncthreads();
#pragma unroll
        for (int kk = 0; kk < BK; kk++) {
            float ra[TM], rw[TN];
#pragma unroll
            for (int i = 0; i < TM; i++) ra[i] = As[kk][ty * TM + i];
#pragma unroll
            for (int j = 0; j < TN; j++) rw[j] = Ws[kk][tx * TN + j];
#pragma unroll
            for (int i = 0; i < TM; i++)
#pragma unroll
                for (int j = 0; j < TN; j++)
                    acc[i][j] = fmaf(ra[i], rw[j], acc[i][j]);
        }
        __syncthreads();
    }

#pragma unroll
    for (int i = 0; i < TM; i++) {
        int row = bm + ty * TM + i;
#pragma unroll
        for (int j = 0; j < TN; j++) {
            int col = bn + tx * TN + j;
            float v = acc[i][j];
            if constexpr (EPI == EPI_BIAS || EPI == EPI_SOFTPLUS || EPI == EPI_GELU)
                v += bias[col];
            if constexpr (EPI == EPI_SOFTPLUS)
                v = (v > 20.f) ? v : log1pf(__expf(v));
            if constexpr (EPI == EPI_GELU) {
                float u = 0.7978845608028654f * (v + 0.044715f * v * v * v);
                v = 0.5f * v * (1.f + tanhf(u));
            }
            if constexpr (EPI == EPI_RESID)
                v += resid[(size_t)row * N + col];
            C[(size_t)row * N + col] = v;
        }
    }
}

// ---------------- layernorm: D=512, one warp per row ----------------
__global__ __launch_bounds__(256) void ln_kernel(
    const float* __restrict__ x, const float* __restrict__ w,
    const float* __restrict__ bb, float* __restrict__ o)
{
    int row  = blockIdx.x * 8 + (threadIdx.x >> 5);
    int lane = threadIdx.x & 31;
    const float* xr = x + (size_t)row * D_MODEL + lane;
    float v[16];
    float s = 0.f, s2 = 0.f;
#pragma unroll
    for (int i = 0; i < 16; i++) {
        v[i] = xr[i * 32];
        s += v[i];
        s2 = fmaf(v[i], v[i], s2);
    }
#pragma unroll
    for (int k = 16; k; k >>= 1) {
        s  += __shfl_xor_sync(0xffffffffu, s,  k);
        s2 += __shfl_xor_sync(0xffffffffu, s2, k);
    }
    float mu  = s * (1.f / 512.f);
    float var = fmaf(s2, 1.f / 512.f, -mu * mu);
    float rs  = rsqrtf(var + 1e-5f);
    float* orow = o + (size_t)row * D_MODEL + lane;
#pragma unroll
    for (int i = 0; i < 16; i++)
        orow[i * 32] = (v[i] - mu) * rs * w[lane + i * 32] + bb[lane + i * 32];
}

// ---------------- causal depthwise conv (k=4) + SiLU ----------------
__global__ __launch_bounds__(256) void conv_silu_kernel(
    const float* __restrict__ xz, const float* __restrict__ cw,
    const float* __restrict__ cb, float* __restrict__ xc)
{
    int idx = blockIdx.x * 256 + threadIdx.x;      // over BL_ROWS*D_INNER
    int d  = idx & (D_INNER - 1);
    int bl = idx >> 10;
    int t  = bl & (L_SEQ - 1);
    const float* xp = xz + (size_t)bl * (2 * D_INNER) + d;   // x part of xz
    float4 w = __ldg((const float4*)cw + d);
    float acc = cb[d];
    acc = fmaf(w.w, xp[0], acc);
    if (t >= 1) acc = fmaf(w.z, xp[-(2 * D_INNER)],     acc);
    if (t >= 2) acc = fmaf(w.y, xp[-2 * (2 * D_INNER)], acc);
    if (t >= 3) acc = fmaf(w.x, xp[-3 * (2 * D_INNER)], acc);
    xc[idx] = __fdividef(acc, 1.f + __expf(-acc));           // silu
}

// ---------------- selective scan (lane-per-state, warp = 2 channels) -----
// ys = (scan(xc,dt,B,C) + xc*Dskip) * silu(z)
__global__ __launch_bounds__(256) void scan_kernel(
    const float* __restrict__ dt_g, const float* __restrict__ xc_g,
    const float* __restrict__ dbl_g, const float* __restrict__ xz_g,
    const float* __restrict__ A_log, const float* __restrict__ Dsk,
    float* __restrict__ ys_g)
{
    const int gw   = (blockIdx.x * 256 + threadIdx.x) >> 5;  // 0..4095
    const int lane = threadIdx.x & 31;
    const int b    = gw >> 9;          // 512 channel-pairs per batch
    const int d0   = (gw & 511) << 1;
    const int half = lane >> 4;
    const int n    = lane & 15;
    const int d    = d0 + half;

    const float An = -__expf(__ldg(A_log + d * N_STATE + n));
    const float Dd = __ldg(Dsk + d);
    const size_t base = (size_t)b * L_SEQ;

    const float2* dtp = (const float2*)(dt_g + base * D_INNER + d0);
    const float2* xcp = (const float2*)(xc_g + base * D_INNER + d0);
    const float2* zp  = (const float2*)(xz_g + base * (2 * D_INNER) + D_INNER + d0);
    const float*  bcp = dbl_g + base * 64 + 32 + lane;   // lanes 0-15: B, 16-31: C
    float* yp = ys_g + base * D_INNER + d;

    float h = 0.f;

    float2 adt[4], axc[4], az[4]; float abc[4];
    float2 bdt[4], bxc[4], bz[4]; float bbc[4];

#define LOADQ(T0, DT, XC, Z, BC)                                         \
    {                                                                     \
        _Pragma("unroll")                                                 \
        for (int j = 0; j < 4; j++) {                                     \
            int tt = (T0) + j;                                            \
            DT[j] = __ldg(dtp + (size_t)tt * (D_INNER / 2));              \
            XC[j] = __ldg(xcp + (size_t)tt * (D_INNER / 2));              \
            Z[j]  = __ldg(zp  + (size_t)tt * D_INNER);                    \
            BC[j] = __ldg(bcp + (size_t)tt * 64);                         \
        }                                                                 \
    }

#define STEP(T, DTv, XCv, Zv, BCv)                                        \
    {                                                                     \
        float dtv = half ? (DTv).y : (DTv).x;                             \
        float xv  = half ? (XCv).y : (XCv).x;                             \
        float bn = __shfl_sync(0xffffffffu, (BCv), n);                    \
        float cn = __shfl_sync(0xffffffffu, (BCv), n + 16);               \
        float dA = __expf(dtv * An);                                      \
        h = fmaf(dA, h, dtv * xv * bn);                                   \
        float p = h * cn;                                                 \
        p += __shfl_xor_sync(0xffffffffu, p, 1);                          \
        p += __shfl_xor_sync(0xffffffffu, p, 2);                          \
        p += __shfl_xor_sync(0xffffffffu, p, 4);                          \
        p += __shfl_xor_sync(0xffffffffu, p, 8);                          \
        if (n == 0) {                                                     \
            float zv = half ? (Zv).y : (Zv).x;                            \
            float yv = fmaf(xv, Dd, p);                                   \
            yp[(size_t)(T) * D_INNER] =                                   \
                yv * __fdividef(zv, 1.f + __expf(-zv));                   \
        }                                                                 \
    }

    LOADQ(0, adt, axc, az, abc);
    for (int t0 = 0; t0 < L_SEQ; t0 += 8) {
        LOADQ(t0 + 4, bdt, bxc, bz, bbc);
#pragma unroll
        for (int j = 0; j < 4; j++) STEP(t0 + j, adt[j], axc[j], az[j], abc[j]);
        if (t0 + 8 < L_SEQ) LOADQ(t0 + 8, adt, axc, az, abc);
#pragma unroll
        for (int j = 0; j < 4; j++) STEP(t0 + 4 + j, bdt[j], bxc[j], bz[j], bbc[j]);
    }
#undef LOADQ
#undef STEP
}

// ---------------- host orchestration ----------------
extern "C" void kernel_launch(void* const* d_in, const int* in_sizes, int n_in,
                              void* d_out, int out_size)
{
    const float* y        = (const float*)d_in[0];
    const float* emb_w    = (const float*)d_in[1];
    const float* emb_b    = (const float*)d_in[2];
    const float* ln_w     = (const float*)d_in[3];
    const float* ln_b     = (const float*)d_in[4];
    const float* mix_w    = (const float*)d_in[5];
    const float* conv_w   = (const float*)d_in[6];
    const float* conv_b   = (const float*)d_in[7];
    const float* xproj_w  = (const float*)d_in[8];
    const float* dtproj_w = (const float*)d_in[9];
    const float* dtproj_b = (const float*)d_in[10];
    const float* A_log    = (const float*)d_in[11];
    const float* Dskip    = (const float*)d_in[12];
    const float* out_w    = (const float*)d_in[13];
    const float* normf_w  = (const float*)d_in[14];
    const float* normf_b  = (const float*)d_in[15];
    const float* ro1_w    = (const float*)d_in[16];
    const float* ro1_b    = (const float*)d_in[17];
    const float* ro2_w    = (const float*)d_in[18];
    const float* ro2_b    = (const float*)d_in[19];

    float *h, *xin, *xz, *xc, *dbl, *dt, *ys, *h2;
    cudaGetSymbolAddress((void**)&h,   g_h);
    cudaGetSymbolAddress((void**)&xin, g_xin);
    cudaGetSymbolAddress((void**)&xz,  g_xz);
    cudaGetSymbolAddress((void**)&xc,  g_xc);
    cudaGetSymbolAddress((void**)&dbl, g_dbl);
    cudaGetSymbolAddress((void**)&dt,  g_dt);
    cudaGetSymbolAddress((void**)&ys,  g_ys);
    cudaGetSymbolAddress((void**)&h2,  g_h2);

    const int M = BL_ROWS;

    // embedding: h = y @ emb_w^T + emb_b      (M x 512, K=32)
    gemm_k<64, 64, 16, 4, 4, EPI_BIAS><<<dim3(D_MODEL / 64, M / 64), 256>>>(
        y, P_DIM, emb_w, emb_b, nullptr, h, M, D_MODEL, P_DIM);

    for (int i = 0; i < N_LAYER; i++) {
        const float* lw  = ln_w + i * D_MODEL;
        const float* lb  = ln_b + i * D_MODEL;
        const float* mw  = mix_w + (size_t)i * 2 * D_INNER * D_MODEL;
        const float* cw  = conv_w + (size_t)i * D_INNER * 4;
        const float* cb  = conv_b + (size_t)i * D_INNER;
        const float* xpw = xproj_w + (size_t)i * 64 * D_INNER;
        const float* dpw = dtproj_w + (size_t)i * D_INNER * DT_RANK;
        const float* dpb = dtproj_b + (size_t)i * D_INNER;
        const float* Al  = A_log + (size_t)i * D_INNER * N_STATE;
        const float* Dk  = Dskip + (size_t)i * D_INNER;
        const float* ow  = out_w + (size_t)i * D_MODEL * D_INNER;

        // LN
        ln_kernel<<<M / 8, 256>>>(h, lw, lb, xin);
        // xz = xin @ mix_w^T          (M x 2048, K=512)
        gemm_k<128, 128, 16, 8, 8, EPI_NONE><<<dim3(2 * D_INNER / 128, M / 128), 256>>>(
            xin, D_MODEL, mw, nullptr, nullptr, xz, M, 2 * D_INNER, D_MODEL);
        // causal depthwise conv + silu
        conv_silu_kernel<<<(M * D_INNER) / 256, 256>>>(xz, cw, cb, xc);
        // dbl = xc @ xproj_w^T        (M x 64, K=1024)
        gemm_k<64, 64, 16, 4, 4, EPI_NONE><<<dim3(1, M / 64), 256>>>(
            xc, D_INNER, xpw, nullptr, nullptr, dbl, M, 64, D_INNER);
        // dt = softplus(dbl[:, :32] @ dtproj_w^T + b)   (M x 1024, K=32, lda=64)
        gemm_k<64, 64, 16, 4, 4, EPI_SOFTPLUS><<<dim3(D_INNER / 64, M / 64), 256>>>(
            dbl, 64, dpw, dpb, nullptr, dt, M, D_INNER, DT_RANK);
        // selective scan + gate
        scan_kernel<<<512, 256>>>(dt, xc, dbl, xz, Al, Dk, ys);
        // h = h + ys @ out_w^T        (M x 512, K=1024)
        gemm_k<128, 128, 16, 8, 8, EPI_RESID><<<dim3(D_MODEL / 128, M / 128), 256>>>(
            ys, D_INNER, ow, nullptr, h, h, M, D_MODEL, D_INNER);
    }

    // final LN
    ln_kernel<<<M / 8, 256>>>(h, normf_w, normf_b, xin);
    // h2 = gelu(xin @ ro1_w^T + ro1_b)   (M x 512, K=512)
    gemm_k<128, 128, 16, 8, 8, EPI_GELU><<<dim3(D_MODEL / 128, M / 128), 256>>>(
        xin, D_MODEL, ro1_w, ro1_b, nullptr, h2, M, D_MODEL, D_MODEL);
    // out = h2 @ ro2_w^T + ro2_b         (M x 128, K=512)
    gemm_k<64, 64, 16, 4, 4, EPI_BIAS><<<dim3(128 / 64, M / 64), 256>>>(
        h2, D_MODEL, ro2_w, ro2_b, nullptr, (float*)d_out, M, 128, D_MODEL);
}

// round 4
// speedup vs baseline: 1.7628x; 1.7628x over previous
#include <cuda_runtime.h>
#include <cuda_bf16.h>
#include <cstdint>

// ---------------- problem constants ----------------
#define B_SZ     8
#define L_SEQ    2048
#define P_DIM    32
#define D_MODEL  512
#define D_INNER  1024
#define N_STATE  16
#define DT_RANK  32
#define N_LAYER  4
#define BL_ROWS  (B_SZ * L_SEQ)          // 16384

// ---------------- scratch (static device globals) ----------------
__device__ __align__(16) float g_h  [(size_t)BL_ROWS * D_MODEL];
__device__ __align__(16) float g_xz [(size_t)BL_ROWS * 2 * D_INNER];
__device__ __align__(16) float g_xc [(size_t)BL_ROWS * D_INNER];
__device__ __align__(16) float g_dbl[(size_t)BL_ROWS * 64];
__device__ __align__(16) float g_dt [(size_t)BL_ROWS * D_INNER];

__device__ __align__(16) __nv_bfloat16 g_xin_h[(size_t)BL_ROWS * D_MODEL];
__device__ __align__(16) __nv_bfloat16 g_xin_l[(size_t)BL_ROWS * D_MODEL];
__device__ __align__(16) __nv_bfloat16 g_xc_h [(size_t)BL_ROWS * D_INNER];
__device__ __align__(16) __nv_bfloat16 g_xc_l [(size_t)BL_ROWS * D_INNER];
__device__ __align__(16) __nv_bfloat16 g_ys_h [(size_t)BL_ROWS * D_INNER];
__device__ __align__(16) __nv_bfloat16 g_ys_l [(size_t)BL_ROWS * D_INNER];
__device__ __align__(16) __nv_bfloat16 g_h2_h [(size_t)BL_ROWS * D_MODEL];
__device__ __align__(16) __nv_bfloat16 g_h2_l [(size_t)BL_ROWS * D_MODEL];

__device__ __align__(16) __nv_bfloat16 g_mixw_h[(size_t)N_LAYER * 2 * D_INNER * D_MODEL];
__device__ __align__(16) __nv_bfloat16 g_mixw_l[(size_t)N_LAYER * 2 * D_INNER * D_MODEL];
__device__ __align__(16) __nv_bfloat16 g_xpw_h [(size_t)N_LAYER * 64 * D_INNER];
__device__ __align__(16) __nv_bfloat16 g_xpw_l [(size_t)N_LAYER * 64 * D_INNER];
__device__ __align__(16) __nv_bfloat16 g_ow_h  [(size_t)N_LAYER * D_MODEL * D_INNER];
__device__ __align__(16) __nv_bfloat16 g_ow_l  [(size_t)N_LAYER * D_MODEL * D_INNER];
__device__ __align__(16) __nv_bfloat16 g_r1w_h [(size_t)D_MODEL * D_MODEL];
__device__ __align__(16) __nv_bfloat16 g_r1w_l [(size_t)D_MODEL * D_MODEL];
__device__ __align__(16) __nv_bfloat16 g_r2w_h [(size_t)128 * D_MODEL];
__device__ __align__(16) __nv_bfloat16 g_r2w_l [(size_t)128 * D_MODEL];

// ---------------- PTX helpers (arch-portable: mma.sync / ldmatrix / cp.async) --
__device__ __forceinline__ uint32_t smem_u32(const void* p) {
    uint32_t a;
    asm("{ .reg .u64 t; cvta.to.shared.u64 t, %1; cvt.u32.u64 %0, t; }"
        : "=r"(a) : "l"(p));
    return a;
}
#define CP_ASYNC16(sa, ga)                                                   \
    asm volatile("cp.async.cg.shared.global [%0], [%1], 16;"                 \
                 :: "r"(sa), "l"(ga))
#define CP_COMMIT() asm volatile("cp.async.commit_group;" ::: "memory")
#define CP_WAIT1()  asm volatile("cp.async.wait_group 1;"  ::: "memory")
#define LDSM4(R, A)                                                          \
    asm volatile("ldmatrix.sync.aligned.m8n8.x4.shared.b16 {%0,%1,%2,%3},[%4];" \
                 : "=r"((R)[0]), "=r"((R)[1]), "=r"((R)[2]), "=r"((R)[3])    \
                 : "r"(A))
#define LDSM2(R, A)                                                          \
    asm volatile("ldmatrix.sync.aligned.m8n8.x2.shared.b16 {%0,%1},[%2];"    \
                 : "=r"((R)[0]), "=r"((R)[1]) : "r"(A))
#define MMA16816(C, A, B)                                                    \
    asm volatile("mma.sync.aligned.m16n8k16.row.col.f32.bf16.bf16.f32 "      \
                 "{%0,%1,%2,%3},{%4,%5,%6,%7},{%8,%9},{%0,%1,%2,%3};"        \
                 : "+f"((C)[0]), "+f"((C)[1]), "+f"((C)[2]), "+f"((C)[3])    \
                 : "r"((A)[0]), "r"((A)[1]), "r"((A)[2]), "r"((A)[3]),       \
                   "r"((B)[0]), "r"((B)[1]))

// ---------------- epilogue ids ----------------
#define EPI_NONE     0
#define EPI_BIAS     1
#define EPI_SOFTPLUS 2
#define EPI_GELU     3
#define EPI_RESID    4

// =======================================================================
// HMMA GEMM: C[M,N] = (Ah+Al)[M,K] @ (Bh+Bl)[N,K]^T   (bf16x3, fp32 acc)
// BM=128, BK=32, 256 threads = 8 warps (2 x 4), warp tile 64 x (BN/4).
// 2-stage cp.async pipeline, 80B-padded smem rows (conflict-free ldmatrix).
// =======================================================================
template<int BN, int EPI>
__global__ __launch_bounds__(256) void mma_gemm(
    const __nv_bfloat16* __restrict__ Ah, const __nv_bfloat16* __restrict__ Al,
    const __nv_bfloat16* __restrict__ Bh, const __nv_bfloat16* __restrict__ Bl,
    const float* __restrict__ bias, const float* __restrict__ resid,
    float* __restrict__ C, __nv_bfloat16* __restrict__ Ch,
    __nv_bfloat16* __restrict__ Cl, int N, int K)
{
    extern __shared__ char smem[];
    constexpr int SA     = 80;                 // bytes per padded row (32 bf16 + pad)
    constexpr int A_TILE = 128 * SA;           // 10240
    constexpr int B_TILE = BN * SA;
    constexpr int STAGE  = 2 * A_TILE + 2 * B_TILE;
    constexpr int WN     = BN / 4;             // cols per warp
    constexpr int NT     = WN / 8;             // n8 tiles per warp

    const int tid  = threadIdx.x;
    const int wid  = tid >> 5;
    const int lane = tid & 31;
    const int wm   = wid >> 2;                 // 0..1
    const int wn   = wid & 3;                  // 0..3
    const int bm   = blockIdx.y * 128;
    const int bn   = blockIdx.x * BN;
    const uint32_t sb = smem_u32(smem);

    float acc[4][NT][4];
#pragma unroll
    for (int mt = 0; mt < 4; mt++)
#pragma unroll
        for (int nt = 0; nt < NT; nt++)
#pragma unroll
            for (int q = 0; q < 4; q++) acc[mt][nt][q] = 0.f;

    auto load_stage = [&](int c, int s) {
        const int k0 = c * 32;
        const uint32_t st = sb + s * STAGE;
#pragma unroll
        for (int i = 0; i < 2; i++) {
            int id = tid + i * 256;
            int r = id >> 2, cc = id & 3;
            uint32_t so = st + r * SA + cc * 16;
            size_t g = (size_t)(bm + r) * K + k0 + cc * 8;
            CP_ASYNC16(so,          Ah + g);
            CP_ASYNC16(so + A_TILE, Al + g);
        }
#pragma unroll
        for (int i = 0; i < BN / 64; i++) {
            int id = tid + i * 256;
            int r = id >> 2, cc = id & 3;
            uint32_t so = st + 2 * A_TILE + r * SA + cc * 16;
            size_t g = (size_t)(bn + r) * K + k0 + cc * 8;
            CP_ASYNC16(so,          Bh + g);
            CP_ASYNC16(so + B_TILE, Bl + g);
        }
        CP_COMMIT();
    };

    const int chunks = K >> 5;
    load_stage(0, 0);
    for (int c = 0; c < chunks; c++) {
        if (c + 1 < chunks) load_stage(c + 1, (c + 1) & 1);
        else                CP_COMMIT();
        CP_WAIT1();
        __syncthreads();
        const uint32_t st = sb + (c & 1) * STAGE;
#pragma unroll
        for (int ks = 0; ks < 2; ks++) {
            uint32_t ah[4][4], al[4][4];
#pragma unroll
            for (int mt = 0; mt < 4; mt++) {
                uint32_t row = wm * 64 + mt * 16 + (lane & 15);
                uint32_t ad = st + row * SA + ks * 32 + ((lane >> 4) << 4);
                LDSM4(ah[mt], ad);
                LDSM4(al[mt], ad + A_TILE);
            }
#pragma unroll
            for (int nt = 0; nt < NT; nt++) {
                uint32_t rn = wn * WN + nt * 8 + (lane & 7);
                uint32_t bd = st + 2 * A_TILE + rn * SA + ks * 32 +
                              (((lane >> 3) & 1) << 4);
                uint32_t bh2[2], bl2[2];
                LDSM2(bh2, bd);
                LDSM2(bl2, bd + B_TILE);
#pragma unroll
                for (int mt = 0; mt < 4; mt++) {
                    MMA16816(acc[mt][nt], ah[mt], bh2);
                    MMA16816(acc[mt][nt], ah[mt], bl2);
                    MMA16816(acc[mt][nt], al[mt], bh2);
                }
            }
        }
        __syncthreads();
    }

    // ---------------- epilogue ----------------
#pragma unroll
    for (int mt = 0; mt < 4; mt++) {
#pragma unroll
        for (int nt = 0; nt < NT; nt++) {
            int r0 = bm + wm * 64 + mt * 16 + (lane >> 2);
            int c0 = bn + wn * WN + nt * 8 + (lane & 3) * 2;
#pragma unroll
            for (int half = 0; half < 2; half++) {
                int row = r0 + half * 8;
                float v0 = acc[mt][nt][half * 2];
                float v1 = acc[mt][nt][half * 2 + 1];
                size_t idx = (size_t)row * N + c0;
                if constexpr (EPI == EPI_BIAS || EPI == EPI_GELU) {
                    v0 += bias[c0];
                    v1 += bias[c0 + 1];
                }
                if constexpr (EPI == EPI_GELU) {
                    float u0 = 0.7978845608028654f * (v0 + 0.044715f * v0 * v0 * v0);
                    float u1 = 0.7978845608028654f * (v1 + 0.044715f * v1 * v1 * v1);
                    v0 = 0.5f * v0 * (1.f + tanhf(u0));
                    v1 = 0.5f * v1 * (1.f + tanhf(u1));
                    __nv_bfloat16 h0 = __float2bfloat16(v0);
                    __nv_bfloat16 h1 = __float2bfloat16(v1);
                    __nv_bfloat16 l0 = __float2bfloat16(v0 - __bfloat162float(h0));
                    __nv_bfloat16 l1 = __float2bfloat16(v1 - __bfloat162float(h1));
                    *(__nv_bfloat162*)(Ch + idx) = __nv_bfloat162(h0, h1);
                    *(__nv_bfloat162*)(Cl + idx) = __nv_bfloat162(l0, l1);
                } else {
                    if constexpr (EPI == EPI_RESID) {
                        float2 rr = *(const float2*)(resid + idx);
                        v0 += rr.x; v1 += rr.y;
                    }
                    *(float2*)(C + idx) = make_float2(v0, v1);
                }
            }
        }
    }
}

// ---------------- fp32 -> bf16 hi/lo decomposition ----------------
__global__ __launch_bounds__(256) void decomp_kernel(
    const float* __restrict__ x, __nv_bfloat16* __restrict__ h,
    __nv_bfloat16* __restrict__ l)
{
    int i = blockIdx.x * 256 + threadIdx.x;
    float4 v = ((const float4*)x)[i];
    __nv_bfloat16 h0 = __float2bfloat16(v.x), h1 = __float2bfloat16(v.y);
    __nv_bfloat16 h2 = __float2bfloat16(v.z), h3 = __float2bfloat16(v.w);
    __nv_bfloat16 l0 = __float2bfloat16(v.x - __bfloat162float(h0));
    __nv_bfloat16 l1 = __float2bfloat16(v.y - __bfloat162float(h1));
    __nv_bfloat16 l2 = __float2bfloat16(v.z - __bfloat162float(h2));
    __nv_bfloat16 l3 = __float2bfloat16(v.w - __bfloat162float(h3));
    ((__nv_bfloat162*)h)[i * 2]     = __nv_bfloat162(h0, h1);
    ((__nv_bfloat162*)h)[i * 2 + 1] = __nv_bfloat162(h2, h3);
    ((__nv_bfloat162*)l)[i * 2]     = __nv_bfloat162(l0, l1);
    ((__nv_bfloat162*)l)[i * 2 + 1] = __nv_bfloat162(l2, l3);
}

// ---------------- SIMT GEMM (small K only: embed, dtproj) ----------------
template<int BM, int BN, int BK, int TM, int TN, int EPI>
__global__ __launch_bounds__(256) void gemm_k(
    const float* __restrict__ A, int lda,
    const float* __restrict__ W,
    const float* __restrict__ bias,
    float* __restrict__ C,
    int M, int N, int K)
{
    __shared__ float As[BK][BM];
    __shared__ float Ws[BK][BN];
    const int tid = threadIdx.x;
    const int bm = blockIdx.y * BM;
    const int bn = blockIdx.x * BN;
    constexpr int TX = BN / TN;
    const int tx = tid % TX;
    const int ty = tid / TX;

    float acc[TM][TN];
#pragma unroll
    for (int i = 0; i < TM; i++)
#pragma unroll
        for (int j = 0; j < TN; j++) acc[i][j] = 0.f;

    for (int k0 = 0; k0 < K; k0 += BK) {
#pragma unroll
        for (int i = tid; i < BM * BK; i += 256) {
            int r = i / BK, c = i % BK;
            As[c][r] = A[(size_t)(bm + r) * lda + k0 + c];
        }
#pragma unroll
        for (int i = tid; i < BN * BK; i += 256) {
            int r = i / BK, c = i % BK;
            Ws[c][r] = W[(size_t)(bn + r) * K + k0 + c];
        }
        __syncthreads();
#pragma unroll
        for (int kk = 0; kk < BK; kk++) {
            float ra[TM], rw[TN];
#pragma unroll
            for (int i = 0; i < TM; i++) ra[i] = As[kk][ty * TM + i];
#pragma unroll
            for (int j = 0; j < TN; j++) rw[j] = Ws[kk][tx * TN + j];
#pragma unroll
            for (int i = 0; i < TM; i++)
#pragma unroll
                for (int j = 0; j < TN; j++)
                    acc[i][j] = fmaf(ra[i], rw[j], acc[i][j]);
        }
        __syncthreads();
    }
#pragma unroll
    for (int i = 0; i < TM; i++) {
        int row = bm + ty * TM + i;
#pragma unroll
        for (int j = 0; j < TN; j++) {
            int col = bn + tx * TN + j;
            float v = acc[i][j];
            if constexpr (EPI == EPI_BIAS || EPI == EPI_SOFTPLUS) v += bias[col];
            if constexpr (EPI == EPI_SOFTPLUS)
                v = (v > 20.f) ? v : log1pf(__expf(v));
            C[(size_t)row * N + col] = v;
        }
    }
}

// ---------------- layernorm -> bf16 hi/lo, one warp per row ----------------
__global__ __launch_bounds__(256) void ln_kernel(
    const float* __restrict__ x, const float* __restrict__ w,
    const float* __restrict__ bb,
    __nv_bfloat16* __restrict__ oh, __nv_bfloat16* __restrict__ ol)
{
    int row  = blockIdx.x * 8 + (threadIdx.x >> 5);
    int lane = threadIdx.x & 31;
    const float* xr = x + (size_t)row * D_MODEL + lane;
    float v[16];
    float s = 0.f, s2 = 0.f;
#pragma unroll
    for (int i = 0; i < 16; i++) {
        v[i] = xr[i * 32];
        s += v[i];
        s2 = fmaf(v[i], v[i], s2);
    }
#pragma unroll
    for (int k = 16; k; k >>= 1) {
        s  += __shfl_xor_sync(0xffffffffu, s,  k);
        s2 += __shfl_xor_sync(0xffffffffu, s2, k);
    }
    float mu  = s * (1.f / 512.f);
    float var = fmaf(s2, 1.f / 512.f, -mu * mu);
    float rs  = rsqrtf(var + 1e-5f);
    size_t ob = (size_t)row * D_MODEL + lane;
#pragma unroll
    for (int i = 0; i < 16; i++) {
        float o = (v[i] - mu) * rs * w[lane + i * 32] + bb[lane + i * 32];
        __nv_bfloat16 hv = __float2bfloat16(o);
        oh[ob + i * 32] = hv;
        ol[ob + i * 32] = __float2bfloat16(o - __bfloat162float(hv));
    }
}

// ---------------- causal depthwise conv (k=4) + SiLU -> fp32 + hi/lo ------
__global__ __launch_bounds__(256) void conv_silu_kernel(
    const float* __restrict__ xz, const float* __restrict__ cw,
    const float* __restrict__ cb, float* __restrict__ xc,
    __nv_bfloat16* __restrict__ xch, __nv_bfloat16* __restrict__ xcl)
{
    int idx = blockIdx.x * 256 + threadIdx.x;
    int d  = idx & (D_INNER - 1);
    int bl = idx >> 10;
    int t  = bl & (L_SEQ - 1);
    const float* xp = xz + (size_t)bl * (2 * D_INNER) + d;
    float4 w = __ldg((const float4*)cw + d);
    float acc = cb[d];
    acc = fmaf(w.w, xp[0], acc);
    if (t >= 1) acc = fmaf(w.z, xp[-(2 * D_INNER)],     acc);
    if (t >= 2) acc = fmaf(w.y, xp[-2 * (2 * D_INNER)], acc);
    if (t >= 3) acc = fmaf(w.x, xp[-3 * (2 * D_INNER)], acc);
    float s = __fdividef(acc, 1.f + __expf(-acc));
    xc[idx] = s;
    __nv_bfloat16 hv = __float2bfloat16(s);
    xch[idx] = hv;
    xcl[idx] = __float2bfloat16(s - __bfloat162float(hv));
}

// ---------------- selective scan -> ys hi/lo ----------------
__global__ __launch_bounds__(256) void scan_kernel(
    const float* __restrict__ dt_g, const float* __restrict__ xc_g,
    const float* __restrict__ dbl_g, const float* __restrict__ xz_g,
    const float* __restrict__ A_log, const float* __restrict__ Dsk,
    __nv_bfloat16* __restrict__ ysh, __nv_bfloat16* __restrict__ ysl)
{
    const int gw   = (blockIdx.x * 256 + threadIdx.x) >> 5;
    const int lane = threadIdx.x & 31;
    const int b    = gw >> 9;
    const int d0   = (gw & 511) << 1;
    const int half = lane >> 4;
    const int n    = lane & 15;
    const int d    = d0 + half;

    const float An = -__expf(__ldg(A_log + d * N_STATE + n));
    const float Dd = __ldg(Dsk + d);
    const size_t base = (size_t)b * L_SEQ;

    const float2* dtp = (const float2*)(dt_g + base * D_INNER + d0);
    const float2* xcp = (const float2*)(xc_g + base * D_INNER + d0);
    const float2* zp  = (const float2*)(xz_g + base * (2 * D_INNER) + D_INNER + d0);
    const float*  bcp = dbl_g + base * 64 + 32 + lane;
    __nv_bfloat16* yph = ysh + base * D_INNER + d;
    __nv_bfloat16* ypl = ysl + base * D_INNER + d;

    float h = 0.f;
    float2 adt[4], axc[4], az[4]; float abc[4];
    float2 bdt[4], bxc[4], bz[4]; float bbc[4];

#define LOADQ(T0, DT, XC, Z, BC)                                          \
    {                                                                     \
        _Pragma("unroll")                                                 \
        for (int j = 0; j < 4; j++) {                                     \
            int tt = (T0) + j;                                            \
            DT[j] = __ldg(dtp + (size_t)tt * (D_INNER / 2));              \
            XC[j] = __ldg(xcp + (size_t)tt * (D_INNER / 2));              \
            Z[j]  = __ldg(zp  + (size_t)tt * D_INNER);                    \
            BC[j] = __ldg(bcp + (size_t)tt * 64);                        \
        }                                                                 \
    }
#define STEP(T, DTv, XCv, Zv, BCv)                                        \
    {                                                                     \
        float dtv = half ? (DTv).y : (DTv).x;                             \
        float xv  = half ? (XCv).y : (XCv).x;                             \
        float bn = __shfl_sync(0xffffffffu, (BCv), n);                    \
        float cn = __shfl_sync(0xffffffffu, (BCv), n + 16);               \
        float dA = __expf(dtv * An);                                      \
        h = fmaf(dA, h, dtv * xv * bn);                                   \
        float p = h * cn;                                                 \
        p += __shfl_xor_sync(0xffffffffu, p, 1);                          \
        p += __shfl_xor_sync(0xffffffffu, p, 2);                          \
        p += __shfl_xor_sync(0xffffffffu, p, 4);                          \
        p += __shfl_xor_sync(0xffffffffu, p, 8);                          \
        if (n == 0) {                                                     \
            float zv = half ? (Zv).y : (Zv).x;                            \
            float yv = fmaf(xv, Dd, p);                                   \
            float o  = yv * __fdividef(zv, 1.f + __expf(-zv));            \
            __nv_bfloat16 hv = __float2bfloat16(o);                       \
            yph[(size_t)(T) * D_INNER] = hv;                              \
            ypl[(size_t)(T) * D_INNER] =                                  \
                __float2bfloat16(o - __bfloat162float(hv));               \
        }                                                                 \
    }

    LOADQ(0, adt, axc, az, abc);
    for (int t0 = 0; t0 < L_SEQ; t0 += 8) {
        LOADQ(t0 + 4, bdt, bxc, bz, bbc);
#pragma unroll
        for (int j = 0; j < 4; j++) STEP(t0 + j, adt[j], axc[j], az[j], abc[j]);
        if (t0 + 8 < L_SEQ) LOADQ(t0 + 8, adt, axc, az, abc);
#pragma unroll
        for (int j = 0; j < 4; j++) STEP(t0 + 4 + j, bdt[j], bxc[j], bz[j], bbc[j]);
    }
#undef LOADQ
#undef STEP
}

// ---------------- host orchestration ----------------
extern "C" void kernel_launch(void* const* d_in, const int* in_sizes, int n_in,
                              void* d_out, int out_size)
{
    const float* y        = (const float*)d_in[0];
    const float* emb_w    = (const float*)d_in[1];
    const float* emb_b    = (const float*)d_in[2];
    const float* ln_w     = (const float*)d_in[3];
    const float* ln_b     = (const float*)d_in[4];
    const float* mix_w    = (const float*)d_in[5];
    const float* conv_w   = (const float*)d_in[6];
    const float* conv_b   = (const float*)d_in[7];
    const float* xproj_w  = (const float*)d_in[8];
    const float* dtproj_w = (const float*)d_in[9];
    const float* dtproj_b = (const float*)d_in[10];
    const float* A_log    = (const float*)d_in[11];
    const float* Dskip    = (const float*)d_in[12];
    const float* out_w    = (const float*)d_in[13];
    const float* normf_w  = (const float*)d_in[14];
    const float* normf_b  = (const float*)d_in[15];
    const float* ro1_w    = (const float*)d_in[16];
    const float* ro1_b    = (const float*)d_in[17];
    const float* ro2_w    = (const float*)d_in[18];
    const float* ro2_b    = (const float*)d_in[19];

    float *h, *xz, *xc, *dbl, *dt;
    cudaGetSymbolAddress((void**)&h,   g_h);
    cudaGetSymbolAddress((void**)&xz,  g_xz);
    cudaGetSymbolAddress((void**)&xc,  g_xc);
    cudaGetSymbolAddress((void**)&dbl, g_dbl);
    cudaGetSymbolAddress((void**)&dt,  g_dt);
    __nv_bfloat16 *xin_h, *xin_l, *xc_h, *xc_l, *ys_h, *ys_l, *h2_h, *h2_l;
    __nv_bfloat16 *mw_h, *mw_l, *xpw_h, *xpw_l, *ow_h, *ow_l, *r1_h, *r1_l, *r2_h, *r2_l;
    cudaGetSymbolAddress((void**)&xin_h, g_xin_h);
    cudaGetSymbolAddress((void**)&xin_l, g_xin_l);
    cudaGetSymbolAddress((void**)&xc_h,  g_xc_h);
    cudaGetSymbolAddress((void**)&xc_l,  g_xc_l);
    cudaGetSymbolAddress((void**)&ys_h,  g_ys_h);
    cudaGetSymbolAddress((void**)&ys_l,  g_ys_l);
    cudaGetSymbolAddress((void**)&h2_h,  g_h2_h);
    cudaGetSymbolAddress((void**)&h2_l,  g_h2_l);
    cudaGetSymbolAddress((void**)&mw_h,  g_mixw_h);
    cudaGetSymbolAddress((void**)&mw_l,  g_mixw_l);
    cudaGetSymbolAddress((void**)&xpw_h, g_xpw_h);
    cudaGetSymbolAddress((void**)&xpw_l, g_xpw_l);
    cudaGetSymbolAddress((void**)&ow_h,  g_ow_h);
    cudaGetSymbolAddress((void**)&ow_l,  g_ow_l);
    cudaGetSymbolAddress((void**)&r1_h,  g_r1w_h);
    cudaGetSymbolAddress((void**)&r1_l,  g_r1w_l);
    cudaGetSymbolAddress((void**)&r2_h,  g_r2w_h);
    cudaGetSymbolAddress((void**)&r2_l,  g_r2w_l);

    const int M = BL_ROWS;
    constexpr int S128 = 2 * (2 * 128 * 80 + 2 * 128 * 80);   // 81920
    constexpr int S64  = 2 * (2 * 128 * 80 + 2 * 64 * 80);    // 61440
    cudaFuncSetAttribute(mma_gemm<128, EPI_NONE>,  cudaFuncAttributeMaxDynamicSharedMemorySize, S128);
    cudaFuncSetAttribute(mma_gemm<128, EPI_RESID>, cudaFuncAttributeMaxDynamicSharedMemorySize, S128);
    cudaFuncSetAttribute(mma_gemm<128, EPI_GELU>,  cudaFuncAttributeMaxDynamicSharedMemorySize, S128);
    cudaFuncSetAttribute(mma_gemm<128, EPI_BIAS>,  cudaFuncAttributeMaxDynamicSharedMemorySize, S128);
    cudaFuncSetAttribute(mma_gemm<64,  EPI_NONE>,  cudaFuncAttributeMaxDynamicSharedMemorySize, S64);

    // decompose weights (every call; deterministic)
    decomp_kernel<<<(N_LAYER * 2 * D_INNER * D_MODEL) / 1024, 256>>>(mix_w, mw_h, mw_l);
    decomp_kernel<<<(N_LAYER * 64 * D_INNER) / 1024, 256>>>(xproj_w, xpw_h, xpw_l);
    decomp_kernel<<<(N_LAYER * D_MODEL * D_INNER) / 1024, 256>>>(out_w, ow_h, ow_l);
    decomp_kernel<<<(D_MODEL * D_MODEL) / 1024, 256>>>(ro1_w, r1_h, r1_l);
    decomp_kernel<<<(128 * D_MODEL) / 1024, 256>>>(ro2_w, r2_h, r2_l);

    // embedding (SIMT, K=32): h = y @ emb_w^T + emb_b
    gemm_k<64, 64, 16, 4, 4, EPI_BIAS><<<dim3(D_MODEL / 64, M / 64), 256>>>(
        y, P_DIM, emb_w, emb_b, h, M, D_MODEL, P_DIM);

    for (int i = 0; i < N_LAYER; i++) {
        const float* lw  = ln_w + i * D_MODEL;
        const float* lb  = ln_b + i * D_MODEL;
        const float* cw  = conv_w + (size_t)i * D_INNER * 4;
        const float* cb  = conv_b + (size_t)i * D_INNER;
        const float* dpw = dtproj_w + (size_t)i * D_INNER * DT_RANK;
        const float* dpb = dtproj_b + (size_t)i * D_INNER;
        const float* Al  = A_log + (size_t)i * D_INNER * N_STATE;
        const float* Dk  = Dskip + (size_t)i * D_INNER;

        // LN -> bf16 hi/lo
        ln_kernel<<<M / 8, 256>>>(h, lw, lb, xin_h, xin_l);
        // xz = xin @ mix_w^T   (M x 2048, K=512) HMMA
        mma_gemm<128, EPI_NONE><<<dim3(16, M / 128), 256, S128>>>(
            xin_h, xin_l,
            mw_h + (size_t)i * 2 * D_INNER * D_MODEL,
            mw_l + (size_t)i * 2 * D_INNER * D_MODEL,
            nullptr, nullptr, xz, nullptr, nullptr, 2 * D_INNER, D_MODEL);
        // conv + silu -> xc fp32 + hi/lo
        conv_silu_kernel<<<(M * D_INNER) / 256, 256>>>(xz, cw, cb, xc, xc_h, xc_l);
        // dbl = xc @ xproj_w^T  (M x 64, K=1024) HMMA
        mma_gemm<64, EPI_NONE><<<dim3(1, M / 128), 256, S64>>>(
            xc_h, xc_l,
            xpw_h + (size_t)i * 64 * D_INNER, xpw_l + (size_t)i * 64 * D_INNER,
            nullptr, nullptr, dbl, nullptr, nullptr, 64, D_INNER);
        // dt = softplus(dbl[:, :32] @ dtproj_w^T + b)  (SIMT, K=32)
        gemm_k<64, 64, 16, 4, 4, EPI_SOFTPLUS><<<dim3(D_INNER / 64, M / 64), 256>>>(
            dbl, 64, dpw, dpb, dt, M, D_INNER, DT_RANK);
        // selective scan + gate -> ys hi/lo
        scan_kernel<<<512, 256>>>(dt, xc, dbl, xz, Al, Dk, ys_h, ys_l);
        // h = h + ys @ out_w^T  (M x 512, K=1024) HMMA
        mma_gemm<128, EPI_RESID><<<dim3(4, M / 128), 256, S128>>>(
            ys_h, ys_l,
            ow_h + (size_t)i * D_MODEL * D_INNER, ow_l + (size_t)i * D_MODEL * D_INNER,
            nullptr, h, h, nullptr, nullptr, D_MODEL, D_INNER);
    }

    // final LN -> hi/lo
    ln_kernel<<<M / 8, 256>>>(h, normf_w, normf_b, xin_h, xin_l);
    // h2 = gelu(xin @ ro1_w^T + b)  (M x 512, K=512) HMMA -> hi/lo
    mma_gemm<128, EPI_GELU><<<dim3(4, M / 128), 256, S128>>>(
        xin_h, xin_l, r1_h, r1_l, ro1_b, nullptr,
        nullptr, h2_h, h2_l, D_MODEL, D_MODEL);
    // out = h2 @ ro2_w^T + b  (M x 128, K=512) HMMA
    mma_gemm<128, EPI_BIAS><<<dim3(1, M / 128), 256, S128>>>(
        h2_h, h2_l, r2_h, r2_l, ro2_b, nullptr,
        (float*)d_out, nullptr, nullptr, 128, D_MODEL);
}

// round 5
// speedup vs baseline: 1.8195x; 1.0322x over previous
#include <cuda_runtime.h>
#include <cuda_bf16.h>
#include <cstdint>

// ---------------- problem constants ----------------
#define B_SZ     8
#define L_SEQ    2048
#define P_DIM    32
#define D_MODEL  512
#define D_INNER  1024
#define N_STATE  16
#define DT_RANK  32
#define N_LAYER  4
#define BL_ROWS  (B_SZ * L_SEQ)          // 16384

// ---------------- scratch (static device globals) ----------------
__device__ __align__(16) float g_h  [(size_t)BL_ROWS * D_MODEL];
__device__ __align__(16) float g_xz [(size_t)BL_ROWS * 2 * D_INNER];
__device__ __align__(16) float g_xc [(size_t)BL_ROWS * D_INNER];
__device__ __align__(16) float g_dbl[(size_t)BL_ROWS * 64];
__device__ __align__(16) float g_dt [(size_t)BL_ROWS * D_INNER];

__device__ __align__(16) __nv_bfloat16 g_xin_h[(size_t)BL_ROWS * D_MODEL];
__device__ __align__(16) __nv_bfloat16 g_xin_l[(size_t)BL_ROWS * D_MODEL];
__device__ __align__(16) __nv_bfloat16 g_xc_h [(size_t)BL_ROWS * D_INNER];
__device__ __align__(16) __nv_bfloat16 g_xc_l [(size_t)BL_ROWS * D_INNER];
__device__ __align__(16) __nv_bfloat16 g_ys_h [(size_t)BL_ROWS * D_INNER];
__device__ __align__(16) __nv_bfloat16 g_ys_l [(size_t)BL_ROWS * D_INNER];
__device__ __align__(16) __nv_bfloat16 g_h2_h [(size_t)BL_ROWS * D_MODEL];
__device__ __align__(16) __nv_bfloat16 g_h2_l [(size_t)BL_ROWS * D_MODEL];

__device__ __align__(16) __nv_bfloat16 g_mixw_h[(size_t)N_LAYER * 2 * D_INNER * D_MODEL];
__device__ __align__(16) __nv_bfloat16 g_mixw_l[(size_t)N_LAYER * 2 * D_INNER * D_MODEL];
__device__ __align__(16) __nv_bfloat16 g_xpw_h [(size_t)N_LAYER * 64 * D_INNER];
__device__ __align__(16) __nv_bfloat16 g_xpw_l [(size_t)N_LAYER * 64 * D_INNER];
__device__ __align__(16) __nv_bfloat16 g_ow_h  [(size_t)N_LAYER * D_MODEL * D_INNER];
__device__ __align__(16) __nv_bfloat16 g_ow_l  [(size_t)N_LAYER * D_MODEL * D_INNER];
__device__ __align__(16) __nv_bfloat16 g_r1w_h [(size_t)D_MODEL * D_MODEL];
__device__ __align__(16) __nv_bfloat16 g_r1w_l [(size_t)D_MODEL * D_MODEL];
__device__ __align__(16) __nv_bfloat16 g_r2w_h [(size_t)128 * D_MODEL];
__device__ __align__(16) __nv_bfloat16 g_r2w_l [(size_t)128 * D_MODEL];

// ---------------- PTX helpers ----------------
__device__ __forceinline__ uint32_t smem_u32(const void* p) {
    uint32_t a;
    asm("{ .reg .u64 t; cvta.to.shared.u64 t, %1; cvt.u32.u64 %0, t; }"
        : "=r"(a) : "l"(p));
    return a;
}
#define CP_ASYNC16(sa, ga)                                                   \
    asm volatile("cp.async.cg.shared.global [%0], [%1], 16;"                 \
                 :: "r"(sa), "l"(ga))
#define CP_COMMIT() asm volatile("cp.async.commit_group;" ::: "memory")
#define CP_WAIT1()  asm volatile("cp.async.wait_group 1;"  ::: "memory")
#define CP_WAIT2()  asm volatile("cp.async.wait_group 2;"  ::: "memory")
#define LDSM4(R, A)                                                          \
    asm volatile("ldmatrix.sync.aligned.m8n8.x4.shared.b16 {%0,%1,%2,%3},[%4];" \
                 : "=r"((R)[0]), "=r"((R)[1]), "=r"((R)[2]), "=r"((R)[3])    \
                 : "r"(A))
#define LDSM2(R, A)                                                          \
    asm volatile("ldmatrix.sync.aligned.m8n8.x2.shared.b16 {%0,%1},[%2];"    \
                 : "=r"((R)[0]), "=r"((R)[1]) : "r"(A))
#define MMA16816(C, A, B)                                                    \
    asm volatile("mma.sync.aligned.m16n8k16.row.col.f32.bf16.bf16.f32 "      \
                 "{%0,%1,%2,%3},{%4,%5,%6,%7},{%8,%9},{%0,%1,%2,%3};"        \
                 : "+f"((C)[0]), "+f"((C)[1]), "+f"((C)[2]), "+f"((C)[3])    \
                 : "r"((A)[0]), "r"((A)[1]), "r"((A)[2]), "r"((A)[3]),       \
                   "r"((B)[0]), "r"((B)[1]))

// ---------------- epilogue ids ----------------
#define EPI_NONE     0
#define EPI_BIAS     1
#define EPI_SOFTPLUS 2
#define EPI_GELU     3
#define EPI_RESID    4

// =======================================================================
// Big HMMA GEMM: BM=256, BN=128, BK=32, 512 threads (16 warps, 4x4),
// warp tile 64x32, 3-stage cp.async pipeline. bf16x3 split, fp32 acc.
// =======================================================================
template<int EPI>
__global__ __launch_bounds__(512) void mma_gemm2(
    const __nv_bfloat16* __restrict__ Ah, const __nv_bfloat16* __restrict__ Al,
    const __nv_bfloat16* __restrict__ Bh, const __nv_bfloat16* __restrict__ Bl,
    const float* __restrict__ bias, const float* __restrict__ resid,
    float* __restrict__ C, __nv_bfloat16* __restrict__ Ch,
    __nv_bfloat16* __restrict__ Cl, int N, int K)
{
    extern __shared__ char smem[];
    constexpr int SA     = 80;
    constexpr int A_TILE = 256 * SA;           // 20480
    constexpr int B_TILE = 128 * SA;           // 10240
    constexpr int STAGE  = 2 * A_TILE + 2 * B_TILE;  // 61440

    const int tid  = threadIdx.x;
    const int wid  = tid >> 5;
    const int lane = tid & 31;
    const int wm   = wid >> 2;                 // 0..3
    const int wn   = wid & 3;                  // 0..3
    const int bm   = blockIdx.y * 256;
    const int bn   = blockIdx.x * 128;
    const uint32_t sb = smem_u32(smem);

    float acc[4][4][4];
#pragma unroll
    for (int mt = 0; mt < 4; mt++)
#pragma unroll
        for (int nt = 0; nt < 4; nt++)
#pragma unroll
            for (int q = 0; q < 4; q++) acc[mt][nt][q] = 0.f;

    auto load_stage = [&](int c, int s) {
        const int k0 = c * 32;
        const uint32_t st = sb + s * STAGE;
#pragma unroll
        for (int i = 0; i < 2; i++) {
            int id = tid + i * 512;
            int r = id >> 2, cc = id & 3;
            uint32_t so = st + r * SA + cc * 16;
            size_t g = (size_t)(bm + r) * K + k0 + cc * 8;
            CP_ASYNC16(so,          Ah + g);
            CP_ASYNC16(so + A_TILE, Al + g);
        }
        {
            int r = tid >> 2, cc = tid & 3;
            uint32_t so = st + 2 * A_TILE + r * SA + cc * 16;
            size_t g = (size_t)(bn + r) * K + k0 + cc * 8;
            CP_ASYNC16(so,          Bh + g);
            CP_ASYNC16(so + B_TILE, Bl + g);
        }
        CP_COMMIT();
    };

    const int chunks = K >> 5;
    load_stage(0, 0);
    load_stage(1, 1);
    int s = 0;                                  // stage of chunk c
    for (int c = 0; c < chunks; c++) {
        int s2 = s + 2; if (s2 >= 3) s2 -= 3;
        if (c + 2 < chunks) load_stage(c + 2, s2);
        else                CP_COMMIT();
        CP_WAIT2();
        __syncthreads();
        const uint32_t st = sb + s * STAGE;
#pragma unroll
        for (int ks = 0; ks < 2; ks++) {
            uint32_t ah[4][4], al[4][4];
#pragma unroll
            for (int mt = 0; mt < 4; mt++) {
                uint32_t row = wm * 64 + mt * 16 + (lane & 15);
                uint32_t ad = st + row * SA + ks * 32 + ((lane >> 4) << 4);
                LDSM4(ah[mt], ad);
                LDSM4(al[mt], ad + A_TILE);
            }
#pragma unroll
            for (int nt = 0; nt < 4; nt++) {
                uint32_t rn = wn * 32 + nt * 8 + (lane & 7);
                uint32_t bd = st + 2 * A_TILE + rn * SA + ks * 32 +
                              (((lane >> 3) & 1) << 4);
                uint32_t bh2[2], bl2[2];
                LDSM2(bh2, bd);
                LDSM2(bl2, bd + B_TILE);
#pragma unroll
                for (int mt = 0; mt < 4; mt++) {
                    MMA16816(acc[mt][nt], ah[mt], bh2);
                    MMA16816(acc[mt][nt], ah[mt], bl2);
                    MMA16816(acc[mt][nt], al[mt], bh2);
                }
            }
        }
        __syncthreads();
        if (++s >= 3) s -= 3;
    }

    // ---------------- epilogue ----------------
#pragma unroll
    for (int mt = 0; mt < 4; mt++) {
#pragma unroll
        for (int nt = 0; nt < 4; nt++) {
            int r0 = bm + wm * 64 + mt * 16 + (lane >> 2);
            int c0 = bn + wn * 32 + nt * 8 + (lane & 3) * 2;
#pragma unroll
            for (int half = 0; half < 2; half++) {
                int row = r0 + half * 8;
                float v0 = acc[mt][nt][half * 2];
                float v1 = acc[mt][nt][half * 2 + 1];
                size_t idx = (size_t)row * N + c0;
                if constexpr (EPI == EPI_BIAS || EPI == EPI_GELU) {
                    v0 += bias[c0];
                    v1 += bias[c0 + 1];
                }
                if constexpr (EPI == EPI_GELU) {
                    float u0 = 0.7978845608028654f * (v0 + 0.044715f * v0 * v0 * v0);
                    float u1 = 0.7978845608028654f * (v1 + 0.044715f * v1 * v1 * v1);
                    v0 = 0.5f * v0 * (1.f + tanhf(u0));
                    v1 = 0.5f * v1 * (1.f + tanhf(u1));
                    __nv_bfloat16 h0 = __float2bfloat16(v0);
                    __nv_bfloat16 h1 = __float2bfloat16(v1);
                    __nv_bfloat16 l0 = __float2bfloat16(v0 - __bfloat162float(h0));
                    __nv_bfloat16 l1 = __float2bfloat16(v1 - __bfloat162float(h1));
                    *(__nv_bfloat162*)(Ch + idx) = __nv_bfloat162(h0, h1);
                    *(__nv_bfloat162*)(Cl + idx) = __nv_bfloat162(l0, l1);
                } else {
                    if constexpr (EPI == EPI_RESID) {
                        float2 rr = *(const float2*)(resid + idx);
                        v0 += rr.x; v1 += rr.y;
                    }
                    *(float2*)(C + idx) = make_float2(v0, v1);
                }
            }
        }
    }
}

// =======================================================================
// Small HMMA GEMM (kept from R4): BM=128, BK=32, 256 threads, 2-stage.
// Used for xproj (N=64) and ro2 (N=128).
// =======================================================================
template<int BN, int EPI>
__global__ __launch_bounds__(256) void mma_gemm(
    const __nv_bfloat16* __restrict__ Ah, const __nv_bfloat16* __restrict__ Al,
    const __nv_bfloat16* __restrict__ Bh, const __nv_bfloat16* __restrict__ Bl,
    const float* __restrict__ bias, const float* __restrict__ resid,
    float* __restrict__ C, __nv_bfloat16* __restrict__ Ch,
    __nv_bfloat16* __restrict__ Cl, int N, int K)
{
    extern __shared__ char smem[];
    constexpr int SA     = 80;
    constexpr int A_TILE = 128 * SA;
    constexpr int B_TILE = BN * SA;
    constexpr int STAGE  = 2 * A_TILE + 2 * B_TILE;
    constexpr int WN     = BN / 4;
    constexpr int NT     = WN / 8;

    const int tid  = threadIdx.x;
    const int wid  = tid >> 5;
    const int lane = tid & 31;
    const int wm   = wid >> 2;
    const int wn   = wid & 3;
    const int bm   = blockIdx.y * 128;
    const int bn   = blockIdx.x * BN;
    const uint32_t sb = smem_u32(smem);

    float acc[4][NT][4];
#pragma unroll
    for (int mt = 0; mt < 4; mt++)
#pragma unroll
        for (int nt = 0; nt < NT; nt++)
#pragma unroll
            for (int q = 0; q < 4; q++) acc[mt][nt][q] = 0.f;

    auto load_stage = [&](int c, int s) {
        const int k0 = c * 32;
        const uint32_t st = sb + s * STAGE;
#pragma unroll
        for (int i = 0; i < 2; i++) {
            int id = tid + i * 256;
            int r = id >> 2, cc = id & 3;
            uint32_t so = st + r * SA + cc * 16;
            size_t g = (size_t)(bm + r) * K + k0 + cc * 8;
            CP_ASYNC16(so,          Ah + g);
            CP_ASYNC16(so + A_TILE, Al + g);
        }
#pragma unroll
        for (int i = 0; i < BN / 64; i++) {
            int id = tid + i * 256;
            int r = id >> 2, cc = id & 3;
            uint32_t so = st + 2 * A_TILE + r * SA + cc * 16;
            size_t g = (size_t)(bn + r) * K + k0 + cc * 8;
            CP_ASYNC16(so,          Bh + g);
            CP_ASYNC16(so + B_TILE, Bl + g);
        }
        CP_COMMIT();
    };

    const int chunks = K >> 5;
    load_stage(0, 0);
    for (int c = 0; c < chunks; c++) {
        if (c + 1 < chunks) load_stage(c + 1, (c + 1) & 1);
        else                CP_COMMIT();
        CP_WAIT1();
        __syncthreads();
        const uint32_t st = sb + (c & 1) * STAGE;
#pragma unroll
        for (int ks = 0; ks < 2; ks++) {
            uint32_t ah[4][4], al[4][4];
#pragma unroll
            for (int mt = 0; mt < 4; mt++) {
                uint32_t row = wm * 64 + mt * 16 + (lane & 15);
                uint32_t ad = st + row * SA + ks * 32 + ((lane >> 4) << 4);
                LDSM4(ah[mt], ad);
                LDSM4(al[mt], ad + A_TILE);
            }
#pragma unroll
            for (int nt = 0; nt < NT; nt++) {
                uint32_t rn = wn * WN + nt * 8 + (lane & 7);
                uint32_t bd = st + 2 * A_TILE + rn * SA + ks * 32 +
                              (((lane >> 3) & 1) << 4);
                uint32_t bh2[2], bl2[2];
                LDSM2(bh2, bd);
                LDSM2(bl2, bd + B_TILE);
#pragma unroll
                for (int mt = 0; mt < 4; mt++) {
                    MMA16816(acc[mt][nt], ah[mt], bh2);
                    MMA16816(acc[mt][nt], ah[mt], bl2);
                    MMA16816(acc[mt][nt], al[mt], bh2);
                }
            }
        }
        __syncthreads();
    }

#pragma unroll
    for (int mt = 0; mt < 4; mt++) {
#pragma unroll
        for (int nt = 0; nt < NT; nt++) {
            int r0 = bm + wm * 64 + mt * 16 + (lane >> 2);
            int c0 = bn + wn * WN + nt * 8 + (lane & 3) * 2;
#pragma unroll
            for (int half = 0; half < 2; half++) {
                int row = r0 + half * 8;
                float v0 = acc[mt][nt][half * 2];
                float v1 = acc[mt][nt][half * 2 + 1];
                size_t idx = (size_t)row * N + c0;
                if constexpr (EPI == EPI_BIAS) {
                    v0 += bias[c0];
                    v1 += bias[c0 + 1];
                }
                if constexpr (EPI == EPI_RESID) {
                    float2 rr = *(const float2*)(resid + idx);
                    v0 += rr.x; v1 += rr.y;
                }
                *(float2*)(C + idx) = make_float2(v0, v1);
            }
        }
    }
}

// ---------------- fp32 -> bf16 hi/lo decomposition ----------------
__global__ __launch_bounds__(256) void decomp_kernel(
    const float* __restrict__ x, __nv_bfloat16* __restrict__ h,
    __nv_bfloat16* __restrict__ l)
{
    int i = blockIdx.x * 256 + threadIdx.x;
    float4 v = ((const float4*)x)[i];
    __nv_bfloat16 h0 = __float2bfloat16(v.x), h1 = __float2bfloat16(v.y);
    __nv_bfloat16 h2 = __float2bfloat16(v.z), h3 = __float2bfloat16(v.w);
    __nv_bfloat16 l0 = __float2bfloat16(v.x - __bfloat162float(h0));
    __nv_bfloat16 l1 = __float2bfloat16(v.y - __bfloat162float(h1));
    __nv_bfloat16 l2 = __float2bfloat16(v.z - __bfloat162float(h2));
    __nv_bfloat16 l3 = __float2bfloat16(v.w - __bfloat162float(h3));
    ((__nv_bfloat162*)h)[i * 2]     = __nv_bfloat162(h0, h1);
    ((__nv_bfloat162*)h)[i * 2 + 1] = __nv_bfloat162(h2, h3);
    ((__nv_bfloat162*)l)[i * 2]     = __nv_bfloat162(l0, l1);
    ((__nv_bfloat162*)l)[i * 2 + 1] = __nv_bfloat162(l2, l3);
}

// ---------------- SIMT GEMM (small K only: embed, dtproj) ----------------
template<int BM, int BN, int BK, int TM, int TN, int EPI>
__global__ __launch_bounds__(256) void gemm_k(
    const float* __restrict__ A, int lda,
    const float* __restrict__ W,
    const float* __restrict__ bias,
    float* __restrict__ C,
    int M, int N, int K)
{
    __shared__ float As[BK][BM];
    __shared__ float Ws[BK][BN];
    const int tid = threadIdx.x;
    const int bm = blockIdx.y * BM;
    const int bn = blockIdx.x * BN;
    constexpr int TX = BN / TN;
    const int tx = tid % TX;
    const int ty = tid / TX;

    float acc[TM][TN];
#pragma unroll
    for (int i = 0; i < TM; i++)
#pragma unroll
        for (int j = 0; j < TN; j++) acc[i][j] = 0.f;

    for (int k0 = 0; k0 < K; k0 += BK) {
#pragma unroll
        for (int i = tid; i < BM * BK; i += 256) {
            int r = i / BK, c = i % BK;
            As[c][r] = A[(size_t)(bm + r) * lda + k0 + c];
        }
#pragma unroll
        for (int i = tid; i < BN * BK; i += 256) {
            int r = i / BK, c = i % BK;
            Ws[c][r] = W[(size_t)(bn + r) * K + k0 + c];
        }
        __syncthreads();
#pragma unroll
        for (int kk = 0; kk < BK; kk++) {
            float ra[TM], rw[TN];
#pragma unroll
            for (int i = 0; i < TM; i++) ra[i] = As[kk][ty * TM + i];
#pragma unroll
            for (int j = 0; j < TN; j++) rw[j] = Ws[kk][tx * TN + j];
#pragma unroll
            for (int i = 0; i < TM; i++)
#pragma unroll
                for (int j = 0; j < TN; j++)
                    acc[i][j] = fmaf(ra[i], rw[j], acc[i][j]);
        }
        __syncthreads();
    }
#pragma unroll
    for (int i = 0; i < TM; i++) {
        int row = bm + ty * TM + i;
#pragma unroll
        for (int j = 0; j < TN; j++) {
            int col = bn + tx * TN + j;
            float v = acc[i][j];
            if constexpr (EPI == EPI_BIAS || EPI == EPI_SOFTPLUS) v += bias[col];
            if constexpr (EPI == EPI_SOFTPLUS)
                v = (v > 20.f) ? v : log1pf(__expf(v));
            C[(size_t)row * N + col] = v;
        }
    }
}

// ---------------- layernorm -> bf16 hi/lo, one warp per row ----------------
__global__ __launch_bounds__(256) void ln_kernel(
    const float* __restrict__ x, const float* __restrict__ w,
    const float* __restrict__ bb,
    __nv_bfloat16* __restrict__ oh, __nv_bfloat16* __restrict__ ol)
{
    int row  = blockIdx.x * 8 + (threadIdx.x >> 5);
    int lane = threadIdx.x & 31;
    const float* xr = x + (size_t)row * D_MODEL + lane;
    float v[16];
    float s = 0.f, s2 = 0.f;
#pragma unroll
    for (int i = 0; i < 16; i++) {
        v[i] = xr[i * 32];
        s += v[i];
        s2 = fmaf(v[i], v[i], s2);
    }
#pragma unroll
    for (int k = 16; k; k >>= 1) {
        s  += __shfl_xor_sync(0xffffffffu, s,  k);
        s2 += __shfl_xor_sync(0xffffffffu, s2, k);
    }
    float mu  = s * (1.f / 512.f);
    float var = fmaf(s2, 1.f / 512.f, -mu * mu);
    float rs  = rsqrtf(var + 1e-5f);
    size_t ob = (size_t)row * D_MODEL + lane;
#pragma unroll
    for (int i = 0; i < 16; i++) {
        float o = (v[i] - mu) * rs * w[lane + i * 32] + bb[lane + i * 32];
        __nv_bfloat16 hv = __float2bfloat16(o);
        oh[ob + i * 32] = hv;
        ol[ob + i * 32] = __float2bfloat16(o - __bfloat162float(hv));
    }
}

// ---------------- causal depthwise conv (k=4) + SiLU -> fp32 + hi/lo ------
__global__ __launch_bounds__(256) void conv_silu_kernel(
    const float* __restrict__ xz, const float* __restrict__ cw,
    const float* __restrict__ cb, float* __restrict__ xc,
    __nv_bfloat16* __restrict__ xch, __nv_bfloat16* __restrict__ xcl)
{
    int idx = blockIdx.x * 256 + threadIdx.x;
    int d  = idx & (D_INNER - 1);
    int bl = idx >> 10;
    int t  = bl & (L_SEQ - 1);
    const float* xp = xz + (size_t)bl * (2 * D_INNER) + d;
    float4 w = __ldg((const float4*)cw + d);
    float acc = cb[d];
    acc = fmaf(w.w, xp[0], acc);
    if (t >= 1) acc = fmaf(w.z, xp[-(2 * D_INNER)],     acc);
    if (t >= 2) acc = fmaf(w.y, xp[-2 * (2 * D_INNER)], acc);
    if (t >= 3) acc = fmaf(w.x, xp[-3 * (2 * D_INNER)], acc);
    float s = __fdividef(acc, 1.f + __expf(-acc));
    xc[idx] = s;
    __nv_bfloat16 hv = __float2bfloat16(s);
    xch[idx] = hv;
    xcl[idx] = __float2bfloat16(s - __bfloat162float(hv));
}

// ---------------- selective scan -> ys hi/lo ----------------
__global__ __launch_bounds__(256) void scan_kernel(
    const float* __restrict__ dt_g, const float* __restrict__ xc_g,
    const float* __restrict__ dbl_g, const float* __restrict__ xz_g,
    const float* __restrict__ A_log, const float* __restrict__ Dsk,
    __nv_bfloat16* __restrict__ ysh, __nv_bfloat16* __restrict__ ysl)
{
    const int gw   = (blockIdx.x * 256 + threadIdx.x) >> 5;
    const int lane = threadIdx.x & 31;
    const int b    = gw >> 9;
    const int d0   = (gw & 511) << 1;
    const int half = lane >> 4;
    const int n    = lane & 15;
    const int d    = d0 + half;

    const float An = -__expf(__ldg(A_log + d * N_STATE + n));
    const float Dd = __ldg(Dsk + d);
    const size_t base = (size_t)b * L_SEQ;

    const float2* dtp = (const float2*)(dt_g + base * D_INNER + d0);
    const float2* xcp = (const float2*)(xc_g + base * D_INNER + d0);
    const float2* zp  = (const float2*)(xz_g + base * (2 * D_INNER) + D_INNER + d0);
    const float*  bcp = dbl_g + base * 64 + 32 + lane;
    __nv_bfloat16* yph = ysh + base * D_INNER + d;
    __nv_bfloat16* ypl = ysl + base * D_INNER + d;

    float h = 0.f;
    float2 adt[4], axc[4], az[4]; float abc[4];
    float2 bdt[4], bxc[4], bz[4]; float bbc[4];

#define LOADQ(T0, DT, XC, Z, BC)                                          \
    {                                                                     \
        _Pragma("unroll")                                                 \
        for (int j = 0; j < 4; j++) {                                     \
            int tt = (T0) + j;                                            \
            DT[j] = __ldg(dtp + (size_t)tt * (D_INNER / 2));              \
            XC[j] = __ldg(xcp + (size_t)tt * (D_INNER / 2));              \
            Z[j]  = __ldg(zp  + (size_t)tt * D_INNER);                    \
            BC[j] = __ldg(bcp + (size_t)tt * 64);                         \
        }                                                                 \
    }
#define STEP(T, DTv, XCv, Zv, BCv)                                        \
    {                                                                     \
        float dtv = half ? (DTv).y : (DTv).x;                             \
        float xv  = half ? (XCv).y : (XCv).x;                             \
        float bn = __shfl_sync(0xffffffffu, (BCv), n);                    \
        float cn = __shfl_sync(0xffffffffu, (BCv), n + 16);               \
        float dA = __expf(dtv * An);                                      \
        h = fmaf(dA, h, dtv * xv * bn);                                   \
        float p = h * cn;                                                 \
        p += __shfl_xor_sync(0xffffffffu, p, 1);                          \
        p += __shfl_xor_sync(0xffffffffu, p, 2);                          \
        p += __shfl_xor_sync(0xffffffffu, p, 4);                          \
        p += __shfl_xor_sync(0xffffffffu, p, 8);                          \
        if (n == 0) {                                                     \
            float zv = half ? (Zv).y : (Zv).x;                            \
            float yv = fmaf(xv, Dd, p);                                   \
            float o  = yv * __fdividef(zv, 1.f + __expf(-zv));            \
            __nv_bfloat16 hv = __float2bfloat16(o);                       \
            yph[(size_t)(T) * D_INNER] = hv;                              \
            ypl[(size_t)(T) * D_INNER] =                                  \
                __float2bfloat16(o - __bfloat162float(hv));               \
        }                                                                 \
    }

    LOADQ(0, adt, axc, az, abc);
    for (int t0 = 0; t0 < L_SEQ; t0 += 8) {
        LOADQ(t0 + 4, bdt, bxc, bz, bbc);
#pragma unroll
        for (int j = 0; j < 4; j++) STEP(t0 + j, adt[j], axc[j], az[j], abc[j]);
        if (t0 + 8 < L_SEQ) LOADQ(t0 + 8, adt, axc, az, abc);
#pragma unroll
        for (int j = 0; j < 4; j++) STEP(t0 + 4 + j, bdt[j], bxc[j], bz[j], bbc[j]);
    }
#undef LOADQ
#undef STEP
}

// ---------------- host orchestration ----------------
extern "C" void kernel_launch(void* const* d_in, const int* in_sizes, int n_in,
                              void* d_out, int out_size)
{
    const float* y        = (const float*)d_in[0];
    const float* emb_w    = (const float*)d_in[1];
    const float* emb_b    = (const float*)d_in[2];
    const float* ln_w     = (const float*)d_in[3];
    const float* ln_b     = (const float*)d_in[4];
    const float* mix_w    = (const float*)d_in[5];
    const float* conv_w   = (const float*)d_in[6];
    const float* conv_b   = (const float*)d_in[7];
    const float* xproj_w  = (const float*)d_in[8];
    const float* dtproj_w = (const float*)d_in[9];
    const float* dtproj_b = (const float*)d_in[10];
    const float* A_log    = (const float*)d_in[11];
    const float* Dskip    = (const float*)d_in[12];
    const float* out_w    = (const float*)d_in[13];
    const float* normf_w  = (const float*)d_in[14];
    const float* normf_b  = (const float*)d_in[15];
    const float* ro1_w    = (const float*)d_in[16];
    const float* ro1_b    = (const float*)d_in[17];
    const float* ro2_w    = (const float*)d_in[18];
    const float* ro2_b    = (const float*)d_in[19];

    float *h, *xz, *xc, *dbl, *dt;
    cudaGetSymbolAddress((void**)&h,   g_h);
    cudaGetSymbolAddress((void**)&xz,  g_xz);
    cudaGetSymbolAddress((void**)&xc,  g_xc);
    cudaGetSymbolAddress((void**)&dbl, g_dbl);
    cudaGetSymbolAddress((void**)&dt,  g_dt);
    __nv_bfloat16 *xin_h, *xin_l, *xc_h, *xc_l, *ys_h, *ys_l, *h2_h, *h2_l;
    __nv_bfloat16 *mw_h, *mw_l, *xpw_h, *xpw_l, *ow_h, *ow_l, *r1_h, *r1_l, *r2_h, *r2_l;
    cudaGetSymbolAddress((void**)&xin_h, g_xin_h);
    cudaGetSymbolAddress((void**)&xin_l, g_xin_l);
    cudaGetSymbolAddress((void**)&xc_h,  g_xc_h);
    cudaGetSymbolAddress((void**)&xc_l,  g_xc_l);
    cudaGetSymbolAddress((void**)&ys_h,  g_ys_h);
    cudaGetSymbolAddress((void**)&ys_l,  g_ys_l);
    cudaGetSymbolAddress((void**)&h2_h,  g_h2_h);
    cudaGetSymbolAddress((void**)&h2_l,  g_h2_l);
    cudaGetSymbolAddress((void**)&mw_h,  g_mixw_h);
    cudaGetSymbolAddress((void**)&mw_l,  g_mixw_l);
    cudaGetSymbolAddress((void**)&xpw_h, g_xpw_h);
    cudaGetSymbolAddress((void**)&xpw_l, g_xpw_l);
    cudaGetSymbolAddress((void**)&ow_h,  g_ow_h);
    cudaGetSymbolAddress((void**)&ow_l,  g_ow_l);
    cudaGetSymbolAddress((void**)&r1_h,  g_r1w_h);
    cudaGetSymbolAddress((void**)&r1_l,  g_r1w_l);
    cudaGetSymbolAddress((void**)&r2_h,  g_r2w_h);
    cudaGetSymbolAddress((void**)&r2_l,  g_r2w_l);

    const int M = BL_ROWS;
    constexpr int SBIG = 3 * 61440;                           // 184320
    constexpr int S128 = 2 * (2 * 128 * 80 + 2 * 128 * 80);   // 81920
    constexpr int S64  = 2 * (2 * 128 * 80 + 2 * 64 * 80);    // 61440
    cudaFuncSetAttribute(mma_gemm2<EPI_NONE>,  cudaFuncAttributeMaxDynamicSharedMemorySize, SBIG);
    cudaFuncSetAttribute(mma_gemm2<EPI_RESID>, cudaFuncAttributeMaxDynamicSharedMemorySize, SBIG);
    cudaFuncSetAttribute(mma_gemm2<EPI_GELU>,  cudaFuncAttributeMaxDynamicSharedMemorySize, SBIG);
    cudaFuncSetAttribute(mma_gemm<128, EPI_BIAS>, cudaFuncAttributeMaxDynamicSharedMemorySize, S128);
    cudaFuncSetAttribute(mma_gemm<64,  EPI_NONE>, cudaFuncAttributeMaxDynamicSharedMemorySize, S64);

    // decompose weights (every call; deterministic)
    decomp_kernel<<<(N_LAYER * 2 * D_INNER * D_MODEL) / 1024, 256>>>(mix_w, mw_h, mw_l);
    decomp_kernel<<<(N_LAYER * 64 * D_INNER) / 1024, 256>>>(xproj_w, xpw_h, xpw_l);
    decomp_kernel<<<(N_LAYER * D_MODEL * D_INNER) / 1024, 256>>>(out_w, ow_h, ow_l);
    decomp_kernel<<<(D_MODEL * D_MODEL) / 1024, 256>>>(ro1_w, r1_h, r1_l);
    decomp_kernel<<<(128 * D_MODEL) / 1024, 256>>>(ro2_w, r2_h, r2_l);

    // embedding (SIMT, K=32): h = y @ emb_w^T + emb_b
    gemm_k<64, 64, 16, 4, 4, EPI_BIAS><<<dim3(D_MODEL / 64, M / 64), 256>>>(
        y, P_DIM, emb_w, emb_b, h, M, D_MODEL, P_DIM);

    for (int i = 0; i < N_LAYER; i++) {
        const float* lw  = ln_w + i * D_MODEL;
        const float* lb  = ln_b + i * D_MODEL;
        const float* cw  = conv_w + (size_t)i * D_INNER * 4;
        const float* cb  = conv_b + (size_t)i * D_INNER;
        const float* dpw = dtproj_w + (size_t)i * D_INNER * DT_RANK;
        const float* dpb = dtproj_b + (size_t)i * D_INNER;
        const float* Al  = A_log + (size_t)i * D_INNER * N_STATE;
        const float* Dk  = Dskip + (size_t)i * D_INNER;

        // LN -> bf16 hi/lo
        ln_kernel<<<M / 8, 256>>>(h, lw, lb, xin_h, xin_l);
        // xz = xin @ mix_w^T   (M x 2048, K=512) big HMMA
        mma_gemm2<EPI_NONE><<<dim3(16, M / 256), 512, SBIG>>>(
            xin_h, xin_l,
            mw_h + (size_t)i * 2 * D_INNER * D_MODEL,
            mw_l + (size_t)i * 2 * D_INNER * D_MODEL,
            nullptr, nullptr, xz, nullptr, nullptr, 2 * D_INNER, D_MODEL);
        // conv + silu -> xc fp32 + hi/lo
        conv_silu_kernel<<<(M * D_INNER) / 256, 256>>>(xz, cw, cb, xc, xc_h, xc_l);
        // dbl = xc @ xproj_w^T  (M x 64, K=1024) small HMMA
        mma_gemm<64, EPI_NONE><<<dim3(1, M / 128), 256, S64>>>(
            xc_h, xc_l,
            xpw_h + (size_t)i * 64 * D_INNER, xpw_l + (size_t)i * 64 * D_INNER,
            nullptr, nullptr, dbl, nullptr, nullptr, 64, D_INNER);
        // dt = softplus(dbl[:, :32] @ dtproj_w^T + b)  (SIMT, K=32)
        gemm_k<64, 64, 16, 4, 4, EPI_SOFTPLUS><<<dim3(D_INNER / 64, M / 64), 256>>>(
            dbl, 64, dpw, dpb, dt, M, D_INNER, DT_RANK);
        // selective scan + gate -> ys hi/lo
        scan_kernel<<<512, 256>>>(dt, xc, dbl, xz, Al, Dk, ys_h, ys_l);
        // h = h + ys @ out_w^T  (M x 512, K=1024) big HMMA
        mma_gemm2<EPI_RESID><<<dim3(4, M / 256), 512, SBIG>>>(
            ys_h, ys_l,
            ow_h + (size_t)i * D_MODEL * D_INNER, ow_l + (size_t)i * D_MODEL * D_INNER,
            nullptr, h, h, nullptr, nullptr, D_MODEL, D_INNER);
    }

    // final LN -> hi/lo
    ln_kernel<<<M / 8, 256>>>(h, normf_w, normf_b, xin_h, xin_l);
    // h2 = gelu(xin @ ro1_w^T + b)  (M x 512, K=512) big HMMA -> hi/lo
    mma_gemm2<EPI_GELU><<<dim3(4, M / 256), 512, SBIG>>>(
        xin_h, xin_l, r1_h, r1_l, ro1_b, nullptr,
        nullptr, h2_h, h2_l, D_MODEL, D_MODEL);
    // out = h2 @ ro2_w^T + b  (M x 128, K=512) small HMMA
    mma_gemm<128, EPI_BIAS><<<dim3(1, M / 128), 256, S128>>>(
        h2_h, h2_l, r2_h, r2_l, ro2_b, nullptr,
        (float*)d_out, nullptr, nullptr, 128, D_MODEL);
}

// round 6
// speedup vs baseline: 2.2167x; 1.2183x over previous
#include <cuda_runtime.h>
#include <cuda_fp16.h>
#include <cstdint>

// ---------------- problem constants ----------------
#define B_SZ     8
#define L_SEQ    2048
#define P_DIM    32
#define D_MODEL  512
#define D_INNER  1024
#define N_STATE  16
#define DT_RANK  32
#define N_LAYER  4
#define BL_ROWS  (B_SZ * L_SEQ)          // 16384

// ---------------- scratch (static device globals) ----------------
__device__ __align__(16) float g_h  [(size_t)BL_ROWS * D_MODEL];
__device__ __align__(16) float g_xz [(size_t)BL_ROWS * 2 * D_INNER];
__device__ __align__(16) float g_xc [(size_t)BL_ROWS * D_INNER];
__device__ __align__(16) float g_dbl[(size_t)BL_ROWS * 64];
__device__ __align__(16) float g_dt [(size_t)BL_ROWS * D_INNER];

__device__ __align__(16) __half g_xin[(size_t)BL_ROWS * D_MODEL];
__device__ __align__(16) __half g_xch[(size_t)BL_ROWS * D_INNER];
__device__ __align__(16) __half g_ysh[(size_t)BL_ROWS * D_INNER];
__device__ __align__(16) __half g_h2 [(size_t)BL_ROWS * D_MODEL];

__device__ __align__(16) __half g_mixw[(size_t)N_LAYER * 2 * D_INNER * D_MODEL];
__device__ __align__(16) __half g_xpw [(size_t)N_LAYER * 64 * D_INNER];
__device__ __align__(16) __half g_ow  [(size_t)N_LAYER * D_MODEL * D_INNER];
__device__ __align__(16) __half g_r1w [(size_t)D_MODEL * D_MODEL];
__device__ __align__(16) __half g_r2w [(size_t)128 * D_MODEL];

// ---------------- PTX helpers ----------------
__device__ __forceinline__ uint32_t smem_u32(const void* p) {
    uint32_t a;
    asm("{ .reg .u64 t; cvta.to.shared.u64 t, %1; cvt.u32.u64 %0, t; }"
        : "=r"(a) : "l"(p));
    return a;
}
#define CP_ASYNC16(sa, ga)                                                   \
    asm volatile("cp.async.cg.shared.global [%0], [%1], 16;"                 \
                 :: "r"(sa), "l"(ga))
#define CP_COMMIT() asm volatile("cp.async.commit_group;" ::: "memory")
#define CP_WAIT1()  asm volatile("cp.async.wait_group 1;"  ::: "memory")
#define CP_WAIT2()  asm volatile("cp.async.wait_group 2;"  ::: "memory")
#define LDSM4(R, A)                                                          \
    asm volatile("ldmatrix.sync.aligned.m8n8.x4.shared.b16 {%0,%1,%2,%3},[%4];" \
                 : "=r"((R)[0]), "=r"((R)[1]), "=r"((R)[2]), "=r"((R)[3])    \
                 : "r"(A))
#define LDSM2(R, A)                                                          \
    asm volatile("ldmatrix.sync.aligned.m8n8.x2.shared.b16 {%0,%1},[%2];"    \
                 : "=r"((R)[0]), "=r"((R)[1]) : "r"(A))
#define MMA16816(C, A, B)                                                    \
    asm volatile("mma.sync.aligned.m16n8k16.row.col.f32.f16.f16.f32 "        \
                 "{%0,%1,%2,%3},{%4,%5,%6,%7},{%8,%9},{%0,%1,%2,%3};"        \
                 : "+f"((C)[0]), "+f"((C)[1]), "+f"((C)[2]), "+f"((C)[3])    \
                 : "r"((A)[0]), "r"((A)[1]), "r"((A)[2]), "r"((A)[3]),       \
                   "r"((B)[0]), "r"((B)[1]))

// ---------------- epilogue ids ----------------
#define EPI_NONE     0
#define EPI_BIAS     1
#define EPI_SOFTPLUS 2
#define EPI_GELU     3
#define EPI_RESID    4

// =======================================================================
// Big HMMA GEMM (fp16 single-term): BM=256, BN=128, BK=32, 512 threads
// (16 warps, 4x4), warp tile 64x32, 3-stage cp.async pipeline, fp32 acc.
// =======================================================================
template<int EPI>
__global__ __launch_bounds__(512) void mma_gemm2(
    const __half* __restrict__ A, const __half* __restrict__ B,
    const float* __restrict__ bias, const float* __restrict__ resid,
    float* __restrict__ C, __half* __restrict__ Ch, int N, int K)
{
    extern __shared__ char smem[];
    constexpr int SA     = 80;
    constexpr int A_TILE = 256 * SA;           // 20480
    constexpr int B_TILE = 128 * SA;           // 10240
    constexpr int STAGE  = A_TILE + B_TILE;    // 30720

    const int tid  = threadIdx.x;
    const int wid  = tid >> 5;
    const int lane = tid & 31;
    const int wm   = wid >> 2;                 // 0..3
    const int wn   = wid & 3;                  // 0..3
    const int bm   = blockIdx.y * 256;
    const int bn   = blockIdx.x * 128;
    const uint32_t sb = smem_u32(smem);

    float acc[4][4][4];
#pragma unroll
    for (int mt = 0; mt < 4; mt++)
#pragma unroll
        for (int nt = 0; nt < 4; nt++)
#pragma unroll
            for (int q = 0; q < 4; q++) acc[mt][nt][q] = 0.f;

    auto load_stage = [&](int c, int s) {
        const int k0 = c * 32;
        const uint32_t st = sb + s * STAGE;
#pragma unroll
        for (int i = 0; i < 2; i++) {
            int id = tid + i * 512;
            int r = id >> 2, cc = id & 3;
            uint32_t so = st + r * SA + cc * 16;
            size_t g = (size_t)(bm + r) * K + k0 + cc * 8;
            CP_ASYNC16(so, A + g);
        }
        {
            int r = tid >> 2, cc = tid & 3;
            uint32_t so = st + A_TILE + r * SA + cc * 16;
            size_t g = (size_t)(bn + r) * K + k0 + cc * 8;
            CP_ASYNC16(so, B + g);
        }
        CP_COMMIT();
    };

    const int chunks = K >> 5;
    load_stage(0, 0);
    load_stage(1, 1);
    int s = 0;
    for (int c = 0; c < chunks; c++) {
        int s2 = s + 2; if (s2 >= 3) s2 -= 3;
        if (c + 2 < chunks) load_stage(c + 2, s2);
        else                CP_COMMIT();
        CP_WAIT2();
        __syncthreads();
        const uint32_t st = sb + s * STAGE;
#pragma unroll
        for (int ks = 0; ks < 2; ks++) {
            uint32_t a4[4][4];
#pragma unroll
            for (int mt = 0; mt < 4; mt++) {
                uint32_t row = wm * 64 + mt * 16 + (lane & 15);
                uint32_t ad = st + row * SA + ks * 32 + ((lane >> 4) << 4);
                LDSM4(a4[mt], ad);
            }
#pragma unroll
            for (int nt = 0; nt < 4; nt++) {
                uint32_t rn = wn * 32 + nt * 8 + (lane & 7);
                uint32_t bd = st + A_TILE + rn * SA + ks * 32 +
                              (((lane >> 3) & 1) << 4);
                uint32_t b2[2];
                LDSM2(b2, bd);
#pragma unroll
                for (int mt = 0; mt < 4; mt++)
                    MMA16816(acc[mt][nt], a4[mt], b2);
            }
        }
        __syncthreads();
        if (++s >= 3) s -= 3;
    }

    // ---------------- epilogue ----------------
#pragma unroll
    for (int mt = 0; mt < 4; mt++) {
#pragma unroll
        for (int nt = 0; nt < 4; nt++) {
            int r0 = bm + wm * 64 + mt * 16 + (lane >> 2);
            int c0 = bn + wn * 32 + nt * 8 + (lane & 3) * 2;
#pragma unroll
            for (int half_ = 0; half_ < 2; half_++) {
                int row = r0 + half_ * 8;
                float v0 = acc[mt][nt][half_ * 2];
                float v1 = acc[mt][nt][half_ * 2 + 1];
                size_t idx = (size_t)row * N + c0;
                if constexpr (EPI == EPI_BIAS || EPI == EPI_GELU) {
                    v0 += bias[c0];
                    v1 += bias[c0 + 1];
                }
                if constexpr (EPI == EPI_GELU) {
                    float u0 = 0.7978845608028654f * (v0 + 0.044715f * v0 * v0 * v0);
                    float u1 = 0.7978845608028654f * (v1 + 0.044715f * v1 * v1 * v1);
                    v0 = 0.5f * v0 * (1.f + tanhf(u0));
                    v1 = 0.5f * v1 * (1.f + tanhf(u1));
                    *(__half2*)(Ch + idx) =
                        __halves2half2(__float2half_rn(v0), __float2half_rn(v1));
                } else {
                    if constexpr (EPI == EPI_RESID) {
                        float2 rr = *(const float2*)(resid + idx);
                        v0 += rr.x; v1 += rr.y;
                    }
                    *(float2*)(C + idx) = make_float2(v0, v1);
                }
            }
        }
    }
}

// =======================================================================
// Small HMMA GEMM (fp16 single-term): BM=128, BK=32, 256 threads, 2-stage.
// Used for xproj (N=64) and ro2 (N=128).
// =======================================================================
template<int BN, int EPI>
__global__ __launch_bounds__(256) void mma_gemm(
    const __half* __restrict__ A, const __half* __restrict__ B,
    const float* __restrict__ bias, float* __restrict__ C, int N, int K)
{
    extern __shared__ char smem[];
    constexpr int SA     = 80;
    constexpr int A_TILE = 128 * SA;
    constexpr int B_TILE = BN * SA;
    constexpr int STAGE  = A_TILE + B_TILE;
    constexpr int WN     = BN / 4;
    constexpr int NT     = WN / 8;

    const int tid  = threadIdx.x;
    const int wid  = tid >> 5;
    const int lane = tid & 31;
    const int wm   = wid >> 2;
    const int wn   = wid & 3;
    const int bm   = blockIdx.y * 128;
    const int bn   = blockIdx.x * BN;
    const uint32_t sb = smem_u32(smem);

    float acc[4][NT][4];
#pragma unroll
    for (int mt = 0; mt < 4; mt++)
#pragma unroll
        for (int nt = 0; nt < NT; nt++)
#pragma unroll
            for (int q = 0; q < 4; q++) acc[mt][nt][q] = 0.f;

    auto load_stage = [&](int c, int s) {
        const int k0 = c * 32;
        const uint32_t st = sb + s * STAGE;
#pragma unroll
        for (int i = 0; i < 2; i++) {
            int id = tid + i * 256;
            int r = id >> 2, cc = id & 3;
            uint32_t so = st + r * SA + cc * 16;
            size_t g = (size_t)(bm + r) * K + k0 + cc * 8;
            CP_ASYNC16(so, A + g);
        }
#pragma unroll
        for (int i = 0; i < BN / 64; i++) {
            int id = tid + i * 256;
            int r = id >> 2, cc = id & 3;
            uint32_t so = st + A_TILE + r * SA + cc * 16;
            size_t g = (size_t)(bn + r) * K + k0 + cc * 8;
            CP_ASYNC16(so, B + g);
        }
        CP_COMMIT();
    };

    const int chunks = K >> 5;
    load_stage(0, 0);
    for (int c = 0; c < chunks; c++) {
        if (c + 1 < chunks) load_stage(c + 1, (c + 1) & 1);
        else                CP_COMMIT();
        CP_WAIT1();
        __syncthreads();
        const uint32_t st = sb + (c & 1) * STAGE;
#pragma unroll
        for (int ks = 0; ks < 2; ks++) {
            uint32_t a4[4][4];
#pragma unroll
            for (int mt = 0; mt < 4; mt++) {
                uint32_t row = wm * 64 + mt * 16 + (lane & 15);
                uint32_t ad = st + row * SA + ks * 32 + ((lane >> 4) << 4);
                LDSM4(a4[mt], ad);
            }
#pragma unroll
            for (int nt = 0; nt < NT; nt++) {
                uint32_t rn = wn * WN + nt * 8 + (lane & 7);
                uint32_t bd = st + A_TILE + rn * SA + ks * 32 +
                              (((lane >> 3) & 1) << 4);
                uint32_t b2[2];
                LDSM2(b2, bd);
#pragma unroll
                for (int mt = 0; mt < 4; mt++)
                    MMA16816(acc[mt][nt], a4[mt], b2);
            }
        }
        __syncthreads();
    }

#pragma unroll
    for (int mt = 0; mt < 4; mt++) {
#pragma unroll
        for (int nt = 0; nt < NT; nt++) {
            int r0 = bm + wm * 64 + mt * 16 + (lane >> 2);
            int c0 = bn + wn * WN + nt * 8 + (lane & 3) * 2;
#pragma unroll
            for (int half_ = 0; half_ < 2; half_++) {
                int row = r0 + half_ * 8;
                float v0 = acc[mt][nt][half_ * 2];
                float v1 = acc[mt][nt][half_ * 2 + 1];
                size_t idx = (size_t)row * N + c0;
                if constexpr (EPI == EPI_BIAS) {
                    v0 += bias[c0];
                    v1 += bias[c0 + 1];
                }
                *(float2*)(C + idx) = make_float2(v0, v1);
            }
        }
    }
}

// ---------------- fp32 -> fp16 conversion ----------------
__global__ __launch_bounds__(256) void cvt_kernel(
    const float* __restrict__ x, __half* __restrict__ h)
{
    int i = blockIdx.x * 256 + threadIdx.x;
    float4 v = ((const float4*)x)[i];
    __half2 p0 = __halves2half2(__float2half_rn(v.x), __float2half_rn(v.y));
    __half2 p1 = __halves2half2(__float2half_rn(v.z), __float2half_rn(v.w));
    ((__half2*)h)[i * 2]     = p0;
    ((__half2*)h)[i * 2 + 1] = p1;
}

// ---------------- SIMT GEMM (small K only: embed, dtproj) ----------------
template<int BM, int BN, int BK, int TM, int TN, int EPI>
__global__ __launch_bounds__(256) void gemm_k(
    const float* __restrict__ A, int lda,
    const float* __restrict__ W,
    const float* __restrict__ bias,
    float* __restrict__ C,
    int M, int N, int K)
{
    __shared__ float As[BK][BM];
    __shared__ float Ws[BK][BN];
    const int tid = threadIdx.x;
    const int bm = blockIdx.y * BM;
    const int bn = blockIdx.x * BN;
    constexpr int TX = BN / TN;
    const int tx = tid % TX;
    const int ty = tid / TX;

    float acc[TM][TN];
#pragma unroll
    for (int i = 0; i < TM; i++)
#pragma unroll
        for (int j = 0; j < TN; j++) acc[i][j] = 0.f;

    for (int k0 = 0; k0 < K; k0 += BK) {
#pragma unroll
        for (int i = tid; i < BM * BK; i += 256) {
            int r = i / BK, c = i % BK;
            As[c][r] = A[(size_t)(bm + r) * lda + k0 + c];
        }
#pragma unroll
        for (int i = tid; i < BN * BK; i += 256) {
            int r = i / BK, c = i % BK;
            Ws[c][r] = W[(size_t)(bn + r) * K + k0 + c];
        }
        __syncthreads();
#pragma unroll
        for (int kk = 0; kk < BK; kk++) {
            float ra[TM], rw[TN];
#pragma unroll
            for (int i = 0; i < TM; i++) ra[i] = As[kk][ty * TM + i];
#pragma unroll
            for (int j = 0; j < TN; j++) rw[j] = Ws[kk][tx * TN + j];
#pragma unroll
            for (int i = 0; i < TM; i++)
#pragma unroll
                for (int j = 0; j < TN; j++)
                    acc[i][j] = fmaf(ra[i], rw[j], acc[i][j]);
        }
        __syncthreads();
    }
#pragma unroll
    for (int i = 0; i < TM; i++) {
        int row = bm + ty * TM + i;
#pragma unroll
        for (int j = 0; j < TN; j++) {
            int col = bn + tx * TN + j;
            float v = acc[i][j];
            if constexpr (EPI == EPI_BIAS || EPI == EPI_SOFTPLUS) v += bias[col];
            if constexpr (EPI == EPI_SOFTPLUS)
                v = (v > 20.f) ? v : log1pf(__expf(v));
            C[(size_t)row * N + col] = v;
        }
    }
}

// ---------------- layernorm -> fp16, one warp per row ----------------
__global__ __launch_bounds__(256) void ln_kernel(
    const float* __restrict__ x, const float* __restrict__ w,
    const float* __restrict__ bb, __half* __restrict__ oh)
{
    int row  = blockIdx.x * 8 + (threadIdx.x >> 5);
    int lane = threadIdx.x & 31;
    const float* xr = x + (size_t)row * D_MODEL + lane;
    float v[16];
    float s = 0.f, s2 = 0.f;
#pragma unroll
    for (int i = 0; i < 16; i++) {
        v[i] = xr[i * 32];
        s += v[i];
        s2 = fmaf(v[i], v[i], s2);
    }
#pragma unroll
    for (int k = 16; k; k >>= 1) {
        s  += __shfl_xor_sync(0xffffffffu, s,  k);
        s2 += __shfl_xor_sync(0xffffffffu, s2, k);
    }
    float mu  = s * (1.f / 512.f);
    float var = fmaf(s2, 1.f / 512.f, -mu * mu);
    float rs  = rsqrtf(var + 1e-5f);
    size_t ob = (size_t)row * D_MODEL + lane;
#pragma unroll
    for (int i = 0; i < 16; i++) {
        float o = (v[i] - mu) * rs * w[lane + i * 32] + bb[lane + i * 32];
        oh[ob + i * 32] = __float2half_rn(o);
    }
}

// ---------------- causal depthwise conv (k=4) + SiLU -> fp32 + fp16 ------
__global__ __launch_bounds__(256) void conv_silu_kernel(
    const float* __restrict__ xz, const float* __restrict__ cw,
    const float* __restrict__ cb, float* __restrict__ xc,
    __half* __restrict__ xch)
{
    int idx = blockIdx.x * 256 + threadIdx.x;
    int d  = idx & (D_INNER - 1);
    int bl = idx >> 10;
    int t  = bl & (L_SEQ - 1);
    const float* xp = xz + (size_t)bl * (2 * D_INNER) + d;
    float4 w = __ldg((const float4*)cw + d);
    float acc = cb[d];
    acc = fmaf(w.w, xp[0], acc);
    if (t >= 1) acc = fmaf(w.z, xp[-(2 * D_INNER)],     acc);
    if (t >= 2) acc = fmaf(w.y, xp[-2 * (2 * D_INNER)], acc);
    if (t >= 3) acc = fmaf(w.x, xp[-3 * (2 * D_INNER)], acc);
    float s = __fdividef(acc, 1.f + __expf(-acc));
    xc[idx] = s;
    xch[idx] = __float2half_rn(s);
}

// ---------------- selective scan -> ys fp16 ----------------
__global__ __launch_bounds__(256) void scan_kernel(
    const float* __restrict__ dt_g, const float* __restrict__ xc_g,
    const float* __restrict__ dbl_g, const float* __restrict__ xz_g,
    const float* __restrict__ A_log, const float* __restrict__ Dsk,
    __half* __restrict__ ysh)
{
    const int gw   = (blockIdx.x * 256 + threadIdx.x) >> 5;
    const int lane = threadIdx.x & 31;
    const int b    = gw >> 9;
    const int d0   = (gw & 511) << 1;
    const int half = lane >> 4;
    const int n    = lane & 15;
    const int d    = d0 + half;

    const float An = -__expf(__ldg(A_log + d * N_STATE + n));
    const float Dd = __ldg(Dsk + d);
    const size_t base = (size_t)b * L_SEQ;

    const float2* dtp = (const float2*)(dt_g + base * D_INNER + d0);
    const float2* xcp = (const float2*)(xc_g + base * D_INNER + d0);
    const float2* zp  = (const float2*)(xz_g + base * (2 * D_INNER) + D_INNER + d0);
    const float*  bcp = dbl_g + base * 64 + 32 + lane;
    __half* yph = ysh + base * D_INNER + d;

    float h = 0.f;
    float2 adt[4], axc[4], az[4]; float abc[4];
    float2 bdt[4], bxc[4], bz[4]; float bbc[4];

#define LOADQ(T0, DT, XC, Z, BC)                                          \
    {                                                                     \
        _Pragma("unroll")                                                 \
        for (int j = 0; j < 4; j++) {                                     \
            int tt = (T0) + j;                                            \
            DT[j] = __ldg(dtp + (size_t)tt * (D_INNER / 2));              \
            XC[j] = __ldg(xcp + (size_t)tt * (D_INNER / 2));              \
            Z[j]  = __ldg(zp  + (size_t)tt * D_INNER);                    \
            BC[j] = __ldg(bcp + (size_t)tt * 64);                         \
        }                                                                 \
    }
#define STEP(T, DTv, XCv, Zv, BCv)                                        \
    {                                                                     \
        float dtv = half ? (DTv).y : (DTv).x;                             \
        float xv  = half ? (XCv).y : (XCv).x;                             \
        float bn = __shfl_sync(0xffffffffu, (BCv), n);                    \
        float cn = __shfl_sync(0xffffffffu, (BCv), n + 16);               \
        float dA = __expf(dtv * An);                                      \
        h = fmaf(dA, h, dtv * xv * bn);                                   \
        float p = h * cn;                                                 \
        p += __shfl_xor_sync(0xffffffffu, p, 1);                          \
        p += __shfl_xor_sync(0xffffffffu, p, 2);                          \
        p += __shfl_xor_sync(0xffffffffu, p, 4);                          \
        p += __shfl_xor_sync(0xffffffffu, p, 8);                          \
        if (n == 0) {                                                     \
            float zv = half ? (Zv).y : (Zv).x;                            \
            float yv = fmaf(xv, Dd, p);                                   \
            float o  = yv * __fdividef(zv, 1.f + __expf(-zv));            \
            yph[(size_t)(T) * D_INNER] = __float2half_rn(o);              \
        }                                                                 \
    }

    LOADQ(0, adt, axc, az, abc);
    for (int t0 = 0; t0 < L_SEQ; t0 += 8) {
        LOADQ(t0 + 4, bdt, bxc, bz, bbc);
#pragma unroll
        for (int j = 0; j < 4; j++) STEP(t0 + j, adt[j], axc[j], az[j], abc[j]);
        if (t0 + 8 < L_SEQ) LOADQ(t0 + 8, adt, axc, az, abc);
#pragma unroll
        for (int j = 0; j < 4; j++) STEP(t0 + 4 + j, bdt[j], bxc[j], bz[j], bbc[j]);
    }
#undef LOADQ
#undef STEP
}

// ---------------- host orchestration ----------------
extern "C" void kernel_launch(void* const* d_in, const int* in_sizes, int n_in,
                              void* d_out, int out_size)
{
    const float* y        = (const float*)d_in[0];
    const float* emb_w    = (const float*)d_in[1];
    const float* emb_b    = (const float*)d_in[2];
    const float* ln_w     = (const float*)d_in[3];
    const float* ln_b     = (const float*)d_in[4];
    const float* mix_w    = (const float*)d_in[5];
    const float* conv_w   = (const float*)d_in[6];
    const float* conv_b   = (const float*)d_in[7];
    const float* xproj_w  = (const float*)d_in[8];
    const float* dtproj_w = (const float*)d_in[9];
    const float* dtproj_b = (const float*)d_in[10];
    const float* A_log    = (const float*)d_in[11];
    const float* Dskip    = (const float*)d_in[12];
    const float* out_w    = (const float*)d_in[13];
    const float* normf_w  = (const float*)d_in[14];
    const float* normf_b  = (const float*)d_in[15];
    const float* ro1_w    = (const float*)d_in[16];
    const float* ro1_b    = (const float*)d_in[17];
    const float* ro2_w    = (const float*)d_in[18];
    const float* ro2_b    = (const float*)d_in[19];

    float *h, *xz, *xc, *dbl, *dt;
    cudaGetSymbolAddress((void**)&h,   g_h);
    cudaGetSymbolAddress((void**)&xz,  g_xz);
    cudaGetSymbolAddress((void**)&xc,  g_xc);
    cudaGetSymbolAddress((void**)&dbl, g_dbl);
    cudaGetSymbolAddress((void**)&dt,  g_dt);
    __half *xin, *xch, *ysh, *h2, *mw, *xpw, *ow, *r1w, *r2w;
    cudaGetSymbolAddress((void**)&xin, g_xin);
    cudaGetSymbolAddress((void**)&xch, g_xch);
    cudaGetSymbolAddress((void**)&ysh, g_ysh);
    cudaGetSymbolAddress((void**)&h2,  g_h2);
    cudaGetSymbolAddress((void**)&mw,  g_mixw);
    cudaGetSymbolAddress((void**)&xpw, g_xpw);
    cudaGetSymbolAddress((void**)&ow,  g_ow);
    cudaGetSymbolAddress((void**)&r1w, g_r1w);
    cudaGetSymbolAddress((void**)&r2w, g_r2w);

    const int M = BL_ROWS;
    constexpr int SBIG = 3 * (256 * 80 + 128 * 80);   // 92160
    constexpr int S128 = 2 * (128 * 80 + 128 * 80);   // 40960
    constexpr int S64  = 2 * (128 * 80 + 64 * 80);    // 30720
    cudaFuncSetAttribute(mma_gemm2<EPI_NONE>,  cudaFuncAttributeMaxDynamicSharedMemorySize, SBIG);
    cudaFuncSetAttribute(mma_gemm2<EPI_RESID>, cudaFuncAttributeMaxDynamicSharedMemorySize, SBIG);
    cudaFuncSetAttribute(mma_gemm2<EPI_GELU>,  cudaFuncAttributeMaxDynamicSharedMemorySize, SBIG);
    cudaFuncSetAttribute(mma_gemm<128, EPI_BIAS>, cudaFuncAttributeMaxDynamicSharedMemorySize, S128);
    cudaFuncSetAttribute(mma_gemm<64,  EPI_NONE>, cudaFuncAttributeMaxDynamicSharedMemorySize, S64);

    // convert weights to fp16 (every call; deterministic)
    cvt_kernel<<<(N_LAYER * 2 * D_INNER * D_MODEL) / 1024, 256>>>(mix_w, mw);
    cvt_kernel<<<(N_LAYER * 64 * D_INNER) / 1024, 256>>>(xproj_w, xpw);
    cvt_kernel<<<(N_LAYER * D_MODEL * D_INNER) / 1024, 256>>>(out_w, ow);
    cvt_kernel<<<(D_MODEL * D_MODEL) / 1024, 256>>>(ro1_w, r1w);
    cvt_kernel<<<(128 * D_MODEL) / 1024, 256>>>(ro2_w, r2w);

    // embedding (SIMT, K=32): h = y @ emb_w^T + emb_b
    gemm_k<64, 64, 16, 4, 4, EPI_BIAS><<<dim3(D_MODEL / 64, M / 64), 256>>>(
        y, P_DIM, emb_w, emb_b, h, M, D_MODEL, P_DIM);

    for (int i = 0; i < N_LAYER; i++) {
        const float* lw  = ln_w + i * D_MODEL;
        const float* lb  = ln_b + i * D_MODEL;
        const float* cw  = conv_w + (size_t)i * D_INNER * 4;
        const float* cb  = conv_b + (size_t)i * D_INNER;
        const float* dpw = dtproj_w + (size_t)i * D_INNER * DT_RANK;
        const float* dpb = dtproj_b + (size_t)i * D_INNER;
        const float* Al  = A_log + (size_t)i * D_INNER * N_STATE;
        const float* Dk  = Dskip + (size_t)i * D_INNER;

        // LN -> fp16
        ln_kernel<<<M / 8, 256>>>(h, lw, lb, xin);
        // xz = xin @ mix_w^T   (M x 2048, K=512)
        mma_gemm2<EPI_NONE><<<dim3(16, M / 256), 512, SBIG>>>(
            xin, mw + (size_t)i * 2 * D_INNER * D_MODEL,
            nullptr, nullptr, xz, nullptr, 2 * D_INNER, D_MODEL);
        // conv + silu -> xc fp32 + fp16
        conv_silu_kernel<<<(M * D_INNER) / 256, 256>>>(xz, cw, cb, xc, xch);
        // dbl = xc @ xproj_w^T  (M x 64, K=1024)
        mma_gemm<64, EPI_NONE><<<dim3(1, M / 128), 256, S64>>>(
            xch, xpw + (size_t)i * 64 * D_INNER, nullptr, dbl, 64, D_INNER);
        // dt = softplus(dbl[:, :32] @ dtproj_w^T + b)  (SIMT, K=32)
        gemm_k<64, 64, 16, 4, 4, EPI_SOFTPLUS><<<dim3(D_INNER / 64, M / 64), 256>>>(
            dbl, 64, dpw, dpb, dt, M, D_INNER, DT_RANK);
        // selective scan + gate -> ys fp16
        scan_kernel<<<512, 256>>>(dt, xc, dbl, xz, Al, Dk, ysh);
        // h = h + ys @ out_w^T  (M x 512, K=1024)
        mma_gemm2<EPI_RESID><<<dim3(4, M / 256), 512, SBIG>>>(
            ysh, ow + (size_t)i * D_MODEL * D_INNER,
            nullptr, h, h, nullptr, D_MODEL, D_INNER);
    }

    // final LN -> fp16
    ln_kernel<<<M / 8, 256>>>(h, normf_w, normf_b, xin);
    // h2 = gelu(xin @ ro1_w^T + b)  (M x 512, K=512) -> fp16
    mma_gemm2<EPI_GELU><<<dim3(4, M / 256), 512, SBIG>>>(
        xin, r1w, ro1_b, nullptr, nullptr, h2, D_MODEL, D_MODEL);
    // out = h2 @ ro2_w^T + b  (M x 128, K=512)
    mma_gemm<128, EPI_BIAS><<<dim3(1, M / 128), 256, S128>>>(
        h2, r2w, ro2_b, (float*)d_out, 128, D_MODEL);
}

// round 7
// speedup vs baseline: 2.2883x; 1.0323x over previous
#include <cuda_runtime.h>
#include <cuda_fp16.h>
#include <cstdint>

// ---------------- problem constants ----------------
#define B_SZ     8
#define L_SEQ    2048
#define P_DIM    32
#define D_MODEL  512
#define D_INNER  1024
#define N_STATE  16
#define DT_RANK  32
#define N_LAYER  4
#define BL_ROWS  (B_SZ * L_SEQ)          // 16384

// ---------------- scratch (static device globals) ----------------
__device__ __align__(16) float g_h  [(size_t)BL_ROWS * D_MODEL];
__device__ __align__(16) float g_xz [(size_t)BL_ROWS * 2 * D_INNER];
__device__ __align__(16) float g_xc [(size_t)BL_ROWS * D_INNER];
__device__ __align__(16) float g_dbl[(size_t)BL_ROWS * 64];
__device__ __align__(16) float g_dt [(size_t)BL_ROWS * D_INNER];

__device__ __align__(16) __half g_xin [(size_t)BL_ROWS * D_MODEL];
__device__ __align__(16) __half g_xch [(size_t)BL_ROWS * D_INNER];
__device__ __align__(16) __half g_ysh [(size_t)BL_ROWS * D_INNER];
__device__ __align__(16) __half g_h2  [(size_t)BL_ROWS * D_MODEL];
__device__ __align__(16) __half g_dblh[(size_t)BL_ROWS * 64];

__device__ __align__(16) __half g_mixw[(size_t)N_LAYER * 2 * D_INNER * D_MODEL];
__device__ __align__(16) __half g_xpw [(size_t)N_LAYER * 64 * D_INNER];
__device__ __align__(16) __half g_ow  [(size_t)N_LAYER * D_MODEL * D_INNER];
__device__ __align__(16) __half g_dtw [(size_t)N_LAYER * D_INNER * DT_RANK];
__device__ __align__(16) __half g_r1w [(size_t)D_MODEL * D_MODEL];
__device__ __align__(16) __half g_r2w [(size_t)128 * D_MODEL];

// ---------------- PTX helpers ----------------
__device__ __forceinline__ uint32_t smem_u32(const void* p) {
    uint32_t a;
    asm("{ .reg .u64 t; cvta.to.shared.u64 t, %1; cvt.u32.u64 %0, t; }"
        : "=r"(a) : "l"(p));
    return a;
}
#define CP_ASYNC16(sa, ga)                                                   \
    asm volatile("cp.async.cg.shared.global [%0], [%1], 16;"                 \
                 :: "r"(sa), "l"(ga))
#define CP_COMMIT() asm volatile("cp.async.commit_group;" ::: "memory")
#define CP_WAIT1()  asm volatile("cp.async.wait_group 1;"  ::: "memory")
#define LDSM4(R, A)                                                          \
    asm volatile("ldmatrix.sync.aligned.m8n8.x4.shared.b16 {%0,%1,%2,%3},[%4];" \
                 : "=r"((R)[0]), "=r"((R)[1]), "=r"((R)[2]), "=r"((R)[3])    \
                 : "r"(A))
#define LDSM2(R, A)                                                          \
    asm volatile("ldmatrix.sync.aligned.m8n8.x2.shared.b16 {%0,%1},[%2];"    \
                 : "=r"((R)[0]), "=r"((R)[1]) : "r"(A))
#define MMA16816(C, A, B)                                                    \
    asm volatile("mma.sync.aligned.m16n8k16.row.col.f32.f16.f16.f32 "        \
                 "{%0,%1,%2,%3},{%4,%5,%6,%7},{%8,%9},{%0,%1,%2,%3};"        \
                 : "+f"((C)[0]), "+f"((C)[1]), "+f"((C)[2]), "+f"((C)[3])    \
                 : "r"((A)[0]), "r"((A)[1]), "r"((A)[2]), "r"((A)[3]),       \
                   "r"((B)[0]), "r"((B)[1]))

// ---------------- epilogue ids ----------------
#define EPI_NONE     0
#define EPI_BIAS     1
#define EPI_SOFTPLUS 2
#define EPI_GELU     3
#define EPI_RESID    4

// =======================================================================
// Big HMMA GEMM (fp16): BM=256, BN=128, BK=64, 512 threads (16 warps 4x4),
// warp tile 64x32, 2-stage cp.async pipeline, fp32 accum.
// =======================================================================
template<int EPI>
__global__ __launch_bounds__(512) void mma_gemm2(
    const __half* __restrict__ A, const __half* __restrict__ B,
    const float* __restrict__ bias, const float* __restrict__ resid,
    float* __restrict__ C, __half* __restrict__ Ch, int N, int K)
{
    extern __shared__ char smem[];
    constexpr int SA     = 144;                // 64 halves (128B) + 16B pad
    constexpr int A_TILE = 256 * SA;           // 36864
    constexpr int B_TILE = 128 * SA;           // 18432
    constexpr int STAGE  = A_TILE + B_TILE;    // 55296

    const int tid  = threadIdx.x;
    const int wid  = tid >> 5;
    const int lane = tid & 31;
    const int wm   = wid >> 2;                 // 0..3
    const int wn   = wid & 3;                  // 0..3
    const int bm   = blockIdx.y * 256;
    const int bn   = blockIdx.x * 128;
    const uint32_t sb = smem_u32(smem);

    float acc[4][4][4];
#pragma unroll
    for (int mt = 0; mt < 4; mt++)
#pragma unroll
        for (int nt = 0; nt < 4; nt++)
#pragma unroll
            for (int q = 0; q < 4; q++) acc[mt][nt][q] = 0.f;

    auto load_stage = [&](int c, int s) {
        const int k0 = c * 64;
        const uint32_t st = sb + s * STAGE;
#pragma unroll
        for (int i = 0; i < 4; i++) {          // A: 256 rows x 8 chunks
            int id = tid + i * 512;
            int r = id >> 3, cc = id & 7;
            uint32_t so = st + r * SA + cc * 16;
            size_t g = (size_t)(bm + r) * K + k0 + cc * 8;
            CP_ASYNC16(so, A + g);
        }
#pragma unroll
        for (int i = 0; i < 2; i++) {          // B: 128 rows x 8 chunks
            int id = tid + i * 512;
            int r = id >> 3, cc = id & 7;
            uint32_t so = st + A_TILE + r * SA + cc * 16;
            size_t g = (size_t)(bn + r) * K + k0 + cc * 8;
            CP_ASYNC16(so, B + g);
        }
        CP_COMMIT();
    };

    const int chunks = K >> 6;
    load_stage(0, 0);
    for (int c = 0; c < chunks; c++) {
        if (c + 1 < chunks) load_stage(c + 1, (c + 1) & 1);
        else                CP_COMMIT();
        CP_WAIT1();
        __syncthreads();
        const uint32_t st = sb + (c & 1) * STAGE;
#pragma unroll
        for (int ks = 0; ks < 4; ks++) {
            uint32_t a4[4][4];
#pragma unroll
            for (int mt = 0; mt < 4; mt++) {
                uint32_t row = wm * 64 + mt * 16 + (lane & 15);
                uint32_t ad = st + row * SA + ks * 32 + ((lane >> 4) << 4);
                LDSM4(a4[mt], ad);
            }
#pragma unroll
            for (int nt = 0; nt < 4; nt++) {
                uint32_t rn = wn * 32 + nt * 8 + (lane & 7);
                uint32_t bd = st + A_TILE + rn * SA + ks * 32 +
                              (((lane >> 3) & 1) << 4);
                uint32_t b2[2];
                LDSM2(b2, bd);
#pragma unroll
                for (int mt = 0; mt < 4; mt++)
                    MMA16816(acc[mt][nt], a4[mt], b2);
            }
        }
        __syncthreads();
    }

    // ---------------- epilogue ----------------
#pragma unroll
    for (int mt = 0; mt < 4; mt++) {
#pragma unroll
        for (int nt = 0; nt < 4; nt++) {
            int r0 = bm + wm * 64 + mt * 16 + (lane >> 2);
            int c0 = bn + wn * 32 + nt * 8 + (lane & 3) * 2;
#pragma unroll
            for (int half_ = 0; half_ < 2; half_++) {
                int row = r0 + half_ * 8;
                float v0 = acc[mt][nt][half_ * 2];
                float v1 = acc[mt][nt][half_ * 2 + 1];
                size_t idx = (size_t)row * N + c0;
                if constexpr (EPI == EPI_BIAS || EPI == EPI_GELU) {
                    v0 += bias[c0];
                    v1 += bias[c0 + 1];
                }
                if constexpr (EPI == EPI_GELU) {
                    float u0 = 0.7978845608028654f * (v0 + 0.044715f * v0 * v0 * v0);
                    float u1 = 0.7978845608028654f * (v1 + 0.044715f * v1 * v1 * v1);
                    v0 = 0.5f * v0 * (1.f + tanhf(u0));
                    v1 = 0.5f * v1 * (1.f + tanhf(u1));
                    *(__half2*)(Ch + idx) =
                        __halves2half2(__float2half_rn(v0), __float2half_rn(v1));
                } else {
                    if constexpr (EPI == EPI_RESID) {
                        float2 rr = *(const float2*)(resid + idx);
                        v0 += rr.x; v1 += rr.y;
                    }
                    *(float2*)(C + idx) = make_float2(v0, v1);
                }
            }
        }
    }
}

// =======================================================================
// Small HMMA GEMM: BM=128, BK=32, 256 threads, 2-stage.
// Used for xproj (N=64, +fp16 copy), dtproj (K=32, softplus), ro2 (N=128).
// =======================================================================
template<int BN, int EPI>
__global__ __launch_bounds__(256) void mma_gemm(
    const __half* __restrict__ A, int lda,
    const __half* __restrict__ B,
    const float* __restrict__ bias, float* __restrict__ C,
    __half* __restrict__ Ch, int N, int K)
{
    extern __shared__ char smem[];
    constexpr int SA     = 80;
    constexpr int A_TILE = 128 * SA;
    constexpr int B_TILE = BN * SA;
    constexpr int STAGE  = A_TILE + B_TILE;
    constexpr int WN     = BN / 4;
    constexpr int NT     = WN / 8;

    const int tid  = threadIdx.x;
    const int wid  = tid >> 5;
    const int lane = tid & 31;
    const int wm   = wid >> 2;
    const int wn   = wid & 3;
    const int bm   = blockIdx.y * 128;
    const int bn   = blockIdx.x * BN;
    const uint32_t sb = smem_u32(smem);

    float acc[4][NT][4];
#pragma unroll
    for (int mt = 0; mt < 4; mt++)
#pragma unroll
        for (int nt = 0; nt < NT; nt++)
#pragma unroll
            for (int q = 0; q < 4; q++) acc[mt][nt][q] = 0.f;

    auto load_stage = [&](int c, int s) {
        const int k0 = c * 32;
        const uint32_t st = sb + s * STAGE;
#pragma unroll
        for (int i = 0; i < 2; i++) {
            int id = tid + i * 256;
            int r = id >> 2, cc = id & 3;
            uint32_t so = st + r * SA + cc * 16;
            size_t g = (size_t)(bm + r) * lda + k0 + cc * 8;
            CP_ASYNC16(so, A + g);
        }
#pragma unroll
        for (int i = 0; i < BN / 64; i++) {
            int id = tid + i * 256;
            int r = id >> 2, cc = id & 3;
            uint32_t so = st + A_TILE + r * SA + cc * 16;
            size_t g = (size_t)(bn + r) * K + k0 + cc * 8;
            CP_ASYNC16(so, B + g);
        }
        CP_COMMIT();
    };

    const int chunks = K >> 5;
    load_stage(0, 0);
    for (int c = 0; c < chunks; c++) {
        if (c + 1 < chunks) load_stage(c + 1, (c + 1) & 1);
        else                CP_COMMIT();
        CP_WAIT1();
        __syncthreads();
        const uint32_t st = sb + (c & 1) * STAGE;
#pragma unroll
        for (int ks = 0; ks < 2; ks++) {
            uint32_t a4[4][4];
#pragma unroll
            for (int mt = 0; mt < 4; mt++) {
                uint32_t row = wm * 64 + mt * 16 + (lane & 15);
                uint32_t ad = st + row * SA + ks * 32 + ((lane >> 4) << 4);
                LDSM4(a4[mt], ad);
            }
#pragma unroll
            for (int nt = 0; nt < NT; nt++) {
                uint32_t rn = wn * WN + nt * 8 + (lane & 7);
                uint32_t bd = st + A_TILE + rn * SA + ks * 32 +
                              (((lane >> 3) & 1) << 4);
                uint32_t b2[2];
                LDSM2(b2, bd);
#pragma unroll
                for (int mt = 0; mt < 4; mt++)
                    MMA16816(acc[mt][nt], a4[mt], b2);
            }
        }
        __syncthreads();
    }

#pragma unroll
    for (int mt = 0; mt < 4; mt++) {
#pragma unroll
        for (int nt = 0; nt < NT; nt++) {
            int r0 = bm + wm * 64 + mt * 16 + (lane >> 2);
            int c0 = bn + wn * WN + nt * 8 + (lane & 3) * 2;
#pragma unroll
            for (int half_ = 0; half_ < 2; half_++) {
                int row = r0 + half_ * 8;
                float v0 = acc[mt][nt][half_ * 2];
                float v1 = acc[mt][nt][half_ * 2 + 1];
                size_t idx = (size_t)row * N + c0;
                if constexpr (EPI == EPI_BIAS || EPI == EPI_SOFTPLUS) {
                    v0 += bias[c0];
                    v1 += bias[c0 + 1];
                }
                if constexpr (EPI == EPI_SOFTPLUS) {
                    v0 = (v0 > 20.f) ? v0 : log1pf(__expf(v0));
                    v1 = (v1 > 20.f) ? v1 : log1pf(__expf(v1));
                }
                *(float2*)(C + idx) = make_float2(v0, v1);
                if (Ch)
                    *(__half2*)(Ch + idx) =
                        __halves2half2(__float2half_rn(v0), __float2half_rn(v1));
            }
        }
    }
}

// ---------------- fp32 -> fp16 conversion ----------------
__global__ __launch_bounds__(256) void cvt_kernel(
    const float* __restrict__ x, __half* __restrict__ h)
{
    int i = blockIdx.x * 256 + threadIdx.x;
    float4 v = ((const float4*)x)[i];
    ((__half2*)h)[i * 2]     = __halves2half2(__float2half_rn(v.x), __float2half_rn(v.y));
    ((__half2*)h)[i * 2 + 1] = __halves2half2(__float2half_rn(v.z), __float2half_rn(v.w));
}

// ---------------- SIMT GEMM (embed only, K=32 fp32) ----------------
template<int BM, int BN, int BK, int TM, int TN>
__global__ __launch_bounds__(256) void gemm_k(
    const float* __restrict__ A, int lda,
    const float* __restrict__ W,
    const float* __restrict__ bias,
    float* __restrict__ C,
    int M, int N, int K)
{
    __shared__ float As[BK][BM];
    __shared__ float Ws[BK][BN];
    const int tid = threadIdx.x;
    const int bm = blockIdx.y * BM;
    const int bn = blockIdx.x * BN;
    constexpr int TX = BN / TN;
    const int tx = tid % TX;
    const int ty = tid / TX;

    float acc[TM][TN];
#pragma unroll
    for (int i = 0; i < TM; i++)
#pragma unroll
        for (int j = 0; j < TN; j++) acc[i][j] = 0.f;

    for (int k0 = 0; k0 < K; k0 += BK) {
#pragma unroll
        for (int i = tid; i < BM * BK; i += 256) {
            int r = i / BK, c = i % BK;
            As[c][r] = A[(size_t)(bm + r) * lda + k0 + c];
        }
#pragma unroll
        for (int i = tid; i < BN * BK; i += 256) {
            int r = i / BK, c = i % BK;
            Ws[c][r] = W[(size_t)(bn + r) * K + k0 + c];
        }
        __syncthreads();
#pragma unroll
        for (int kk = 0; kk < BK; kk++) {
            float ra[TM], rw[TN];
#pragma unroll
            for (int i = 0; i < TM; i++) ra[i] = As[kk][ty * TM + i];
#pragma unroll
            for (int j = 0; j < TN; j++) rw[j] = Ws[kk][tx * TN + j];
#pragma unroll
            for (int i = 0; i < TM; i++)
#pragma unroll
                for (int j = 0; j < TN; j++)
                    acc[i][j] = fmaf(ra[i], rw[j], acc[i][j]);
        }
        __syncthreads();
    }
#pragma unroll
    for (int i = 0; i < TM; i++) {
        int row = bm + ty * TM + i;
#pragma unroll
        for (int j = 0; j < TN; j++) {
            int col = bn + tx * TN + j;
            C[(size_t)row * N + col] = acc[i][j] + bias[col];
        }
    }
}

// ---------------- layernorm -> fp16, one warp per row ----------------
__global__ __launch_bounds__(256) void ln_kernel(
    const float* __restrict__ x, const float* __restrict__ w,
    const float* __restrict__ bb, __half* __restrict__ oh)
{
    int row  = blockIdx.x * 8 + (threadIdx.x >> 5);
    int lane = threadIdx.x & 31;
    const float* xr = x + (size_t)row * D_MODEL + lane;
    float v[16];
    float s = 0.f, s2 = 0.f;
#pragma unroll
    for (int i = 0; i < 16; i++) {
        v[i] = xr[i * 32];
        s += v[i];
        s2 = fmaf(v[i], v[i], s2);
    }
#pragma unroll
    for (int k = 16; k; k >>= 1) {
        s  += __shfl_xor_sync(0xffffffffu, s,  k);
        s2 += __shfl_xor_sync(0xffffffffu, s2, k);
    }
    float mu  = s * (1.f / 512.f);
    float var = fmaf(s2, 1.f / 512.f, -mu * mu);
    float rs  = rsqrtf(var + 1e-5f);
    size_t ob = (size_t)row * D_MODEL + lane;
#pragma unroll
    for (int i = 0; i < 16; i++) {
        float o = (v[i] - mu) * rs * w[lane + i * 32] + bb[lane + i * 32];
        oh[ob + i * 32] = __float2half_rn(o);
    }
}

// ---------------- causal depthwise conv (k=4) + SiLU -> fp32 + fp16 ------
__global__ __launch_bounds__(256) void conv_silu_kernel(
    const float* __restrict__ xz, const float* __restrict__ cw,
    const float* __restrict__ cb, float* __restrict__ xc,
    __half* __restrict__ xch)
{
    int idx = blockIdx.x * 256 + threadIdx.x;
    int d  = idx & (D_INNER - 1);
    int bl = idx >> 10;
    int t  = bl & (L_SEQ - 1);
    const float* xp = xz + (size_t)bl * (2 * D_INNER) + d;
    float4 w = __ldg((const float4*)cw + d);
    float acc = cb[d];
    acc = fmaf(w.w, xp[0], acc);
    if (t >= 1) acc = fmaf(w.z, xp[-(2 * D_INNER)],     acc);
    if (t >= 2) acc = fmaf(w.y, xp[-2 * (2 * D_INNER)], acc);
    if (t >= 3) acc = fmaf(w.x, xp[-3 * (2 * D_INNER)], acc);
    float s = __fdividef(acc, 1.f + __expf(-acc));
    xc[idx] = s;
    xch[idx] = __float2half_rn(s);
}

// ---------------- selective scan -> ys fp16 ----------------
__global__ __launch_bounds__(256) void scan_kernel(
    const float* __restrict__ dt_g, const float* __restrict__ xc_g,
    const float* __restrict__ dbl_g, const float* __restrict__ xz_g,
    const float* __restrict__ A_log, const float* __restrict__ Dsk,
    __half* __restrict__ ysh)
{
    const int gw   = (blockIdx.x * 256 + threadIdx.x) >> 5;
    const int lane = threadIdx.x & 31;
    const int b    = gw >> 9;
    const int d0   = (gw & 511) << 1;
    const int half = lane >> 4;
    const int n    = lane & 15;
    const int d    = d0 + half;

    const float An = -__expf(__ldg(A_log + d * N_STATE + n));
    const float Dd = __ldg(Dsk + d);
    const size_t base = (size_t)b * L_SEQ;

    const float2* dtp = (const float2*)(dt_g + base * D_INNER + d0);
    const float2* xcp = (const float2*)(xc_g + base * D_INNER + d0);
    const float2* zp  = (const float2*)(xz_g + base * (2 * D_INNER) + D_INNER + d0);
    const float*  bcp = dbl_g + base * 64 + 32 + lane;
    __half* yph = ysh + base * D_INNER + d;

    float h = 0.f;
    float2 adt[4], axc[4], az[4]; float abc[4];
    float2 bdt[4], bxc[4], bz[4]; float bbc[4];

#define LOADQ(T0, DT, XC, Z, BC)                                          \
    {                                                                     \
        _Pragma("unroll")                                                 \
        for (int j = 0; j < 4; j++) {                                     \
            int tt = (T0) + j;                                            \
            DT[j] = __ldg(dtp + (size_t)tt * (D_INNER / 2));              \
            XC[j] = __ldg(xcp + (size_t)tt * (D_INNER / 2));              \
            Z[j]  = __ldg(zp  + (size_t)tt * D_INNER);                    \
            BC[j] = __ldg(bcp + (size_t)tt * 64);                         \
        }                                                                 \
    }
#define STEP(T, DTv, XCv, Zv, BCv)                                        \
    {                                                                     \
        float dtv = half ? (DTv).y : (DTv).x;                             \
        float xv  = half ? (XCv).y : (XCv).x;                             \
        float bn = __shfl_sync(0xffffffffu, (BCv), n);                    \
        float cn = __shfl_sync(0xffffffffu, (BCv), n + 16);               \
        float dA = __expf(dtv * An);                                      \
        h = fmaf(dA, h, dtv * xv * bn);                                   \
        float p = h * cn;                                                 \
        p += __shfl_xor_sync(0xffffffffu, p, 1);                          \
        p += __shfl_xor_sync(0xffffffffu, p, 2);                          \
        p += __shfl_xor_sync(0xffffffffu, p, 4);                          \
        p += __shfl_xor_sync(0xffffffffu, p, 8);                          \
        if (n == 0) {                                                     \
            float zv = half ? (Zv).y : (Zv).x;                            \
            float yv = fmaf(xv, Dd, p);                                   \
            float o  = yv * __fdividef(zv, 1.f + __expf(-zv));            \
            yph[(size_t)(T) * D_INNER] = __float2half_rn(o);              \
        }                                                                 \
    }

    LOADQ(0, adt, axc, az, abc);
    for (int t0 = 0; t0 < L_SEQ; t0 += 8) {
        LOADQ(t0 + 4, bdt, bxc, bz, bbc);
#pragma unroll
        for (int j = 0; j < 4; j++) STEP(t0 + j, adt[j], axc[j], az[j], abc[j]);
        if (t0 + 8 < L_SEQ) LOADQ(t0 + 8, adt, axc, az, abc);
#pragma unroll
        for (int j = 0; j < 4; j++) STEP(t0 + 4 + j, bdt[j], bxc[j], bz[j], bbc[j]);
    }
#undef LOADQ
#undef STEP
}

// ---------------- host orchestration ----------------
extern "C" void kernel_launch(void* const* d_in, const int* in_sizes, int n_in,
                              void* d_out, int out_size)
{
    const float* y        = (const float*)d_in[0];
    const float* emb_w    = (const float*)d_in[1];
    const float* emb_b    = (const float*)d_in[2];
    const float* ln_w     = (const float*)d_in[3];
    const float* ln_b     = (const float*)d_in[4];
    const float* mix_w    = (const float*)d_in[5];
    const float* conv_w   = (const float*)d_in[6];
    const float* conv_b   = (const float*)d_in[7];
    const float* xproj_w  = (const float*)d_in[8];
    const float* dtproj_w = (const float*)d_in[9];
    const float* dtproj_b = (const float*)d_in[10];
    const float* A_log    = (const float*)d_in[11];
    const float* Dskip    = (const float*)d_in[12];
    const float* out_w    = (const float*)d_in[13];
    const float* normf_w  = (const float*)d_in[14];
    const float* normf_b  = (const float*)d_in[15];
    const float* ro1_w    = (const float*)d_in[16];
    const float* ro1_b    = (const float*)d_in[17];
    const float* ro2_w    = (const float*)d_in[18];
    const float* ro2_b    = (const float*)d_in[19];

    float *h, *xz, *xc, *dbl, *dt;
    cudaGetSymbolAddress((void**)&h,   g_h);
    cudaGetSymbolAddress((void**)&xz,  g_xz);
    cudaGetSymbolAddress((void**)&xc,  g_xc);
    cudaGetSymbolAddress((void**)&dbl, g_dbl);
    cudaGetSymbolAddress((void**)&dt,  g_dt);
    __half *xin, *xch, *ysh, *h2, *dblh, *mw, *xpw, *ow, *dtw, *r1w, *r2w;
    cudaGetSymbolAddress((void**)&xin,  g_xin);
    cudaGetSymbolAddress((void**)&xch,  g_xch);
    cudaGetSymbolAddress((void**)&ysh,  g_ysh);
    cudaGetSymbolAddress((void**)&h2,   g_h2);
    cudaGetSymbolAddress((void**)&dblh, g_dblh);
    cudaGetSymbolAddress((void**)&mw,   g_mixw);
    cudaGetSymbolAddress((void**)&xpw,  g_xpw);
    cudaGetSymbolAddress((void**)&ow,   g_ow);
    cudaGetSymbolAddress((void**)&dtw,  g_dtw);
    cudaGetSymbolAddress((void**)&r1w,  g_r1w);
    cudaGetSymbolAddress((void**)&r2w,  g_r2w);

    const int M = BL_ROWS;
    constexpr int SBIG = 2 * (256 * 144 + 128 * 144);  // 110592
    constexpr int S128 = 2 * (128 * 80 + 128 * 80);    // 40960
    constexpr int S64  = 2 * (128 * 80 + 64 * 80);     // 30720
    cudaFuncSetAttribute(mma_gemm2<EPI_NONE>,  cudaFuncAttributeMaxDynamicSharedMemorySize, SBIG);
    cudaFuncSetAttribute(mma_gemm2<EPI_RESID>, cudaFuncAttributeMaxDynamicSharedMemorySize, SBIG);
    cudaFuncSetAttribute(mma_gemm2<EPI_GELU>,  cudaFuncAttributeMaxDynamicSharedMemorySize, SBIG);
    cudaFuncSetAttribute(mma_gemm<128, EPI_BIAS>,     cudaFuncAttributeMaxDynamicSharedMemorySize, S128);
    cudaFuncSetAttribute(mma_gemm<128, EPI_SOFTPLUS>, cudaFuncAttributeMaxDynamicSharedMemorySize, S128);
    cudaFuncSetAttribute(mma_gemm<64,  EPI_NONE>,     cudaFuncAttributeMaxDynamicSharedMemorySize, S64);

    // order chosen so launch index 5 (ncu -s 5 -c 1) = layer-0 mix GEMM
    gemm_k<64, 64, 16, 4, 4><<<dim3(D_MODEL / 64, M / 64), 256>>>(
        y, P_DIM, emb_w, emb_b, h, M, D_MODEL, P_DIM);                  // 0
    cvt_kernel<<<(N_LAYER * 2 * D_INNER * D_MODEL) / 1024, 256>>>(mix_w, mw); // 1
    cvt_kernel<<<(N_LAYER * 64 * D_INNER) / 1024, 256>>>(xproj_w, xpw);       // 2
    cvt_kernel<<<(N_LAYER * D_MODEL * D_INNER) / 1024, 256>>>(out_w, ow);     // 3
    ln_kernel<<<M / 8, 256>>>(h, ln_w, ln_b, xin);                            // 4
    mma_gemm2<EPI_NONE><<<dim3(16, M / 256), 512, SBIG>>>(                    // 5
        xin, mw, nullptr, nullptr, xz, nullptr, 2 * D_INNER, D_MODEL);
    cvt_kernel<<<(N_LAYER * D_INNER * DT_RANK) / 1024, 256>>>(dtproj_w, dtw); // 6
    cvt_kernel<<<(D_MODEL * D_MODEL) / 1024, 256>>>(ro1_w, r1w);              // 7
    cvt_kernel<<<(128 * D_MODEL) / 1024, 256>>>(ro2_w, r2w);                  // 8

    for (int i = 0; i < N_LAYER; i++) {
        const float* cw  = conv_w + (size_t)i * D_INNER * 4;
        const float* cb  = conv_b + (size_t)i * D_INNER;
        const float* dpb = dtproj_b + (size_t)i * D_INNER;
        const float* Al  = A_log + (size_t)i * D_INNER * N_STATE;
        const float* Dk  = Dskip + (size_t)i * D_INNER;

        if (i > 0) {
            ln_kernel<<<M / 8, 256>>>(h, ln_w + i * D_MODEL, ln_b + i * D_MODEL, xin);
            mma_gemm2<EPI_NONE><<<dim3(16, M / 256), 512, SBIG>>>(
                xin, mw + (size_t)i * 2 * D_INNER * D_MODEL,
                nullptr, nullptr, xz, nullptr, 2 * D_INNER, D_MODEL);
        }
        // conv + silu -> xc fp32 + fp16
        conv_silu_kernel<<<(M * D_INNER) / 256, 256>>>(xz, cw, cb, xc, xch);
        // dbl = xc @ xproj_w^T  (M x 64, K=1024) -> fp32 + fp16
        mma_gemm<64, EPI_NONE><<<dim3(1, M / 128), 256, S64>>>(
            xch, D_INNER, xpw + (size_t)i * 64 * D_INNER,
            nullptr, dbl, dblh, 64, D_INNER);
        // dt = softplus(dbl_h[:, :32] @ dtproj_w^T + b)  (M x 1024, K=32) HMMA
        mma_gemm<128, EPI_SOFTPLUS><<<dim3(D_INNER / 128, M / 128), 256, S128>>>(
            dblh, 64, dtw + (size_t)i * D_INNER * DT_RANK,
            dpb, dt, nullptr, D_INNER, DT_RANK);
        // selective scan + gate -> ys fp16
        scan_kernel<<<512, 256>>>(dt, xc, dbl, xz, Al, Dk, ysh);
        // h = h + ys @ out_w^T  (M x 512, K=1024)
        mma_gemm2<EPI_RESID><<<dim3(4, M / 256), 512, SBIG>>>(
            ysh, ow + (size_t)i * D_MODEL * D_INNER,
            nullptr, h, h, nullptr, D_MODEL, D_INNER);
    }

    // final LN -> fp16
    ln_kernel<<<M / 8, 256>>>(h, normf_w, normf_b, xin);
    // h2 = gelu(xin @ ro1_w^T + b) -> fp16
    mma_gemm2<EPI_GELU><<<dim3(4, M / 256), 512, SBIG>>>(
        xin, r1w, ro1_b, nullptr, nullptr, h2, D_MODEL, D_MODEL);
    // out = h2 @ ro2_w^T + b
    mma_gemm<128, EPI_BIAS><<<dim3(1, M / 128), 256, S128>>>(
        h2, D_MODEL, r2w, ro2_b, (float*)d_out, nullptr, 128, D_MODEL);
}

// round 9
// speedup vs baseline: 2.3424x; 1.0236x over previous
#include <cuda_runtime.h>
#include <cuda_fp16.h>
#include <cstdint>

// ---------------- problem constants ----------------
#define B_SZ     8
#define L_SEQ    2048
#define P_DIM    32
#define D_MODEL  512
#define D_INNER  1024
#define N_STATE  16
#define DT_RANK  32
#define N_LAYER  4
#define BL_ROWS  (B_SZ * L_SEQ)          // 16384

// ---------------- scratch (static device globals) ----------------
__device__ __align__(16) float g_h  [(size_t)BL_ROWS * D_MODEL];
__device__ __align__(16) float g_xz [(size_t)BL_ROWS * 2 * D_INNER];
__device__ __align__(16) float g_xc [(size_t)BL_ROWS * D_INNER];
__device__ __align__(16) float g_dbl[(size_t)BL_ROWS * 64];
__device__ __align__(16) float g_dt [(size_t)BL_ROWS * D_INNER];

__device__ __align__(16) __half g_xin [(size_t)BL_ROWS * D_MODEL];
__device__ __align__(16) __half g_xch [(size_t)BL_ROWS * D_INNER];
__device__ __align__(16) __half g_ysh [(size_t)BL_ROWS * D_INNER];
__device__ __align__(16) __half g_h2  [(size_t)BL_ROWS * D_MODEL];
__device__ __align__(16) __half g_dblh[(size_t)BL_ROWS * 64];

__device__ __align__(16) __half g_mixw[(size_t)N_LAYER * 2 * D_INNER * D_MODEL];
__device__ __align__(16) __half g_xpw [(size_t)N_LAYER * 64 * D_INNER];
__device__ __align__(16) __half g_ow  [(size_t)N_LAYER * D_MODEL * D_INNER];
__device__ __align__(16) __half g_dtw [(size_t)N_LAYER * D_INNER * DT_RANK];
__device__ __align__(16) __half g_r1w [(size_t)D_MODEL * D_MODEL];
__device__ __align__(16) __half g_r2w [(size_t)128 * D_MODEL];

// ---------------- PTX helpers ----------------
__device__ __forceinline__ uint32_t smem_u32(const void* p) {
    uint32_t a;
    asm("{ .reg .u64 t; cvta.to.shared.u64 t, %1; cvt.u32.u64 %0, t; }"
        : "=r"(a) : "l"(p));
    return a;
}
#define CP_ASYNC16(sa, ga)                                                   \
    asm volatile("cp.async.cg.shared.global [%0], [%1], 16;"                 \
                 :: "r"(sa), "l"(ga))
#define CP_COMMIT() asm volatile("cp.async.commit_group;" ::: "memory")
#define CP_WAIT1()  asm volatile("cp.async.wait_group 1;"  ::: "memory")
#define LDSM4(R, A)                                                          \
    asm volatile("ldmatrix.sync.aligned.m8n8.x4.shared.b16 {%0,%1,%2,%3},[%4];" \
                 : "=r"((R)[0]), "=r"((R)[1]), "=r"((R)[2]), "=r"((R)[3])    \
                 : "r"(A))
#define LDSM2(R, A)                                                          \
    asm volatile("ldmatrix.sync.aligned.m8n8.x2.shared.b16 {%0,%1},[%2];"    \
                 : "=r"((R)[0]), "=r"((R)[1]) : "r"(A))
#define MMA16816(C, A, B)                                                    \
    asm volatile("mma.sync.aligned.m16n8k16.row.col.f32.f16.f16.f32 "        \
                 "{%0,%1,%2,%3},{%4,%5,%6,%7},{%8,%9},{%0,%1,%2,%3};"        \
                 : "+f"((C)[0]), "+f"((C)[1]), "+f"((C)[2]), "+f"((C)[3])    \
                 : "r"((A)[0]), "r"((A)[1]), "r"((A)[2]), "r"((A)[3]),       \
                   "r"((B)[0]), "r"((B)[1]))

// ---------------- epilogue ids ----------------
#define EPI_NONE     0
#define EPI_BIAS     1
#define EPI_SOFTPLUS 2
#define EPI_GELU     3
#define EPI_RESID    4

// =======================================================================
// Unified HMMA GEMM: BM=128, BN in {64,128}, BK=64, 256 threads (8 warps
// 2x4), warp tile 64x32(or 64x16), 2-stage cp.async, fp32 accum.
// smem 73.7KB (BN=128) => 2-3 CTAs/SM for cross-CTA latency hiding.
// =======================================================================
template<int BN, int EPI>
__global__ __launch_bounds__(256, 2) void mma_gemmU(
    const __half* __restrict__ A, int lda,
    const __half* __restrict__ B,
    const float* __restrict__ bias, const float* __restrict__ resid,
    float* __restrict__ C, __half* __restrict__ Ch, int N, int K)
{
    extern __shared__ char smem[];
    constexpr int SA     = 144;                 // 64 halves (128B) + 16B pad
    constexpr int A_TILE = 128 * SA;            // 18432
    constexpr int B_TILE = BN * SA;
    constexpr int STAGE  = A_TILE + B_TILE;
    constexpr int WN     = BN / 4;
    constexpr int NT     = WN / 8;

    const int tid  = threadIdx.x;
    const int wid  = tid >> 5;
    const int lane = tid & 31;
    const int wm   = wid >> 2;                  // 0..1
    const int wn   = wid & 3;                   // 0..3
    const int bm   = blockIdx.y * 128;
    const int bn   = blockIdx.x * BN;
    const uint32_t sb = smem_u32(smem);

    float acc[4][NT][4];
#pragma unroll
    for (int mt = 0; mt < 4; mt++)
#pragma unroll
        for (int nt = 0; nt < NT; nt++)
#pragma unroll
            for (int q = 0; q < 4; q++) acc[mt][nt][q] = 0.f;

    auto load_stage = [&](int c, int s) {
        const int k0 = c * 64;
        const uint32_t st = sb + s * STAGE;
#pragma unroll
        for (int i = 0; i < 4; i++) {           // A: 128 rows x 8 x 16B
            int id = tid + i * 256;
            int r = id >> 3, cc = id & 7;
            uint32_t so = st + r * SA + cc * 16;
            size_t g = (size_t)(bm + r) * lda + k0 + cc * 8;
            CP_ASYNC16(so, A + g);
        }
#pragma unroll
        for (int i = 0; i < BN / 32; i++) {     // B: BN rows x 8 x 16B
            int id = tid + i * 256;
            int r = id >> 3, cc = id & 7;
            uint32_t so = st + A_TILE + r * SA + cc * 16;
            size_t g = (size_t)(bn + r) * K + k0 + cc * 8;
            CP_ASYNC16(so, B + g);
        }
        CP_COMMIT();
    };

    const int chunks = K >> 6;
    load_stage(0, 0);
    for (int c = 0; c < chunks; c++) {
        if (c + 1 < chunks) load_stage(c + 1, (c + 1) & 1);
        else                CP_COMMIT();
        CP_WAIT1();
        __syncthreads();
        const uint32_t st = sb + (c & 1) * STAGE;
#pragma unroll
        for (int ks = 0; ks < 4; ks++) {
            uint32_t a4[4][4];
#pragma unroll
            for (int mt = 0; mt < 4; mt++) {
                uint32_t row = wm * 64 + mt * 16 + (lane & 15);
                uint32_t ad = st + row * SA + ks * 32 + ((lane >> 4) << 4);
                LDSM4(a4[mt], ad);
            }
#pragma unroll
            for (int nt = 0; nt < NT; nt++) {
                uint32_t rn = wn * WN + nt * 8 + (lane & 7);
                uint32_t bd = st + A_TILE + rn * SA + ks * 32 +
                              (((lane >> 3) & 1) << 4);
                uint32_t b2[2];
                LDSM2(b2, bd);
#pragma unroll
                for (int mt = 0; mt < 4; mt++)
                    MMA16816(acc[mt][nt], a4[mt], b2);
            }
        }
        __syncthreads();
    }

    // ---------------- epilogue ----------------
#pragma unroll
    for (int mt = 0; mt < 4; mt++) {
#pragma unroll
        for (int nt = 0; nt < NT; nt++) {
            int r0 = bm + wm * 64 + mt * 16 + (lane >> 2);
            int c0 = bn + wn * WN + nt * 8 + (lane & 3) * 2;
#pragma unroll
            for (int half_ = 0; half_ < 2; half_++) {
                int row = r0 + half_ * 8;
                float v0 = acc[mt][nt][half_ * 2];
                float v1 = acc[mt][nt][half_ * 2 + 1];
                size_t idx = (size_t)row * N + c0;
                if constexpr (EPI == EPI_BIAS || EPI == EPI_GELU) {
                    v0 += bias[c0];
                    v1 += bias[c0 + 1];
                }
                if constexpr (EPI == EPI_GELU) {
                    float u0 = 0.7978845608028654f * (v0 + 0.044715f * v0 * v0 * v0);
                    float u1 = 0.7978845608028654f * (v1 + 0.044715f * v1 * v1 * v1);
                    v0 = 0.5f * v0 * (1.f + tanhf(u0));
                    v1 = 0.5f * v1 * (1.f + tanhf(u1));
                    *(__half2*)(Ch + idx) =
                        __halves2half2(__float2half_rn(v0), __float2half_rn(v1));
                } else {
                    if constexpr (EPI == EPI_RESID) {
                        float2 rr = *(const float2*)(resid + idx);
                        v0 += rr.x; v1 += rr.y;
                    }
                    *(float2*)(C + idx) = make_float2(v0, v1);
                    if (Ch)
                        *(__half2*)(Ch + idx) =
                            __halves2half2(__float2half_rn(v0), __float2half_rn(v1));
                }
            }
        }
    }
}

// =======================================================================
// Small HMMA GEMM: BM=128, BK=32, 256 threads, 2-stage. Used for dtproj
// (K=32, softplus epilogue).
// =======================================================================
template<int BN, int EPI>
__global__ __launch_bounds__(256) void mma_gemm(
    const __half* __restrict__ A, int lda,
    const __half* __restrict__ B,
    const float* __restrict__ bias, float* __restrict__ C,
    __half* __restrict__ Ch, int N, int K)
{
    extern __shared__ char smem[];
    constexpr int SA     = 80;
    constexpr int A_TILE = 128 * SA;
    constexpr int B_TILE = BN * SA;
    constexpr int STAGE  = A_TILE + B_TILE;
    constexpr int WN     = BN / 4;
    constexpr int NT     = WN / 8;

    const int tid  = threadIdx.x;
    const int wid  = tid >> 5;
    const int lane = tid & 31;
    const int wm   = wid >> 2;
    const int wn   = wid & 3;
    const int bm   = blockIdx.y * 128;
    const int bn   = blockIdx.x * BN;
    const uint32_t sb = smem_u32(smem);

    float acc[4][NT][4];
#pragma unroll
    for (int mt = 0; mt < 4; mt++)
#pragma unroll
        for (int nt = 0; nt < NT; nt++)
#pragma unroll
            for (int q = 0; q < 4; q++) acc[mt][nt][q] = 0.f;

    auto load_stage = [&](int c, int s) {
        const int k0 = c * 32;
        const uint32_t st = sb + s * STAGE;
#pragma unroll
        for (int i = 0; i < 2; i++) {
            int id = tid + i * 256;
            int r = id >> 2, cc = id & 3;
            uint32_t so = st + r * SA + cc * 16;
            size_t g = (size_t)(bm + r) * lda + k0 + cc * 8;
            CP_ASYNC16(so, A + g);
        }
#pragma unroll
        for (int i = 0; i < BN / 64; i++) {
            int id = tid + i * 256;
            int r = id >> 2, cc = id & 3;
            uint32_t so = st + A_TILE + r * SA + cc * 16;
            size_t g = (size_t)(bn + r) * K + k0 + cc * 8;
            CP_ASYNC16(so, B + g);
        }
        CP_COMMIT();
    };

    const int chunks = K >> 5;
    load_stage(0, 0);
    for (int c = 0; c < chunks; c++) {
        if (c + 1 < chunks) load_stage(c + 1, (c + 1) & 1);
        else                CP_COMMIT();
        CP_WAIT1();
        __syncthreads();
        const uint32_t st = sb + (c & 1) * STAGE;
#pragma unroll
        for (int ks = 0; ks < 2; ks++) {
            uint32_t a4[4][4];
#pragma unroll
            for (int mt = 0; mt < 4; mt++) {
                uint32_t row = wm * 64 + mt * 16 + (lane & 15);
                uint32_t ad = st + row * SA + ks * 32 + ((lane >> 4) << 4);
                LDSM4(a4[mt], ad);
            }
#pragma unroll
            for (int nt = 0; nt < NT; nt++) {
                uint32_t rn = wn * WN + nt * 8 + (lane & 7);
                uint32_t bd = st + A_TILE + rn * SA + ks * 32 +
                              (((lane >> 3) & 1) << 4);
                uint32_t b2[2];
                LDSM2(b2, bd);
#pragma unroll
                for (int mt = 0; mt < 4; mt++)
                    MMA16816(acc[mt][nt], a4[mt], b2);
            }
        }
        __syncthreads();
    }

#pragma unroll
    for (int mt = 0; mt < 4; mt++) {
#pragma unroll
        for (int nt = 0; nt < NT; nt++) {
            int r0 = bm + wm * 64 + mt * 16 + (lane >> 2);
            int c0 = bn + wn * WN + nt * 8 + (lane & 3) * 2;
#pragma unroll
            for (int half_ = 0; half_ < 2; half_++) {
                int row = r0 + half_ * 8;
                float v0 = acc[mt][nt][half_ * 2];
                float v1 = acc[mt][nt][half_ * 2 + 1];
                size_t idx = (size_t)row * N + c0;
                if constexpr (EPI == EPI_BIAS || EPI == EPI_SOFTPLUS) {
                    v0 += bias[c0];
                    v1 += bias[c0 + 1];
                }
                if constexpr (EPI == EPI_SOFTPLUS) {
                    v0 = (v0 > 20.f) ? v0 : log1pf(__expf(v0));
                    v1 = (v1 > 20.f) ? v1 : log1pf(__expf(v1));
                }
                *(float2*)(C + idx) = make_float2(v0, v1);
                if (Ch)
                    *(__half2*)(Ch + idx) =
                        __halves2half2(__float2half_rn(v0), __float2half_rn(v1));
            }
        }
    }
}

// ---------------- fp32 -> fp16 conversion ----------------
__global__ __launch_bounds__(256) void cvt_kernel(
    const float* __restrict__ x, __half* __restrict__ h)
{
    int i = blockIdx.x * 256 + threadIdx.x;
    float4 v = ((const float4*)x)[i];
    ((__half2*)h)[i * 2]     = __halves2half2(__float2half_rn(v.x), __float2half_rn(v.y));
    ((__half2*)h)[i * 2 + 1] = __halves2half2(__float2half_rn(v.z), __float2half_rn(v.w));
}

// ---------------- SIMT GEMM (embed only, K=32 fp32) ----------------
template<int BM, int BN, int BK, int TM, int TN>
__global__ __launch_bounds__(256) void gemm_k(
    const float* __restrict__ A, int lda,
    const float* __restrict__ W,
    const float* __restrict__ bias,
    float* __restrict__ C,
    int M, int N, int K)
{
    __shared__ float As[BK][BM];
    __shared__ float Ws[BK][BN];
    const int tid = threadIdx.x;
    const int bm = blockIdx.y * BM;
    const int bn = blockIdx.x * BN;
    constexpr int TX = BN / TN;
    const int tx = tid % TX;
    const int ty = tid / TX;

    float acc[TM][TN];
#pragma unroll
    for (int i = 0; i < TM; i++)
#pragma unroll
        for (int j = 0; j < TN; j++) acc[i][j] = 0.f;

    for (int k0 = 0; k0 < K; k0 += BK) {
#pragma unroll
        for (int i = tid; i < BM * BK; i += 256) {
            int r = i / BK, c = i % BK;
            As[c][r] = A[(size_t)(bm + r) * lda + k0 + c];
        }
#pragma unroll
        for (int i = tid; i < BN * BK; i += 256) {
            int r = i / BK, c = i % BK;
            Ws[c][r] = W[(size_t)(bn + r) * K + k0 + c];
        }
        __syncthreads();
#pragma unroll
        for (int kk = 0; kk < BK; kk++) {
            float ra[TM], rw[TN];
#pragma unroll
            for (int i = 0; i < TM; i++) ra[i] = As[kk][ty * TM + i];
#pragma unroll
            for (int j = 0; j < TN; j++) rw[j] = Ws[kk][tx * TN + j];
#pragma unroll
            for (int i = 0; i < TM; i++)
#pragma unroll
                for (int j = 0; j < TN; j++)
                    acc[i][j] = fmaf(ra[i], rw[j], acc[i][j]);
        }
        __syncthreads();
    }
#pragma unroll
    for (int i = 0; i < TM; i++) {
        int row = bm + ty * TM + i;
#pragma unroll
        for (int j = 0; j < TN; j++) {
            int col = bn + tx * TN + j;
            C[(size_t)row * N + col] = acc[i][j] + bias[col];
        }
    }
}

// ---------------- layernorm -> fp16, one warp per row ----------------
__global__ __launch_bounds__(256) void ln_kernel(
    const float* __restrict__ x, const float* __restrict__ w,
    const float* __restrict__ bb, __half* __restrict__ oh)
{
    int row  = blockIdx.x * 8 + (threadIdx.x >> 5);
    int lane = threadIdx.x & 31;
    const float* xr = x + (size_t)row * D_MODEL + lane;
    float v[16];
    float s = 0.f, s2 = 0.f;
#pragma unroll
    for (int i = 0; i < 16; i++) {
        v[i] = xr[i * 32];
        s += v[i];
        s2 = fmaf(v[i], v[i], s2);
    }
#pragma unroll
    for (int k = 16; k; k >>= 1) {
        s  += __shfl_xor_sync(0xffffffffu, s,  k);
        s2 += __shfl_xor_sync(0xffffffffu, s2, k);
    }
    float mu  = s * (1.f / 512.f);
    float var = fmaf(s2, 1.f / 512.f, -mu * mu);
    float rs  = rsqrtf(var + 1e-5f);
    size_t ob = (size_t)row * D_MODEL + lane;
#pragma unroll
    for (int i = 0; i < 16; i++) {
        float o = (v[i] - mu) * rs * w[lane + i * 32] + bb[lane + i * 32];
        oh[ob + i * 32] = __float2half_rn(o);
    }
}

// ---------------- causal depthwise conv (k=4) + SiLU -> fp32 + fp16 ------
__global__ __launch_bounds__(256) void conv_silu_kernel(
    const float* __restrict__ xz, const float* __restrict__ cw,
    const float* __restrict__ cb, float* __restrict__ xc,
    __half* __restrict__ xch)
{
    int idx = blockIdx.x * 256 + threadIdx.x;
    int d  = idx & (D_INNER - 1);
    int bl = idx >> 10;
    int t  = bl & (L_SEQ - 1);
    const float* xp = xz + (size_t)bl * (2 * D_INNER) + d;
    float4 w = __ldg((const float4*)cw + d);
    float acc = cb[d];
    acc = fmaf(w.w, xp[0], acc);
    if (t >= 1) acc = fmaf(w.z, xp[-(2 * D_INNER)],     acc);
    if (t >= 2) acc = fmaf(w.y, xp[-2 * (2 * D_INNER)], acc);
    if (t >= 3) acc = fmaf(w.x, xp[-3 * (2 * D_INNER)], acc);
    float s = __fdividef(acc, 1.f + __expf(-acc));
    xc[idx] = s;
    xch[idx] = __float2half_rn(s);
}

// ---------------- selective scan -> ys fp16 ----------------
__global__ __launch_bounds__(256) void scan_kernel(
    const float* __restrict__ dt_g, const float* __restrict__ xc_g,
    const float* __restrict__ dbl_g, const float* __restrict__ xz_g,
    const float* __restrict__ A_log, const float* __restrict__ Dsk,
    __half* __restrict__ ysh)
{
    const int gw   = (blockIdx.x * 256 + threadIdx.x) >> 5;
    const int lane = threadIdx.x & 31;
    const int b    = gw >> 9;
    const int d0   = (gw & 511) << 1;
    const int half = lane >> 4;
    const int n    = lane & 15;
    const int d    = d0 + half;

    const float An = -__expf(__ldg(A_log + d * N_STATE + n));
    const float Dd = __ldg(Dsk + d);
    const size_t base = (size_t)b * L_SEQ;

    const float2* dtp = (const float2*)(dt_g + base * D_INNER + d0);
    const float2* xcp = (const float2*)(xc_g + base * D_INNER + d0);
    const float2* zp  = (const float2*)(xz_g + base * (2 * D_INNER) + D_INNER + d0);
    const float*  bcp = dbl_g + base * 64 + 32 + lane;
    __half* yph = ysh + base * D_INNER + d;

    float h = 0.f;
    float2 adt[4], axc[4], az[4]; float abc[4];
    float2 bdt[4], bxc[4], bz[4]; float bbc[4];

#define LOADQ(T0, DT, XC, Z, BC)                                          \
    {                                                                     \
        _Pragma("unroll")                                                 \
        for (int j = 0; j < 4; j++) {                                     \
            int tt = (T0) + j;                                            \
            DT[j] = __ldg(dtp + (size_t)tt * (D_INNER / 2));              \
            XC[j] = __ldg(xcp + (size_t)tt * (D_INNER / 2));              \
            Z[j]  = __ldg(zp  + (size_t)tt * D_INNER);                    \
            BC[j] = __ldg(bcp + (size_t)tt * 64);                         \
        }                                                                 \
    }
#define STEP(T, DTv, XCv, Zv, BCv)                                        \
    {                                                                     \
        float dtv = half ? (DTv).y : (DTv).x;                             \
        float xv  = half ? (XCv).y : (XCv).x;                             \
        float bn = __shfl_sync(0xffffffffu, (BCv), n);                    \
        float cn = __shfl_sync(0xffffffffu, (BCv), n + 16);               \
        float dA = __expf(dtv * An);                                      \
        h = fmaf(dA, h, dtv * xv * bn);                                   \
        float p = h * cn;                                                 \
        p += __shfl_xor_sync(0xffffffffu, p, 1);                          \
        p += __shfl_xor_sync(0xffffffffu, p, 2);                          \
        p += __shfl_xor_sync(0xffffffffu, p, 4);                          \
        p += __shfl_xor_sync(0xffffffffu, p, 8);                          \
        if (n == 0) {                                                     \
            float zv = half ? (Zv).y : (Zv).x;                            \
            float yv = fmaf(xv, Dd, p);                                   \
            float o  = yv * __fdividef(zv, 1.f + __expf(-zv));            \
            yph[(size_t)(T) * D_INNER] = __float2half_rn(o);              \
        }                                                                 \
    }

    LOADQ(0, adt, axc, az, abc);
    for (int t0 = 0; t0 < L_SEQ; t0 += 8) {
        LOADQ(t0 + 4, bdt, bxc, bz, bbc);
#pragma unroll
        for (int j = 0; j < 4; j++) STEP(t0 + j, adt[j], axc[j], az[j], abc[j]);
        if (t0 + 8 < L_SEQ) LOADQ(t0 + 8, adt, axc, az, abc);
#pragma unroll
        for (int j = 0; j < 4; j++) STEP(t0 + 4 + j, bdt[j], bxc[j], bz[j], bbc[j]);
    }
#undef LOADQ
#undef STEP
}

// ---------------- host orchestration ----------------
extern "C" void kernel_launch(void* const* d_in, const int* in_sizes, int n_in,
                              void* d_out, int out_size)
{
    const float* y        = (const float*)d_in[0];
    const float* emb_w    = (const float*)d_in[1];
    const float* emb_b    = (const float*)d_in[2];
    const float* ln_w     = (const float*)d_in[3];
    const float* ln_b     = (const float*)d_in[4];
    const float* mix_w    = (const float*)d_in[5];
    const float* conv_w   = (const float*)d_in[6];
    const float* conv_b   = (const float*)d_in[7];
    const float* xproj_w  = (const float*)d_in[8];
    const float* dtproj_w = (const float*)d_in[9];
    const float* dtproj_b = (const float*)d_in[10];
    const float* A_log    = (const float*)d_in[11];
    const float* Dskip    = (const float*)d_in[12];
    const float* out_w    = (const float*)d_in[13];
    const float* normf_w  = (const float*)d_in[14];
    const float* normf_b  = (const float*)d_in[15];
    const float* ro1_w    = (const float*)d_in[16];
    const float* ro1_b    = (const float*)d_in[17];
    const float* ro2_w    = (const float*)d_in[18];
    const float* ro2_b    = (const float*)d_in[19];

    float *h, *xz, *xc, *dbl, *dt;
    cudaGetSymbolAddress((void**)&h,   g_h);
    cudaGetSymbolAddress((void**)&xz,  g_xz);
    cudaGetSymbolAddress((void**)&xc,  g_xc);
    cudaGetSymbolAddress((void**)&dbl, g_dbl);
    cudaGetSymbolAddress((void**)&dt,  g_dt);
    __half *xin, *xch, *ysh, *h2, *dblh, *mw, *xpw, *ow, *dtw, *r1w, *r2w;
    cudaGetSymbolAddress((void**)&xin,  g_xin);
    cudaGetSymbolAddress((void**)&xch,  g_xch);
    cudaGetSymbolAddress((void**)&ysh,  g_ysh);
    cudaGetSymbolAddress((void**)&h2,   g_h2);
    cudaGetSymbolAddress((void**)&dblh, g_dblh);
    cudaGetSymbolAddress((void**)&mw,   g_mixw);
    cudaGetSymbolAddress((void**)&xpw,  g_xpw);
    cudaGetSymbolAddress((void**)&ow,   g_ow);
    cudaGetSymbolAddress((void**)&dtw,  g_dtw);
    cudaGetSymbolAddress((void**)&r1w,  g_r1w);
    cudaGetSymbolAddress((void**)&r2w,  g_r2w);

    const int M = BL_ROWS;
    constexpr int SU128 = 2 * (128 * 144 + 128 * 144);  // 73728
    constexpr int SU64  = 2 * (128 * 144 + 64 * 144);   // 55296
    constexpr int S128  = 2 * (128 * 80 + 128 * 80);    // 40960
    cudaFuncSetAttribute(mma_gemmU<128, EPI_NONE>,  cudaFuncAttributeMaxDynamicSharedMemorySize, SU128);
    cudaFuncSetAttribute(mma_gemmU<128, EPI_RESID>, cudaFuncAttributeMaxDynamicSharedMemorySize, SU128);
    cudaFuncSetAttribute(mma_gemmU<128, EPI_GELU>,  cudaFuncAttributeMaxDynamicSharedMemorySize, SU128);
    cudaFuncSetAttribute(mma_gemmU<128, EPI_BIAS>,  cudaFuncAttributeMaxDynamicSharedMemorySize, SU128);
    cudaFuncSetAttribute(mma_gemmU<64,  EPI_NONE>,  cudaFuncAttributeMaxDynamicSharedMemorySize, SU64);
    cudaFuncSetAttribute(mma_gemm<128, EPI_SOFTPLUS>, cudaFuncAttributeMaxDynamicSharedMemorySize, S128);

    // launch order: my index 3 = layer-0 mix GEMM (= global index 5 for ncu)
    gemm_k<64, 64, 16, 4, 4><<<dim3(D_MODEL / 64, M / 64), 256>>>(
        y, P_DIM, emb_w, emb_b, h, M, D_MODEL, P_DIM);                        // 0
    cvt_kernel<<<(N_LAYER * 2 * D_INNER * D_MODEL) / 1024, 256>>>(mix_w, mw); // 1
    ln_kernel<<<M / 8, 256>>>(h, ln_w, ln_b, xin);                            // 2
    mma_gemmU<128, EPI_NONE><<<dim3(16, M / 128), 256, SU128>>>(              // 3
        xin, D_MODEL, mw, nullptr, nullptr, xz, nullptr, 2 * D_INNER, D_MODEL);
    cvt_kernel<<<(N_LAYER * 64 * D_INNER) / 1024, 256>>>(xproj_w, xpw);       // 4
    cvt_kernel<<<(N_LAYER * D_MODEL * D_INNER) / 1024, 256>>>(out_w, ow);     // 5
    cvt_kernel<<<(N_LAYER * D_INNER * DT_RANK) / 1024, 256>>>(dtproj_w, dtw); // 6
    cvt_kernel<<<(D_MODEL * D_MODEL) / 1024, 256>>>(ro1_w, r1w);              // 7
    cvt_kernel<<<(128 * D_MODEL) / 1024, 256>>>(ro2_w, r2w);                  // 8

    for (int i = 0; i < N_LAYER; i++) {
        const float* cw  = conv_w + (size_t)i * D_INNER * 4;
        const float* cb  = conv_b + (size_t)i * D_INNER;
        const float* dpb = dtproj_b + (size_t)i * D_INNER;
        const float* Al  = A_log + (size_t)i * D_INNER * N_STATE;
        const float* Dk  = Dskip + (size_t)i * D_INNER;

        if (i > 0) {
            ln_kernel<<<M / 8, 256>>>(h, ln_w + i * D_MODEL, ln_b + i * D_MODEL, xin);
            mma_gemmU<128, EPI_NONE><<<dim3(16, M / 128), 256, SU128>>>(
                xin, D_MODEL, mw + (size_t)i * 2 * D_INNER * D_MODEL,
                nullptr, nullptr, xz, nullptr, 2 * D_INNER, D_MODEL);
        }
        // conv + silu -> xc fp32 + fp16
        conv_silu_kernel<<<(M * D_INNER) / 256, 256>>>(xz, cw, cb, xc, xch);
        // dbl = xc @ xproj_w^T  (M x 64, K=1024) -> fp32 + fp16
        mma_gemmU<64, EPI_NONE><<<dim3(1, M / 128), 256, SU64>>>(
            xch, D_INNER, xpw + (size_t)i * 64 * D_INNER,
            nullptr, nullptr, dbl, dblh, 64, D_INNER);
        // dt = softplus(dbl_h[:, :32] @ dtproj_w^T + b)  (M x 1024, K=32)
        mma_gemm<128, EPI_SOFTPLUS><<<dim3(D_INNER / 128, M / 128), 256, S128>>>(
            dblh, 64, dtw + (size_t)i * D_INNER * DT_RANK,
            dpb, dt, nullptr, D_INNER, DT_RANK);
        // selective scan + gate -> ys fp16
        scan_kernel<<<512, 256>>>(dt, xc, dbl, xz, Al, Dk, ysh);
        // h = h + ys @ out_w^T  (M x 512, K=1024)
        mma_gemmU<128, EPI_RESID><<<dim3(4, M / 128), 256, SU128>>>(
            ysh, D_INNER, ow + (size_t)i * D_MODEL * D_INNER,
            nullptr, h, h, nullptr, D_MODEL, D_INNER);
    }

    // final LN -> fp16
    ln_kernel<<<M / 8, 256>>>(h, normf_w, normf_b, xin);
    // h2 = gelu(xin @ ro1_w^T + b) -> fp16
    mma_gemmU<128, EPI_GELU><<<dim3(4, M / 128), 256, SU128>>>(
        xin, D_MODEL, r1w, ro1_b, nullptr, nullptr, h2, D_MODEL, D_MODEL);
    // out = h2 @ ro2_w^T + b
    mma_gemmU<128, EPI_BIAS><<<dim3(1, M / 128), 256, SU128>>>(
        h2, D_MODEL, r2w, ro2_b, nullptr, (float*)d_out, nullptr, 128, D_MODEL);
}

// round 11
// speedup vs baseline: 4.1032x; 1.7517x over previous
#include <cuda_runtime.h>
#include <cuda_fp16.h>
#include <cstdint>

// ---------------- problem constants ----------------
#define B_SZ     8
#define L_SEQ    2048
#define P_DIM    32
#define D_MODEL  512
#define D_INNER  1024
#define N_STATE  16
#define DT_RANK  32
#define N_LAYER  4
#define BL_ROWS  (B_SZ * L_SEQ)          // 16384

// ---------------- scratch (static device globals) ----------------
__device__ __align__(16) float g_h [(size_t)BL_ROWS * D_MODEL];

__device__ __align__(16) __half g_xzh [(size_t)BL_ROWS * 2 * D_INNER];
__device__ __align__(16) __half g_xin [(size_t)BL_ROWS * D_MODEL];
__device__ __align__(16) __half g_xch [(size_t)BL_ROWS * D_INNER];
__device__ __align__(16) __half g_dth [(size_t)BL_ROWS * D_INNER];
__device__ __align__(16) __half g_ysh [(size_t)BL_ROWS * D_INNER];
__device__ __align__(16) __half g_h2  [(size_t)BL_ROWS * D_MODEL];
__device__ __align__(16) __half g_dblh[(size_t)BL_ROWS * 64];

__device__ __align__(16) __half g_mixw[(size_t)N_LAYER * 2 * D_INNER * D_MODEL];
__device__ __align__(16) __half g_xpw [(size_t)N_LAYER * 64 * D_INNER];
__device__ __align__(16) __half g_ow  [(size_t)N_LAYER * D_MODEL * D_INNER];
__device__ __align__(16) __half g_dtw [(size_t)N_LAYER * D_INNER * DT_RANK];
__device__ __align__(16) __half g_r1w [(size_t)D_MODEL * D_MODEL];
__device__ __align__(16) __half g_r2w [(size_t)128 * D_MODEL];
__device__ __align__(16) __half g_cwT [(size_t)N_LAYER * 4 * D_INNER];

// ---------------- PTX helpers ----------------
__device__ __forceinline__ uint32_t smem_u32(const void* p) {
    uint32_t a;
    asm("{ .reg .u64 t; cvta.to.shared.u64 t, %1; cvt.u32.u64 %0, t; }"
        : "=r"(a) : "l"(p));
    return a;
}
#define CP_ASYNC16(sa, ga)                                                   \
    asm volatile("cp.async.cg.shared.global [%0], [%1], 16;"                 \
                 :: "r"(sa), "l"(ga))
#define CP_COMMIT() asm volatile("cp.async.commit_group;" ::: "memory")
#define CP_WAIT1()  asm volatile("cp.async.wait_group 1;"  ::: "memory")
#define LDSM4(R, A)                                                          \
    asm volatile("ldmatrix.sync.aligned.m8n8.x4.shared.b16 {%0,%1,%2,%3},[%4];" \
                 : "=r"((R)[0]), "=r"((R)[1]), "=r"((R)[2]), "=r"((R)[3])    \
                 : "r"(A))
#define LDSM2(R, A)                                                          \
    asm volatile("ldmatrix.sync.aligned.m8n8.x2.shared.b16 {%0,%1},[%2];"    \
                 : "=r"((R)[0]), "=r"((R)[1]) : "r"(A))
#define MMA16816(C, A, B)                                                    \
    asm volatile("mma.sync.aligned.m16n8k16.row.col.f32.f16.f16.f32 "        \
                 "{%0,%1,%2,%3},{%4,%5,%6,%7},{%8,%9},{%0,%1,%2,%3};"        \
                 : "+f"((C)[0]), "+f"((C)[1]), "+f"((C)[2]), "+f"((C)[3])    \
                 : "r"((A)[0]), "r"((A)[1]), "r"((A)[2]), "r"((A)[3]),       \
                   "r"((B)[0]), "r"((B)[1]))

// ---------------- epilogue ids ----------------
#define EPI_NONE     0
#define EPI_BIAS     1
#define EPI_SOFTPLUS 2
#define EPI_GELU     3
#define EPI_RESID    4

// =======================================================================
// Unified HMMA GEMM: BM=128, BN in {64,128}, BK=64, 256 threads (8 warps
// 2x4), 2-stage cp.async, fp32 accum. Optional fp32 C / fp16 Ch outputs.
// =======================================================================
template<int BN, int EPI>
__global__ __launch_bounds__(256, 2) void mma_gemmU(
    const __half* __restrict__ A, int lda,
    const __half* __restrict__ B,
    const float* __restrict__ bias, const float* __restrict__ resid,
    float* __restrict__ C, __half* __restrict__ Ch, int N, int K)
{
    extern __shared__ char smem[];
    constexpr int SA     = 144;
    constexpr int A_TILE = 128 * SA;
    constexpr int B_TILE = BN * SA;
    constexpr int STAGE  = A_TILE + B_TILE;
    constexpr int WN     = BN / 4;
    constexpr int NT     = WN / 8;

    const int tid  = threadIdx.x;
    const int wid  = tid >> 5;
    const int lane = tid & 31;
    const int wm   = wid >> 2;
    const int wn   = wid & 3;
    const int bm   = blockIdx.y * 128;
    const int bn   = blockIdx.x * BN;
    const uint32_t sb = smem_u32(smem);

    float acc[4][NT][4];
#pragma unroll
    for (int mt = 0; mt < 4; mt++)
#pragma unroll
        for (int nt = 0; nt < NT; nt++)
#pragma unroll
            for (int q = 0; q < 4; q++) acc[mt][nt][q] = 0.f;

    auto load_stage = [&](int c, int s) {
        const int k0 = c * 64;
        const uint32_t st = sb + s * STAGE;
#pragma unroll
        for (int i = 0; i < 4; i++) {
            int id = tid + i * 256;
            int r = id >> 3, cc = id & 7;
            uint32_t so = st + r * SA + cc * 16;
            size_t g = (size_t)(bm + r) * lda + k0 + cc * 8;
            CP_ASYNC16(so, A + g);
        }
#pragma unroll
        for (int i = 0; i < BN / 32; i++) {
            int id = tid + i * 256;
            int r = id >> 3, cc = id & 7;
            uint32_t so = st + A_TILE + r * SA + cc * 16;
            size_t g = (size_t)(bn + r) * K + k0 + cc * 8;
            CP_ASYNC16(so, B + g);
        }
        CP_COMMIT();
    };

    const int chunks = K >> 6;
    load_stage(0, 0);
    for (int c = 0; c < chunks; c++) {
        if (c + 1 < chunks) load_stage(c + 1, (c + 1) & 1);
        else                CP_COMMIT();
        CP_WAIT1();
        __syncthreads();
        const uint32_t st = sb + (c & 1) * STAGE;
#pragma unroll
        for (int ks = 0; ks < 4; ks++) {
            uint32_t a4[4][4];
#pragma unroll
            for (int mt = 0; mt < 4; mt++) {
                uint32_t row = wm * 64 + mt * 16 + (lane & 15);
                uint32_t ad = st + row * SA + ks * 32 + ((lane >> 4) << 4);
                LDSM4(a4[mt], ad);
            }
#pragma unroll
            for (int nt = 0; nt < NT; nt++) {
                uint32_t rn = wn * WN + nt * 8 + (lane & 7);
                uint32_t bd = st + A_TILE + rn * SA + ks * 32 +
                              (((lane >> 3) & 1) << 4);
                uint32_t b2[2];
                LDSM2(b2, bd);
#pragma unroll
                for (int mt = 0; mt < 4; mt++)
                    MMA16816(acc[mt][nt], a4[mt], b2);
            }
        }
        __syncthreads();
    }

    // ---------------- epilogue ----------------
#pragma unroll
    for (int mt = 0; mt < 4; mt++) {
#pragma unroll
        for (int nt = 0; nt < NT; nt++) {
            int r0 = bm + wm * 64 + mt * 16 + (lane >> 2);
            int c0 = bn + wn * WN + nt * 8 + (lane & 3) * 2;
#pragma unroll
            for (int half_ = 0; half_ < 2; half_++) {
                int row = r0 + half_ * 8;
                float v0 = acc[mt][nt][half_ * 2];
                float v1 = acc[mt][nt][half_ * 2 + 1];
                size_t idx = (size_t)row * N + c0;
                if constexpr (EPI == EPI_BIAS || EPI == EPI_GELU) {
                    v0 += bias[c0];
                    v1 += bias[c0 + 1];
                }
                if constexpr (EPI == EPI_GELU) {
                    float u0 = 0.7978845608028654f * (v0 + 0.044715f * v0 * v0 * v0);
                    float u1 = 0.7978845608028654f * (v1 + 0.044715f * v1 * v1 * v1);
                    v0 = 0.5f * v0 * (1.f + tanhf(u0));
                    v1 = 0.5f * v1 * (1.f + tanhf(u1));
                    *(__half2*)(Ch + idx) =
                        __halves2half2(__float2half_rn(v0), __float2half_rn(v1));
                } else {
                    if constexpr (EPI == EPI_RESID) {
                        float2 rr = *(const float2*)(resid + idx);
                        v0 += rr.x; v1 += rr.y;
                    }
                    if (C)
                        *(float2*)(C + idx) = make_float2(v0, v1);
                    if (Ch)
                        *(__half2*)(Ch + idx) =
                            __halves2half2(__float2half_rn(v0), __float2half_rn(v1));
                }
            }
        }
    }
}

// =======================================================================
// Small HMMA GEMM: BM=128, BK=32, 256 threads, 2-stage (dtproj, K=32).
// =======================================================================
template<int BN, int EPI>
__global__ __launch_bounds__(256) void mma_gemm(
    const __half* __restrict__ A, int lda,
    const __half* __restrict__ B,
    const float* __restrict__ bias, float* __restrict__ C,
    __half* __restrict__ Ch, int N, int K)
{
    extern __shared__ char smem[];
    constexpr int SA     = 80;
    constexpr int A_TILE = 128 * SA;
    constexpr int B_TILE = BN * SA;
    constexpr int STAGE  = A_TILE + B_TILE;
    constexpr int WN     = BN / 4;
    constexpr int NT     = WN / 8;

    const int tid  = threadIdx.x;
    const int wid  = tid >> 5;
    const int lane = tid & 31;
    const int wm   = wid >> 2;
    const int wn   = wid & 3;
    const int bm   = blockIdx.y * 128;
    const int bn   = blockIdx.x * BN;
    const uint32_t sb = smem_u32(smem);

    float acc[4][NT][4];
#pragma unroll
    for (int mt = 0; mt < 4; mt++)
#pragma unroll
        for (int nt = 0; nt < NT; nt++)
#pragma unroll
            for (int q = 0; q < 4; q++) acc[mt][nt][q] = 0.f;

    auto load_stage = [&](int c, int s) {
        const int k0 = c * 32;
        const uint32_t st = sb + s * STAGE;
#pragma unroll
        for (int i = 0; i < 2; i++) {
            int id = tid + i * 256;
            int r = id >> 2, cc = id & 3;
            uint32_t so = st + r * SA + cc * 16;
            size_t g = (size_t)(bm + r) * lda + k0 + cc * 8;
            CP_ASYNC16(so, A + g);
        }
#pragma unroll
        for (int i = 0; i < BN / 64; i++) {
            int id = tid + i * 256;
            int r = id >> 2, cc = id & 3;
            uint32_t so = st + A_TILE + r * SA + cc * 16;
            size_t g = (size_t)(bn + r) * K + k0 + cc * 8;
            CP_ASYNC16(so, B + g);
        }
        CP_COMMIT();
    };

    const int chunks = K >> 5;
    load_stage(0, 0);
    for (int c = 0; c < chunks; c++) {
        if (c + 1 < chunks) load_stage(c + 1, (c + 1) & 1);
        else                CP_COMMIT();
        CP_WAIT1();
        __syncthreads();
        const uint32_t st = sb + (c & 1) * STAGE;
#pragma unroll
        for (int ks = 0; ks < 2; ks++) {
            uint32_t a4[4][4];
#pragma unroll
            for (int mt = 0; mt < 4; mt++) {
                uint32_t row = wm * 64 + mt * 16 + (lane & 15);
                uint32_t ad = st + row * SA + ks * 32 + ((lane >> 4) << 4);
                LDSM4(a4[mt], ad);
            }
#pragma unroll
            for (int nt = 0; nt < NT; nt++) {
                uint32_t rn = wn * WN + nt * 8 + (lane & 7);
                uint32_t bd = st + A_TILE + rn * SA + ks * 32 +
                              (((lane >> 3) & 1) << 4);
                uint32_t b2[2];
                LDSM2(b2, bd);
#pragma unroll
                for (int mt = 0; mt < 4; mt++)
                    MMA16816(acc[mt][nt], a4[mt], b2);
            }
        }
        __syncthreads();
    }

#pragma unroll
    for (int mt = 0; mt < 4; mt++) {
#pragma unroll
        for (int nt = 0; nt < NT; nt++) {
            int r0 = bm + wm * 64 + mt * 16 + (lane >> 2);
            int c0 = bn + wn * WN + nt * 8 + (lane & 3) * 2;
#pragma unroll
            for (int half_ = 0; half_ < 2; half_++) {
                int row = r0 + half_ * 8;
                float v0 = acc[mt][nt][half_ * 2];
                float v1 = acc[mt][nt][half_ * 2 + 1];
                size_t idx = (size_t)row * N + c0;
                if constexpr (EPI == EPI_BIAS || EPI == EPI_SOFTPLUS) {
                    v0 += bias[c0];
                    v1 += bias[c0 + 1];
                }
                if constexpr (EPI == EPI_SOFTPLUS) {
                    v0 = (v0 > 20.f) ? v0 : log1pf(__expf(v0));
                    v1 = (v1 > 20.f) ? v1 : log1pf(__expf(v1));
                }
                if (C)
                    *(float2*)(C + idx) = make_float2(v0, v1);
                if (Ch)
                    *(__half2*)(Ch + idx) =
                        __halves2half2(__float2half_rn(v0), __float2half_rn(v1));
            }
        }
    }
}

// ---------------- fp32 -> fp16 conversion ----------------
__global__ __launch_bounds__(256) void cvt_kernel(
    const float* __restrict__ x, __half* __restrict__ h)
{
    int i = blockIdx.x * 256 + threadIdx.x;
    float4 v = ((const float4*)x)[i];
    ((__half2*)h)[i * 2]     = __halves2half2(__float2half_rn(v.x), __float2half_rn(v.y));
    ((__half2*)h)[i * 2 + 1] = __halves2half2(__float2half_rn(v.z), __float2half_rn(v.w));
}

// conv weights: [L][D][4] fp32 -> [L][4][D] fp16
__global__ __launch_bounds__(256) void cvt_convw(
    const float* __restrict__ w, __half* __restrict__ o)
{
    int idx = blockIdx.x * 256 + threadIdx.x;          // 16384
    int l = idx >> 12, r = idx & 4095, k = r >> 10, d = r & 1023;
    o[idx] = __float2half_rn(w[l * 4096 + d * 4 + k]);
}

// ---------------- SIMT GEMM (embed only, K=32 fp32) ----------------
template<int BM, int BN, int BK, int TM, int TN>
__global__ __launch_bounds__(256) void gemm_k(
    const float* __restrict__ A, int lda,
    const float* __restrict__ W,
    const float* __restrict__ bias,
    float* __restrict__ C,
    int M, int N, int K)
{
    __shared__ float As[BK][BM];
    __shared__ float Ws[BK][BN];
    const int tid = threadIdx.x;
    const int bm = blockIdx.y * BM;
    const int bn = blockIdx.x * BN;
    constexpr int TX = BN / TN;
    const int tx = tid % TX;
    const int ty = tid / TX;

    float acc[TM][TN];
#pragma unroll
    for (int i = 0; i < TM; i++)
#pragma unroll
        for (int j = 0; j < TN; j++) acc[i][j] = 0.f;

    for (int k0 = 0; k0 < K; k0 += BK) {
#pragma unroll
        for (int i = tid; i < BM * BK; i += 256) {
            int r = i / BK, c = i % BK;
            As[c][r] = A[(size_t)(bm + r) * lda + k0 + c];
        }
#pragma unroll
        for (int i = tid; i < BN * BK; i += 256) {
            int r = i / BK, c = i % BK;
            Ws[c][r] = W[(size_t)(bn + r) * K + k0 + c];
        }
        __syncthreads();
#pragma unroll
        for (int kk = 0; kk < BK; kk++) {
            float ra[TM], rw[TN];
#pragma unroll
            for (int i = 0; i < TM; i++) ra[i] = As[kk][ty * TM + i];
#pragma unroll
            for (int j = 0; j < TN; j++) rw[j] = Ws[kk][tx * TN + j];
#pragma unroll
            for (int i = 0; i < TM; i++)
#pragma unroll
                for (int j = 0; j < TN; j++)
                    acc[i][j] = fmaf(ra[i], rw[j], acc[i][j]);
        }
        __syncthreads();
    }
#pragma unroll
    for (int i = 0; i < TM; i++) {
        int row = bm + ty * TM + i;
#pragma unroll
        for (int j = 0; j < TN; j++) {
            int col = bn + tx * TN + j;
            C[(size_t)row * N + col] = acc[i][j] + bias[col];
        }
    }
}

// ---------------- layernorm -> fp16, one warp per row ----------------
__global__ __launch_bounds__(256) void ln_kernel(
    const float* __restrict__ x, const float* __restrict__ w,
    const float* __restrict__ bb, __half* __restrict__ oh)
{
    int row  = blockIdx.x * 8 + (threadIdx.x >> 5);
    int lane = threadIdx.x & 31;
    const float* xr = x + (size_t)row * D_MODEL + lane;
    float v[16];
    float s = 0.f, s2 = 0.f;
#pragma unroll
    for (int i = 0; i < 16; i++) {
        v[i] = xr[i * 32];
        s += v[i];
        s2 = fmaf(v[i], v[i], s2);
    }
#pragma unroll
    for (int k = 16; k; k >>= 1) {
        s  += __shfl_xor_sync(0xffffffffu, s,  k);
        s2 += __shfl_xor_sync(0xffffffffu, s2, k);
    }
    float mu  = s * (1.f / 512.f);
    float var = fmaf(s2, 1.f / 512.f, -mu * mu);
    float rs  = rsqrtf(var + 1e-5f);
    size_t ob = (size_t)row * D_MODEL + lane;
#pragma unroll
    for (int i = 0; i < 16; i++) {
        float o = (v[i] - mu) * rs * w[lane + i * 32] + bb[lane + i * 32];
        oh[ob + i * 32] = __float2half_rn(o);
    }
}

// ---------------- causal depthwise conv (k=4) + SiLU, half2 -------------
__global__ __launch_bounds__(256) void conv_silu_kernel(
    const __half* __restrict__ xz, const __half* __restrict__ cwT,
    const float* __restrict__ cb, __half* __restrict__ xch)
{
    int idx = blockIdx.x * 256 + threadIdx.x;          // over BL_ROWS*512
    int d2 = idx & 511;
    int bl = idx >> 9;
    int t  = bl & (L_SEQ - 1);
    const __half2* xp = (const __half2*)xz + (size_t)bl * 1024 + d2;
    const __half2* wp = (const __half2*)cwT + d2;      // [k][d2] stride 512
    float2 cbv = *(const float2*)(cb + d2 * 2);
    float a0 = cbv.x, a1 = cbv.y;
    {
        float2 w = __half22float2(__ldg(wp + 3 * 512));
        float2 x = __half22float2(__ldg(xp));
        a0 = fmaf(w.x, x.x, a0); a1 = fmaf(w.y, x.y, a1);
    }
    if (t >= 1) {
        float2 w = __half22float2(__ldg(wp + 2 * 512));
        float2 x = __half22float2(__ldg(xp - 1024));
        a0 = fmaf(w.x, x.x, a0); a1 = fmaf(w.y, x.y, a1);
    }
    if (t >= 2) {
        float2 w = __half22float2(__ldg(wp + 512));
        float2 x = __half22float2(__ldg(xp - 2048));
        a0 = fmaf(w.x, x.x, a0); a1 = fmaf(w.y, x.y, a1);
    }
    if (t >= 3) {
        float2 w = __half22float2(__ldg(wp));
        float2 x = __half22float2(__ldg(xp - 3072));
        a0 = fmaf(w.x, x.x, a0); a1 = fmaf(w.y, x.y, a1);
    }
    float s0 = __fdividef(a0, 1.f + __expf(-a0));
    float s1 = __fdividef(a1, 1.f + __expf(-a1));
    ((__half2*)xch)[idx] = __halves2half2(__float2half_rn(s0), __float2half_rn(s1));
}

// ---------------- selective scan (all-fp16 inputs) -> ys fp16 -----------
__global__ __launch_bounds__(128) void scan_kernel(
    const __half* __restrict__ dt_g, const __half* __restrict__ xc_g,
    const __half* __restrict__ dbl_g, const __half* __restrict__ xz_g,
    const float* __restrict__ A_log, const float* __restrict__ Dsk,
    __half* __restrict__ ysh)
{
    const int gw   = (blockIdx.x * 128 + threadIdx.x) >> 5;
    const int lane = threadIdx.x & 31;
    const int b    = gw >> 9;
    const int d0   = (gw & 511) << 1;
    const int hi   = lane >> 4;
    const int n    = lane & 15;
    const int d    = d0 + hi;

    const float An = -__expf(__ldg(A_log + d * N_STATE + n));
    const float Dd = __ldg(Dsk + d);
    const size_t base = (size_t)b * L_SEQ;

    const __half2* dtp = (const __half2*)(dt_g + base * D_INNER + d0);
    const __half2* xcp = (const __half2*)(xc_g + base * D_INNER + d0);
    const __half2* zp  = (const __half2*)(xz_g + base * 2048 + D_INNER + d0);
    const __half*  bcp = dbl_g + base * 64 + 32 + lane;
    __half* yph = ysh + base * D_INNER + d;

    float h = 0.f;
    __half2 adt[4], axc[4], az[4]; __half abc[4];
    __half2 bdt[4], bxc[4], bz[4]; __half bbc[4];

#define LOADQ(T0, DT, XC, Z, BC)                                          \
    {                                                                     \
        _Pragma("unroll")                                                 \
        for (int j = 0; j < 4; j++) {                                     \
            int tt = (T0) + j;                                            \
            DT[j] = __ldg(dtp + tt * (D_INNER / 2));                      \
            XC[j] = __ldg(xcp + tt * (D_INNER / 2));                      \
            Z[j]  = __ldg(zp  + tt * D_INNER);                            \
            BC[j] = __ldg(bcp + tt * 64);                                 \
        }                                                                 \
    }
#define STEP(T, DTv, XCv, Zv, BCv)                                        \
    {                                                                     \
        float dtv = hi ? __high2float(DTv) : __low2float(DTv);            \
        float xv  = hi ? __high2float(XCv) : __low2float(XCv);            \
        float bcf = __half2float(BCv);                                    \
        float bn = __shfl_sync(0xffffffffu, bcf, n);                      \
        float cn = __shfl_sync(0xffffffffu, bcf, n + 16);                 \
        float dA = __expf(dtv * An);                                      \
        h = fmaf(dA, h, dtv * xv * bn);                                   \
        float p = h * cn;                                                 \
        p += __shfl_xor_sync(0xffffffffu, p, 1);                          \
        p += __shfl_xor_sync(0xffffffffu, p, 2);                          \
        p += __shfl_xor_sync(0xffffffffu, p, 4);                          \
        p += __shfl_xor_sync(0xffffffffu, p, 8);                          \
        if (n == 0) {                                                     \
            float zv = hi ? __high2float(Zv) : __low2float(Zv);           \
            float yv = fmaf(xv, Dd, p);                                   \
            float o  = yv * __fdividef(zv, 1.f + __expf(-zv));            \
            yph[(T) * D_INNER] = __float2half_rn(o);                      \
        }                                                                 \
    }

    LOADQ(0, adt, axc, az, abc);
    for (int t0 = 0; t0 < L_SEQ; t0 += 8) {
        LOADQ(t0 + 4, bdt, bxc, bz, bbc);
#pragma unroll
        for (int j = 0; j < 4; j++) STEP(t0 + j, adt[j], axc[j], az[j], abc[j]);
        if (t0 + 8 < L_SEQ) LOADQ(t0 + 8, adt, axc, az, abc);
#pragma unroll
        for (int j = 0; j < 4; j++) STEP(t0 + 4 + j, bdt[j], bxc[j], bz[j], bbc[j]);
    }
#undef LOADQ
#undef STEP
}

// ---------------- host orchestration ----------------
extern "C" void kernel_launch(void* const* d_in, const int* in_sizes, int n_in,
                              void* d_out, int out_size)
{
    const float* y        = (const float*)d_in[0];
    const float* emb_w    = (const float*)d_in[1];
    const float* emb_b    = (const float*)d_in[2];
    const float* ln_w     = (const float*)d_in[3];
    const float* ln_b     = (const float*)d_in[4];
    const float* mix_w    = (const float*)d_in[5];
    const float* conv_w   = (const float*)d_in[6];
    const float* conv_b   = (const float*)d_in[7];
    const float* xproj_w  = (const float*)d_in[8];
    const float* dtproj_w = (const float*)d_in[9];
    const float* dtproj_b = (const float*)d_in[10];
    const float* A_log    = (const float*)d_in[11];
    const float* Dskip    = (const float*)d_in[12];
    const float* out_w    = (const float*)d_in[13];
    const float* normf_w  = (const float*)d_in[14];
    const float* normf_b  = (const float*)d_in[15];
    const float* ro1_w    = (const float*)d_in[16];
    const float* ro1_b    = (const float*)d_in[17];
    const float* ro2_w    = (const float*)d_in[18];
    const float* ro2_b    = (const float*)d_in[19];

    float* h;
    cudaGetSymbolAddress((void**)&h, g_h);
    __half *xzh, *xin, *xch, *dth, *ysh, *h2, *dblh;
    __half *mw, *xpw, *ow, *dtw, *r1w, *r2w, *cwT;
    cudaGetSymbolAddress((void**)&xzh,  g_xzh);
    cudaGetSymbolAddress((void**)&xin,  g_xin);
    cudaGetSymbolAddress((void**)&xch,  g_xch);
    cudaGetSymbolAddress((void**)&dth,  g_dth);
    cudaGetSymbolAddress((void**)&ysh,  g_ysh);
    cudaGetSymbolAddress((void**)&h2,   g_h2);
    cudaGetSymbolAddress((void**)&dblh, g_dblh);
    cudaGetSymbolAddress((void**)&mw,   g_mixw);
    cudaGetSymbolAddress((void**)&xpw,  g_xpw);
    cudaGetSymbolAddress((void**)&ow,   g_ow);
    cudaGetSymbolAddress((void**)&dtw,  g_dtw);
    cudaGetSymbolAddress((void**)&r1w,  g_r1w);
    cudaGetSymbolAddress((void**)&r2w,  g_r2w);
    cudaGetSymbolAddress((void**)&cwT,  g_cwT);

    const int M = BL_ROWS;
    constexpr int SU128 = 2 * (128 * 144 + 128 * 144);  // 73728
    constexpr int SU64  = 2 * (128 * 144 + 64 * 144);   // 55296
    constexpr int S128  = 2 * (128 * 80 + 128 * 80);    // 40960
    cudaFuncSetAttribute(mma_gemmU<128, EPI_NONE>,  cudaFuncAttributeMaxDynamicSharedMemorySize, SU128);
    cudaFuncSetAttribute(mma_gemmU<128, EPI_RESID>, cudaFuncAttributeMaxDynamicSharedMemorySize, SU128);
    cudaFuncSetAttribute(mma_gemmU<128, EPI_GELU>,  cudaFuncAttributeMaxDynamicSharedMemorySize, SU128);
    cudaFuncSetAttribute(mma_gemmU<128, EPI_BIAS>,  cudaFuncAttributeMaxDynamicSharedMemorySize, SU128);
    cudaFuncSetAttribute(mma_gemmU<64,  EPI_NONE>,  cudaFuncAttributeMaxDynamicSharedMemorySize, SU64);
    cudaFuncSetAttribute(mma_gemm<128, EPI_SOFTPLUS>, cudaFuncAttributeMaxDynamicSharedMemorySize, S128);

    // launch order: my index 3 = layer-0 mix GEMM (profiled at global idx 5)
    gemm_k<64, 64, 16, 4, 4><<<dim3(D_MODEL / 64, M / 64), 256>>>(
        y, P_DIM, emb_w, emb_b, h, M, D_MODEL, P_DIM);                        // 0
    cvt_kernel<<<(N_LAYER * 2 * D_INNER * D_MODEL) / 1024, 256>>>(mix_w, mw); // 1
    ln_kernel<<<M / 8, 256>>>(h, ln_w, ln_b, xin);                            // 2
    mma_gemmU<128, EPI_NONE><<<dim3(16, M / 128), 256, SU128>>>(              // 3
        xin, D_MODEL, mw, nullptr, nullptr, nullptr, xzh, 2 * D_INNER, D_MODEL);
    cvt_kernel<<<(N_LAYER * 64 * D_INNER) / 1024, 256>>>(xproj_w, xpw);       // 4
    cvt_kernel<<<(N_LAYER * D_MODEL * D_INNER) / 1024, 256>>>(out_w, ow);     // 5
    cvt_kernel<<<(N_LAYER * D_INNER * DT_RANK) / 1024, 256>>>(dtproj_w, dtw); // 6
    cvt_kernel<<<(D_MODEL * D_MODEL) / 1024, 256>>>(ro1_w, r1w);              // 7
    cvt_kernel<<<(128 * D_MODEL) / 1024, 256>>>(ro2_w, r2w);                  // 8
    cvt_convw<<<(N_LAYER * 4 * D_INNER) / 256, 256>>>(conv_w, cwT);           // 9

    for (int i = 0; i < N_LAYER; i++) {
        const float* cb  = conv_b + (size_t)i * D_INNER;
        const float* dpb = dtproj_b + (size_t)i * D_INNER;
        const float* Al  = A_log + (size_t)i * D_INNER * N_STATE;
        const float* Dk  = Dskip + (size_t)i * D_INNER;

        if (i > 0) {
            ln_kernel<<<M / 8, 256>>>(h, ln_w + i * D_MODEL, ln_b + i * D_MODEL, xin);
            mma_gemmU<128, EPI_NONE><<<dim3(16, M / 128), 256, SU128>>>(
                xin, D_MODEL, mw + (size_t)i * 2 * D_INNER * D_MODEL,
                nullptr, nullptr, nullptr, xzh, 2 * D_INNER, D_MODEL);
        }
        // conv + silu -> xc fp16
        conv_silu_kernel<<<(M * 512) / 256, 256>>>(
            xzh, cwT + (size_t)i * 4 * D_INNER, cb, xch);
        // dbl = xc @ xproj_w^T  (M x 64, K=1024) -> fp16
        mma_gemmU<64, EPI_NONE><<<dim3(1, M / 128), 256, SU64>>>(
            xch, D_INNER, xpw + (size_t)i * 64 * D_INNER,
            nullptr, nullptr, nullptr, dblh, 64, D_INNER);
        // dt = softplus(dblh[:, :32] @ dtproj_w^T + b) -> fp16
        mma_gemm<128, EPI_SOFTPLUS><<<dim3(D_INNER / 128, M / 128), 256, S128>>>(
            dblh, 64, dtw + (size_t)i * D_INNER * DT_RANK,
            dpb, nullptr, dth, D_INNER, DT_RANK);
        // selective scan + gate -> ys fp16
        scan_kernel<<<1024, 128>>>(dth, xch, dblh, xzh, Al, Dk, ysh);
        // h = h + ys @ out_w^T  (M x 512, K=1024)
        mma_gemmU<128, EPI_RESID><<<dim3(4, M / 128), 256, SU128>>>(
            ysh, D_INNER, ow + (size_t)i * D_MODEL * D_INNER,
            nullptr, h, h, nullptr, D_MODEL, D_INNER);
    }

    // final LN -> fp16
    ln_kernel<<<M / 8, 256>>>(h, normf_w, normf_b, xin);
    // h2 = gelu(xin @ ro1_w^T + b) -> fp16
    mma_gemmU<128, EPI_GELU><<<dim3(4, M / 128), 256, SU128>>>(
        xin, D_MODEL, r1w, ro1_b, nullptr, nullptr, h2, D_MODEL, D_MODEL);
    // out = h2 @ ro2_w^T + b
    mma_gemmU<128, EPI_BIAS><<<dim3(1, M / 128), 256, SU128>>>(
        h2, D_MODEL, r2w, ro2_b, nullptr, (float*)d_out, nullptr, 128, D_MODEL);
}

// round 12
// speedup vs baseline: 5.6370x; 1.3738x over previous
#include <cuda_runtime.h>
#include <cuda_fp16.h>
#include <cstdint>

// ---------------- problem constants ----------------
#define B_SZ     8
#define L_SEQ    2048
#define P_DIM    32
#define D_MODEL  512
#define D_INNER  1024
#define N_STATE  16
#define DT_RANK  32
#define N_LAYER  4
#define BL_ROWS  (B_SZ * L_SEQ)          // 16384

// ---------------- scratch (static device globals) ----------------
__device__ __align__(16) float g_h [(size_t)BL_ROWS * D_MODEL];

__device__ __align__(16) __half g_xzh [(size_t)BL_ROWS * 2 * D_INNER];
__device__ __align__(16) __half g_xin [(size_t)BL_ROWS * D_MODEL];
__device__ __align__(16) __half g_xch [(size_t)BL_ROWS * D_INNER];
__device__ __align__(16) __half g_dth [(size_t)BL_ROWS * D_INNER];
__device__ __align__(16) __half g_ysh [(size_t)BL_ROWS * D_INNER];
__device__ __align__(16) __half g_h2  [(size_t)BL_ROWS * D_MODEL];
__device__ __align__(16) __half g_dblh[(size_t)BL_ROWS * 64];

__device__ __align__(16) __half g_mixw[(size_t)N_LAYER * 2 * D_INNER * D_MODEL];
__device__ __align__(16) __half g_xpw [(size_t)N_LAYER * 64 * D_INNER];
__device__ __align__(16) __half g_ow  [(size_t)N_LAYER * D_MODEL * D_INNER];
__device__ __align__(16) __half g_dtw [(size_t)N_LAYER * D_INNER * DT_RANK];
__device__ __align__(16) __half g_r1w [(size_t)D_MODEL * D_MODEL];
__device__ __align__(16) __half g_r2w [(size_t)128 * D_MODEL];
__device__ __align__(16) __half g_cwT [(size_t)N_LAYER * 4 * D_INNER];

// ---------------- PTX helpers ----------------
__device__ __forceinline__ uint32_t smem_u32(const void* p) {
    uint32_t a;
    asm("{ .reg .u64 t; cvta.to.shared.u64 t, %1; cvt.u32.u64 %0, t; }"
        : "=r"(a) : "l"(p));
    return a;
}
#define CP_ASYNC16(sa, ga)                                                   \
    asm volatile("cp.async.cg.shared.global [%0], [%1], 16;"                 \
                 :: "r"(sa), "l"(ga))
#define CP_COMMIT() asm volatile("cp.async.commit_group;" ::: "memory")
#define CP_WAIT1()  asm volatile("cp.async.wait_group 1;"  ::: "memory")
#define LDSM4(R, A)                                                          \
    asm volatile("ldmatrix.sync.aligned.m8n8.x4.shared.b16 {%0,%1,%2,%3},[%4];" \
                 : "=r"((R)[0]), "=r"((R)[1]), "=r"((R)[2]), "=r"((R)[3])    \
                 : "r"(A))
#define LDSM2(R, A)                                                          \
    asm volatile("ldmatrix.sync.aligned.m8n8.x2.shared.b16 {%0,%1},[%2];"    \
                 : "=r"((R)[0]), "=r"((R)[1]) : "r"(A))
#define MMA16816(C, A, B)                                                    \
    asm volatile("mma.sync.aligned.m16n8k16.row.col.f32.f16.f16.f32 "        \
                 "{%0,%1,%2,%3},{%4,%5,%6,%7},{%8,%9},{%0,%1,%2,%3};"        \
                 : "+f"((C)[0]), "+f"((C)[1]), "+f"((C)[2]), "+f"((C)[3])    \
                 : "r"((A)[0]), "r"((A)[1]), "r"((A)[2]), "r"((A)[3]),       \
                   "r"((B)[0]), "r"((B)[1]))

// ---------------- epilogue ids ----------------
#define EPI_NONE     0
#define EPI_BIAS     1
#define EPI_SOFTPLUS 2
#define EPI_GELU     3
#define EPI_RESID    4

// =======================================================================
// Unified HMMA GEMM: BM=128, BN in {64,128}, BK=64, 256 threads (8 warps
// 2x4), 2-stage cp.async, fp32 accum. Optional fp32 C / fp16 Ch outputs.
// =======================================================================
template<int BN, int EPI>
__global__ __launch_bounds__(256, 2) void mma_gemmU(
    const __half* __restrict__ A, int lda,
    const __half* __restrict__ B,
    const float* __restrict__ bias, const float* __restrict__ resid,
    float* __restrict__ C, __half* __restrict__ Ch, int N, int K)
{
    extern __shared__ char smem[];
    constexpr int SA     = 144;
    constexpr int A_TILE = 128 * SA;
    constexpr int B_TILE = BN * SA;
    constexpr int STAGE  = A_TILE + B_TILE;
    constexpr int WN     = BN / 4;
    constexpr int NT     = WN / 8;

    const int tid  = threadIdx.x;
    const int wid  = tid >> 5;
    const int lane = tid & 31;
    const int wm   = wid >> 2;
    const int wn   = wid & 3;
    const int bm   = blockIdx.y * 128;
    const int bn   = blockIdx.x * BN;
    const uint32_t sb = smem_u32(smem);

    float acc[4][NT][4];
#pragma unroll
    for (int mt = 0; mt < 4; mt++)
#pragma unroll
        for (int nt = 0; nt < NT; nt++)
#pragma unroll
            for (int q = 0; q < 4; q++) acc[mt][nt][q] = 0.f;

    auto load_stage = [&](int c, int s) {
        const int k0 = c * 64;
        const uint32_t st = sb + s * STAGE;
#pragma unroll
        for (int i = 0; i < 4; i++) {
            int id = tid + i * 256;
            int r = id >> 3, cc = id & 7;
            uint32_t so = st + r * SA + cc * 16;
            size_t g = (size_t)(bm + r) * lda + k0 + cc * 8;
            CP_ASYNC16(so, A + g);
        }
#pragma unroll
        for (int i = 0; i < BN / 32; i++) {
            int id = tid + i * 256;
            int r = id >> 3, cc = id & 7;
            uint32_t so = st + A_TILE + r * SA + cc * 16;
            size_t g = (size_t)(bn + r) * K + k0 + cc * 8;
            CP_ASYNC16(so, B + g);
        }
        CP_COMMIT();
    };

    const int chunks = K >> 6;
    load_stage(0, 0);
    for (int c = 0; c < chunks; c++) {
        if (c + 1 < chunks) load_stage(c + 1, (c + 1) & 1);
        else                CP_COMMIT();
        CP_WAIT1();
        __syncthreads();
        const uint32_t st = sb + (c & 1) * STAGE;
#pragma unroll
        for (int ks = 0; ks < 4; ks++) {
            uint32_t a4[4][4];
#pragma unroll
            for (int mt = 0; mt < 4; mt++) {
                uint32_t row = wm * 64 + mt * 16 + (lane & 15);
                uint32_t ad = st + row * SA + ks * 32 + ((lane >> 4) << 4);
                LDSM4(a4[mt], ad);
            }
#pragma unroll
            for (int nt = 0; nt < NT; nt++) {
                uint32_t rn = wn * WN + nt * 8 + (lane & 7);
                uint32_t bd = st + A_TILE + rn * SA + ks * 32 +
                              (((lane >> 3) & 1) << 4);
                uint32_t b2[2];
                LDSM2(b2, bd);
#pragma unroll
                for (int mt = 0; mt < 4; mt++)
                    MMA16816(acc[mt][nt], a4[mt], b2);
            }
        }
        __syncthreads();
    }

    // ---------------- epilogue ----------------
#pragma unroll
    for (int mt = 0; mt < 4; mt++) {
#pragma unroll
        for (int nt = 0; nt < NT; nt++) {
            int r0 = bm + wm * 64 + mt * 16 + (lane >> 2);
            int c0 = bn + wn * WN + nt * 8 + (lane & 3) * 2;
#pragma unroll
            for (int half_ = 0; half_ < 2; half_++) {
                int row = r0 + half_ * 8;
                float v0 = acc[mt][nt][half_ * 2];
                float v1 = acc[mt][nt][half_ * 2 + 1];
                size_t idx = (size_t)row * N + c0;
                if constexpr (EPI == EPI_BIAS || EPI == EPI_GELU) {
                    v0 += bias[c0];
                    v1 += bias[c0 + 1];
                }
                if constexpr (EPI == EPI_GELU) {
                    float u0 = 0.7978845608028654f * (v0 + 0.044715f * v0 * v0 * v0);
                    float u1 = 0.7978845608028654f * (v1 + 0.044715f * v1 * v1 * v1);
                    v0 = 0.5f * v0 * (1.f + tanhf(u0));
                    v1 = 0.5f * v1 * (1.f + tanhf(u1));
                    *(__half2*)(Ch + idx) =
                        __halves2half2(__float2half_rn(v0), __float2half_rn(v1));
                } else {
                    if constexpr (EPI == EPI_RESID) {
                        float2 rr = *(const float2*)(resid + idx);
                        v0 += rr.x; v1 += rr.y;
                    }
                    if (C)
                        *(float2*)(C + idx) = make_float2(v0, v1);
                    if (Ch)
                        *(__half2*)(Ch + idx) =
                            __halves2half2(__float2half_rn(v0), __float2half_rn(v1));
                }
            }
        }
    }
}

// =======================================================================
// Small HMMA GEMM: BM=128, BK=32, 256 threads, 2-stage (dtproj, K=32).
// =======================================================================
template<int BN, int EPI>
__global__ __launch_bounds__(256) void mma_gemm(
    const __half* __restrict__ A, int lda,
    const __half* __restrict__ B,
    const float* __restrict__ bias, float* __restrict__ C,
    __half* __restrict__ Ch, int N, int K)
{
    extern __shared__ char smem[];
    constexpr int SA     = 80;
    constexpr int A_TILE = 128 * SA;
    constexpr int B_TILE = BN * SA;
    constexpr int STAGE  = A_TILE + B_TILE;
    constexpr int WN     = BN / 4;
    constexpr int NT     = WN / 8;

    const int tid  = threadIdx.x;
    const int wid  = tid >> 5;
    const int lane = tid & 31;
    const int wm   = wid >> 2;
    const int wn   = wid & 3;
    const int bm   = blockIdx.y * 128;
    const int bn   = blockIdx.x * BN;
    const uint32_t sb = smem_u32(smem);

    float acc[4][NT][4];
#pragma unroll
    for (int mt = 0; mt < 4; mt++)
#pragma unroll
        for (int nt = 0; nt < NT; nt++)
#pragma unroll
            for (int q = 0; q < 4; q++) acc[mt][nt][q] = 0.f;

    auto load_stage = [&](int c, int s) {
        const int k0 = c * 32;
        const uint32_t st = sb + s * STAGE;
#pragma unroll
        for (int i = 0; i < 2; i++) {
            int id = tid + i * 256;
            int r = id >> 2, cc = id & 3;
            uint32_t so = st + r * SA + cc * 16;
            size_t g = (size_t)(bm + r) * lda + k0 + cc * 8;
            CP_ASYNC16(so, A + g);
        }
#pragma unroll
        for (int i = 0; i < BN / 64; i++) {
            int id = tid + i * 256;
            int r = id >> 2, cc = id & 3;
            uint32_t so = st + A_TILE + r * SA + cc * 16;
            size_t g = (size_t)(bn + r) * K + k0 + cc * 8;
            CP_ASYNC16(so, B + g);
        }
        CP_COMMIT();
    };

    const int chunks = K >> 5;
    load_stage(0, 0);
    for (int c = 0; c < chunks; c++) {
        if (c + 1 < chunks) load_stage(c + 1, (c + 1) & 1);
        else                CP_COMMIT();
        CP_WAIT1();
        __syncthreads();
        const uint32_t st = sb + (c & 1) * STAGE;
#pragma unroll
        for (int ks = 0; ks < 2; ks++) {
            uint32_t a4[4][4];
#pragma unroll
            for (int mt = 0; mt < 4; mt++) {
                uint32_t row = wm * 64 + mt * 16 + (lane & 15);
                uint32_t ad = st + row * SA + ks * 32 + ((lane >> 4) << 4);
                LDSM4(a4[mt], ad);
            }
#pragma unroll
            for (int nt = 0; nt < NT; nt++) {
                uint32_t rn = wn * WN + nt * 8 + (lane & 7);
                uint32_t bd = st + A_TILE + rn * SA + ks * 32 +
                              (((lane >> 3) & 1) << 4);
                uint32_t b2[2];
                LDSM2(b2, bd);
#pragma unroll
                for (int mt = 0; mt < 4; mt++)
                    MMA16816(acc[mt][nt], a4[mt], b2);
            }
        }
        __syncthreads();
    }

#pragma unroll
    for (int mt = 0; mt < 4; mt++) {
#pragma unroll
        for (int nt = 0; nt < NT; nt++) {
            int r0 = bm + wm * 64 + mt * 16 + (lane >> 2);
            int c0 = bn + wn * WN + nt * 8 + (lane & 3) * 2;
#pragma unroll
            for (int half_ = 0; half_ < 2; half_++) {
                int row = r0 + half_ * 8;
                float v0 = acc[mt][nt][half_ * 2];
                float v1 = acc[mt][nt][half_ * 2 + 1];
                size_t idx = (size_t)row * N + c0;
                if constexpr (EPI == EPI_BIAS || EPI == EPI_SOFTPLUS) {
                    v0 += bias[c0];
                    v1 += bias[c0 + 1];
                }
                if constexpr (EPI == EPI_SOFTPLUS) {
                    v0 = (v0 > 20.f) ? v0 : log1pf(__expf(v0));
                    v1 = (v1 > 20.f) ? v1 : log1pf(__expf(v1));
                }
                if (C)
                    *(float2*)(C + idx) = make_float2(v0, v1);
                if (Ch)
                    *(__half2*)(Ch + idx) =
                        __halves2half2(__float2half_rn(v0), __float2half_rn(v1));
            }
        }
    }
}

// ---------------- fp32 -> fp16 conversion ----------------
__global__ __launch_bounds__(256) void cvt_kernel(
    const float* __restrict__ x, __half* __restrict__ h)
{
    int i = blockIdx.x * 256 + threadIdx.x;
    float4 v = ((const float4*)x)[i];
    ((__half2*)h)[i * 2]     = __halves2half2(__float2half_rn(v.x), __float2half_rn(v.y));
    ((__half2*)h)[i * 2 + 1] = __halves2half2(__float2half_rn(v.z), __float2half_rn(v.w));
}

// conv weights: [L][D][4] fp32 -> [L][4][D] fp16
__global__ __launch_bounds__(256) void cvt_convw(
    const float* __restrict__ w, __half* __restrict__ o)
{
    int idx = blockIdx.x * 256 + threadIdx.x;          // 16384
    int l = idx >> 12, r = idx & 4095, k = r >> 10, d = r & 1023;
    o[idx] = __float2half_rn(w[l * 4096 + d * 4 + k]);
}

// ---------------- SIMT GEMM (embed only, K=32 fp32) ----------------
template<int BM, int BN, int BK, int TM, int TN>
__global__ __launch_bounds__(256) void gemm_k(
    const float* __restrict__ A, int lda,
    const float* __restrict__ W,
    const float* __restrict__ bias,
    float* __restrict__ C,
    int M, int N, int K)
{
    __shared__ float As[BK][BM];
    __shared__ float Ws[BK][BN];
    const int tid = threadIdx.x;
    const int bm = blockIdx.y * BM;
    const int bn = blockIdx.x * BN;
    constexpr int TX = BN / TN;
    const int tx = tid % TX;
    const int ty = tid / TX;

    float acc[TM][TN];
#pragma unroll
    for (int i = 0; i < TM; i++)
#pragma unroll
        for (int j = 0; j < TN; j++) acc[i][j] = 0.f;

    for (int k0 = 0; k0 < K; k0 += BK) {
#pragma unroll
        for (int i = tid; i < BM * BK; i += 256) {
            int r = i / BK, c = i % BK;
            As[c][r] = A[(size_t)(bm + r) * lda + k0 + c];
        }
#pragma unroll
        for (int i = tid; i < BN * BK; i += 256) {
            int r = i / BK, c = i % BK;
            Ws[c][r] = W[(size_t)(bn + r) * K + k0 + c];
        }
        __syncthreads();
#pragma unroll
        for (int kk = 0; kk < BK; kk++) {
            float ra[TM], rw[TN];
#pragma unroll
            for (int i = 0; i < TM; i++) ra[i] = As[kk][ty * TM + i];
#pragma unroll
            for (int j = 0; j < TN; j++) rw[j] = Ws[kk][tx * TN + j];
#pragma unroll
            for (int i = 0; i < TM; i++)
#pragma unroll
                for (int j = 0; j < TN; j++)
                    acc[i][j] = fmaf(ra[i], rw[j], acc[i][j]);
        }
        __syncthreads();
    }
#pragma unroll
    for (int i = 0; i < TM; i++) {
        int row = bm + ty * TM + i;
#pragma unroll
        for (int j = 0; j < TN; j++) {
            int col = bn + tx * TN + j;
            C[(size_t)row * N + col] = acc[i][j] + bias[col];
        }
    }
}

// ---------------- layernorm -> fp16, one warp per row ----------------
__global__ __launch_bounds__(256) void ln_kernel(
    const float* __restrict__ x, const float* __restrict__ w,
    const float* __restrict__ bb, __half* __restrict__ oh)
{
    int row  = blockIdx.x * 8 + (threadIdx.x >> 5);
    int lane = threadIdx.x & 31;
    const float* xr = x + (size_t)row * D_MODEL + lane;
    float v[16];
    float s = 0.f, s2 = 0.f;
#pragma unroll
    for (int i = 0; i < 16; i++) {
        v[i] = xr[i * 32];
        s += v[i];
        s2 = fmaf(v[i], v[i], s2);
    }
#pragma unroll
    for (int k = 16; k; k >>= 1) {
        s  += __shfl_xor_sync(0xffffffffu, s,  k);
        s2 += __shfl_xor_sync(0xffffffffu, s2, k);
    }
    float mu  = s * (1.f / 512.f);
    float var = fmaf(s2, 1.f / 512.f, -mu * mu);
    float rs  = rsqrtf(var + 1e-5f);
    size_t ob = (size_t)row * D_MODEL + lane;
#pragma unroll
    for (int i = 0; i < 16; i++) {
        float o = (v[i] - mu) * rs * w[lane + i * 32] + bb[lane + i * 32];
        oh[ob + i * 32] = __float2half_rn(o);
    }
}

// ---------------- causal depthwise conv (k=4) + SiLU, half2 -------------
__global__ __launch_bounds__(256) void conv_silu_kernel(
    const __half* __restrict__ xz, const __half* __restrict__ cwT,
    const float* __restrict__ cb, __half* __restrict__ xch)
{
    int idx = blockIdx.x * 256 + threadIdx.x;          // over BL_ROWS*512
    int d2 = idx & 511;
    int bl = idx >> 9;
    int t  = bl & (L_SEQ - 1);
    const __half2* xp = (const __half2*)xz + (size_t)bl * 1024 + d2;
    const __half2* wp = (const __half2*)cwT + d2;      // [k][d2] stride 512
    float2 cbv = *(const float2*)(cb + d2 * 2);
    float a0 = cbv.x, a1 = cbv.y;
    {
        float2 w = __half22float2(__ldg(wp + 3 * 512));
        float2 x = __half22float2(__ldg(xp));
        a0 = fmaf(w.x, x.x, a0); a1 = fmaf(w.y, x.y, a1);
    }
    if (t >= 1) {
        float2 w = __half22float2(__ldg(wp + 2 * 512));
        float2 x = __half22float2(__ldg(xp - 1024));
        a0 = fmaf(w.x, x.x, a0); a1 = fmaf(w.y, x.y, a1);
    }
    if (t >= 2) {
        float2 w = __half22float2(__ldg(wp + 512));
        float2 x = __half22float2(__ldg(xp - 2048));
        a0 = fmaf(w.x, x.x, a0); a1 = fmaf(w.y, x.y, a1);
    }
    if (t >= 3) {
        float2 w = __half22float2(__ldg(wp));
        float2 x = __half22float2(__ldg(xp - 3072));
        a0 = fmaf(w.x, x.x, a0); a1 = fmaf(w.y, x.y, a1);
    }
    float s0 = __fdividef(a0, 1.f + __expf(-a0));
    float s1 = __fdividef(a1, 1.f + __expf(-a1));
    ((__half2*)xch)[idx] = __halves2half2(__float2half_rn(s0), __float2half_rn(s1));
}

// ---------------- selective scan: warp = 4 channels x 8 lanes, 2 states --
// per lane. B/C loaded per-lane (no broadcast shfls); 3-step butterfly
// reduction over 8 lanes shared by 4 channels.
__global__ __launch_bounds__(128) void scan_kernel(
    const __half* __restrict__ dt_g, const __half* __restrict__ xc_g,
    const __half* __restrict__ dbl_g, const __half* __restrict__ xz_g,
    const float* __restrict__ A_log, const float* __restrict__ Dsk,
    __half* __restrict__ ysh)
{
    const int gw   = (blockIdx.x * 128 + threadIdx.x) >> 5;   // 0..2047
    const int lane = threadIdx.x & 31;
    const int b    = gw >> 8;            // 256 warps per batch
    const int d0   = (gw & 255) << 2;    // 4 channels per warp
    const int c    = lane >> 3;          // channel within warp
    const int sub  = lane & 7;           // 8 lanes per channel
    const int d    = d0 + c;

    const float An0 = -__expf(__ldg(A_log + d * N_STATE + sub * 2));
    const float An1 = -__expf(__ldg(A_log + d * N_STATE + sub * 2 + 1));
    const float Dd  = __ldg(Dsk + d);
    const size_t base = (size_t)b * L_SEQ;

    const __half*  dtp = dt_g + base * D_INNER + d;
    const __half*  xcp = xc_g + base * D_INNER + d;
    const __half*  zp  = xz_g + base * 2048 + D_INNER + d;
    const __half2* bp  = (const __half2*)(dbl_g + base * 64 + 32) + sub;
    const __half2* cp  = (const __half2*)(dbl_g + base * 64 + 48) + sub;
    __half* yph = ysh + base * D_INNER + d;

    float h0 = 0.f, h1 = 0.f;

    __half adt[4], axc[4], az[4]; __half2 ab[4], ac[4];
    __half bdt[4], bxc[4], bz[4]; __half2 bb[4], bc[4];

#define LOADQ(T0, DT, XC, Z, BB, CC)                                      \
    {                                                                     \
        _Pragma("unroll")                                                 \
        for (int j = 0; j < 4; j++) {                                     \
            int tt = (T0) + j;                                            \
            DT[j] = __ldg(dtp + tt * D_INNER);                            \
            XC[j] = __ldg(xcp + tt * D_INNER);                            \
            Z[j]  = __ldg(zp  + tt * 2048);                               \
            BB[j] = __ldg(bp  + tt * 32);                                 \
            CC[j] = __ldg(cp  + tt * 32);                                 \
        }                                                                 \
    }
#define STEP(T, DTv, XCv, Zv, BBv, CCv)                                   \
    {                                                                     \
        float dtv = __half2float(DTv);                                    \
        float xv  = __half2float(XCv);                                    \
        float e0 = __expf(dtv * An0);                                     \
        float e1 = __expf(dtv * An1);                                     \
        float2 Bv = __half22float2(BBv);                                  \
        float2 Cv = __half22float2(CCv);                                  \
        float u = dtv * xv;                                               \
        h0 = fmaf(e0, h0, u * Bv.x);                                      \
        h1 = fmaf(e1, h1, u * Bv.y);                                      \
        float p = fmaf(h1, Cv.y, h0 * Cv.x);                              \
        p += __shfl_xor_sync(0xffffffffu, p, 1);                          \
        p += __shfl_xor_sync(0xffffffffu, p, 2);                          \
        p += __shfl_xor_sync(0xffffffffu, p, 4);                          \
        if (sub == 0) {                                                   \
            float zv = __half2float(Zv);                                  \
            float yv = fmaf(xv, Dd, p);                                   \
            float o  = yv * __fdividef(zv, 1.f + __expf(-zv));            \
            yph[(T) * D_INNER] = __float2half_rn(o);                      \
        }                                                                 \
    }

    LOADQ(0, adt, axc, az, ab, ac);
    for (int t0 = 0; t0 < L_SEQ; t0 += 8) {
        LOADQ(t0 + 4, bdt, bxc, bz, bb, bc);
#pragma unroll
        for (int j = 0; j < 4; j++) STEP(t0 + j, adt[j], axc[j], az[j], ab[j], ac[j]);
        if (t0 + 8 < L_SEQ) LOADQ(t0 + 8, adt, axc, az, ab, ac);
#pragma unroll
        for (int j = 0; j < 4; j++) STEP(t0 + 4 + j, bdt[j], bxc[j], bz[j], bb[j], bc[j]);
    }
#undef LOADQ
#undef STEP
}

// ---------------- host orchestration ----------------
extern "C" void kernel_launch(void* const* d_in, const int* in_sizes, int n_in,
                              void* d_out, int out_size)
{
    const float* y        = (const float*)d_in[0];
    const float* emb_w    = (const float*)d_in[1];
    const float* emb_b    = (const float*)d_in[2];
    const float* ln_w     = (const float*)d_in[3];
    const float* ln_b     = (const float*)d_in[4];
    const float* mix_w    = (const float*)d_in[5];
    const float* conv_w   = (const float*)d_in[6];
    const float* conv_b   = (const float*)d_in[7];
    const float* xproj_w  = (const float*)d_in[8];
    const float* dtproj_w = (const float*)d_in[9];
    const float* dtproj_b = (const float*)d_in[10];
    const float* A_log    = (const float*)d_in[11];
    const float* Dskip    = (const float*)d_in[12];
    const float* out_w    = (const float*)d_in[13];
    const float* normf_w  = (const float*)d_in[14];
    const float* normf_b  = (const float*)d_in[15];
    const float* ro1_w    = (const float*)d_in[16];
    const float* ro1_b    = (const float*)d_in[17];
    const float* ro2_w    = (const float*)d_in[18];
    const float* ro2_b    = (const float*)d_in[19];

    float* h;
    cudaGetSymbolAddress((void**)&h, g_h);
    __half *xzh, *xin, *xch, *dth, *ysh, *h2, *dblh;
    __half *mw, *xpw, *ow, *dtw, *r1w, *r2w, *cwT;
    cudaGetSymbolAddress((void**)&xzh,  g_xzh);
    cudaGetSymbolAddress((void**)&xin,  g_xin);
    cudaGetSymbolAddress((void**)&xch,  g_xch);
    cudaGetSymbolAddress((void**)&dth,  g_dth);
    cudaGetSymbolAddress((void**)&ysh,  g_ysh);
    cudaGetSymbolAddress((void**)&h2,   g_h2);
    cudaGetSymbolAddress((void**)&dblh, g_dblh);
    cudaGetSymbolAddress((void**)&mw,   g_mixw);
    cudaGetSymbolAddress((void**)&xpw,  g_xpw);
    cudaGetSymbolAddress((void**)&ow,   g_ow);
    cudaGetSymbolAddress((void**)&dtw,  g_dtw);
    cudaGetSymbolAddress((void**)&r1w,  g_r1w);
    cudaGetSymbolAddress((void**)&r2w,  g_r2w);
    cudaGetSymbolAddress((void**)&cwT,  g_cwT);

    const int M = BL_ROWS;
    constexpr int SU128 = 2 * (128 * 144 + 128 * 144);  // 73728
    constexpr int SU64  = 2 * (128 * 144 + 64 * 144);   // 55296
    constexpr int S128  = 2 * (128 * 80 + 128 * 80);    // 40960
    cudaFuncSetAttribute(mma_gemmU<128, EPI_NONE>,  cudaFuncAttributeMaxDynamicSharedMemorySize, SU128);
    cudaFuncSetAttribute(mma_gemmU<128, EPI_RESID>, cudaFuncAttributeMaxDynamicSharedMemorySize, SU128);
    cudaFuncSetAttribute(mma_gemmU<128, EPI_GELU>,  cudaFuncAttributeMaxDynamicSharedMemorySize, SU128);
    cudaFuncSetAttribute(mma_gemmU<128, EPI_BIAS>,  cudaFuncAttributeMaxDynamicSharedMemorySize, SU128);
    cudaFuncSetAttribute(mma_gemmU<64,  EPI_NONE>,  cudaFuncAttributeMaxDynamicSharedMemorySize, SU64);
    cudaFuncSetAttribute(mma_gemm<128, EPI_SOFTPLUS>, cudaFuncAttributeMaxDynamicSharedMemorySize, S128);

    // launch order: my index 3 = layer-0 mix GEMM (profiled at global idx 5)
    gemm_k<64, 64, 16, 4, 4><<<dim3(D_MODEL / 64, M / 64), 256>>>(
        y, P_DIM, emb_w, emb_b, h, M, D_MODEL, P_DIM);                        // 0
    cvt_kernel<<<(N_LAYER * 2 * D_INNER * D_MODEL) / 1024, 256>>>(mix_w, mw); // 1
    ln_kernel<<<M / 8, 256>>>(h, ln_w, ln_b, xin);                            // 2
    mma_gemmU<128, EPI_NONE><<<dim3(16, M / 128), 256, SU128>>>(              // 3
        xin, D_MODEL, mw, nullptr, nullptr, nullptr, xzh, 2 * D_INNER, D_MODEL);
    cvt_kernel<<<(N_LAYER * 64 * D_INNER) / 1024, 256>>>(xproj_w, xpw);       // 4
    cvt_kernel<<<(N_LAYER * D_MODEL * D_INNER) / 1024, 256>>>(out_w, ow);     // 5
    cvt_kernel<<<(N_LAYER * D_INNER * DT_RANK) / 1024, 256>>>(dtproj_w, dtw); // 6
    cvt_kernel<<<(D_MODEL * D_MODEL) / 1024, 256>>>(ro1_w, r1w);              // 7
    cvt_kernel<<<(128 * D_MODEL) / 1024, 256>>>(ro2_w, r2w);                  // 8
    cvt_convw<<<(N_LAYER * 4 * D_INNER) / 256, 256>>>(conv_w, cwT);           // 9

    for (int i = 0; i < N_LAYER; i++) {
        const float* cb  = conv_b + (size_t)i * D_INNER;
        const float* dpb = dtproj_b + (size_t)i * D_INNER;
        const float* Al  = A_log + (size_t)i * D_INNER * N_STATE;
        const float* Dk  = Dskip + (size_t)i * D_INNER;

        if (i > 0) {
            ln_kernel<<<M / 8, 256>>>(h, ln_w + i * D_MODEL, ln_b + i * D_MODEL, xin);
            mma_gemmU<128, EPI_NONE><<<dim3(16, M / 128), 256, SU128>>>(
                xin, D_MODEL, mw + (size_t)i * 2 * D_INNER * D_MODEL,
                nullptr, nullptr, nullptr, xzh, 2 * D_INNER, D_MODEL);
        }
        // conv + silu -> xc fp16
        conv_silu_kernel<<<(M * 512) / 256, 256>>>(
            xzh, cwT + (size_t)i * 4 * D_INNER, cb, xch);
        // dbl = xc @ xproj_w^T  (M x 64, K=1024) -> fp16
        mma_gemmU<64, EPI_NONE><<<dim3(1, M / 128), 256, SU64>>>(
            xch, D_INNER, xpw + (size_t)i * 64 * D_INNER,
            nullptr, nullptr, nullptr, dblh, 64, D_INNER);
        // dt = softplus(dblh[:, :32] @ dtproj_w^T + b) -> fp16
        mma_gemm<128, EPI_SOFTPLUS><<<dim3(D_INNER / 128, M / 128), 256, S128>>>(
            dblh, 64, dtw + (size_t)i * D_INNER * DT_RANK,
            dpb, nullptr, dth, D_INNER, DT_RANK);
        // selective scan + gate -> ys fp16
        scan_kernel<<<512, 128>>>(dth, xch, dblh, xzh, Al, Dk, ysh);
        // h = h + ys @ out_w^T  (M x 512, K=1024)
        mma_gemmU<128, EPI_RESID><<<dim3(4, M / 128), 256, SU128>>>(
            ysh, D_INNER, ow + (size_t)i * D_MODEL * D_INNER,
            nullptr, h, h, nullptr, D_MODEL, D_INNER);
    }

    // final LN -> fp16
    ln_kernel<<<M / 8, 256>>>(h, normf_w, normf_b, xin);
    // h2 = gelu(xin @ ro1_w^T + b) -> fp16
    mma_gemmU<128, EPI_GELU><<<dim3(4, M / 128), 256, SU128>>>(
        xin, D_MODEL, r1w, ro1_b, nullptr, nullptr, h2, D_MODEL, D_MODEL);
    // out = h2 @ ro2_w^T + b
    mma_gemmU<128, EPI_BIAS><<<dim3(1, M / 128), 256, SU128>>>(
        h2, D_MODEL, r2w, ro2_b, nullptr, (float*)d_out, nullptr, 128, D_MODEL);
}